// round 11
// baseline (speedup 1.0000x reference)
#include <cuda_runtime.h>
#include <cuda_fp16.h>
#include <math.h>
#include <stdint.h>

// ---------------- problem constants ----------------
#define BATCH 4
#define HEADS 8
#define NSEQ  4096
#define DH    64
#define DIM   512
#define NL    256
#define LGRP  16
#define BHD   (BATCH*HEADS)
#define CONV_TAPS 33
#define CONV_PAD 16

#define S_PINV 64.0f
#define S_W    256.0f

// ---------------- scratch (fp32) ----------------
__device__ float g_q [(size_t)BHD*NSEQ*DH];
__device__ float g_k [(size_t)BHD*NSEQ*DH];
__device__ float g_v [(size_t)BHD*NSEQ*DH];
__device__ float g_ql[(size_t)BHD*NL*DH];
__device__ float g_kl[(size_t)BHD*NL*DH];
__device__ float g_a2[(size_t)BHD*NL*NL];
__device__ float g_za3v[(size_t)BHD*NL*DH];
__device__ float g_part[(size_t)4*BHD*NL*DH];
__device__ float g_lpart[(size_t)4*BHD*NL];
__device__ float g_oh [(size_t)BHD*NSEQ*DH];
__device__ float g_scal[2];
__device__ unsigned g_barc;

// ---------------- scratch (half splits; all row-major) ----------------
__device__ __half g_xh [(size_t)BATCH*NSEQ*DIM];
__device__ __half g_xl [(size_t)BATCH*NSEQ*DIM];
__device__ __half g_wqh[(size_t)DIM*3*DIM];
__device__ __half g_wql[(size_t)DIM*3*DIM];
__device__ __half g_woh[(size_t)DIM*DIM];
__device__ __half g_wol[(size_t)DIM*DIM];
__device__ __half g_x2h[(size_t)BATCH*NSEQ*DIM];
__device__ __half g_x2l[(size_t)BATCH*NSEQ*DIM];
__device__ __half g_a2h[(size_t)BHD*NL*NL];
__device__ __half g_a2l[(size_t)BHD*NL*NL];
__device__ __half g_zAh[(size_t)BHD*NL*NL];
__device__ __half g_zAl[(size_t)BHD*NL*NL];
__device__ __half g_zBh[(size_t)BHD*NL*NL];
__device__ __half g_zBl[(size_t)BHD*NL*NL];
__device__ __half g_xzh[(size_t)BHD*NL*NL];
__device__ __half g_xzl[(size_t)BHD*NL*NL];
__device__ __half g_T1h[(size_t)BHD*NL*NL];
__device__ __half g_T1l[(size_t)BHD*NL*NL];
__device__ __half g_T2h[(size_t)BHD*NL*NL];
__device__ __half g_T2l[(size_t)BHD*NL*NL];
__device__ __half g_a3vh[(size_t)BHD*NL*DH];
__device__ __half g_a3vl[(size_t)BHD*NL*DH];

// ---------------- helpers ----------------
__device__ __forceinline__ void split_tf32(float v, uint32_t &hi, uint32_t &lo) {
    asm("cvt.rna.tf32.f32 %0, %1;" : "=r"(hi) : "f"(v));
    float r = v - __uint_as_float(hi);
    asm("cvt.rna.tf32.f32 %0, %1;" : "=r"(lo) : "f"(r));
}

__device__ __forceinline__ void split_h(float v, __half &hi, __half &lo) {
    hi = __float2half_rn(v);
    lo = __float2half_rn(v - __half2float(hi));
}

#define MMA_TF32(D, A0,A1,A2,A3, B0,B1) \
    asm volatile("mma.sync.aligned.m16n8k8.row.col.f32.tf32.tf32.f32 " \
                 "{%0,%1,%2,%3},{%4,%5,%6,%7},{%8,%9},{%0,%1,%2,%3};" \
                 : "+f"((D)[0]), "+f"((D)[1]), "+f"((D)[2]), "+f"((D)[3]) \
                 : "r"(A0), "r"(A1), "r"(A2), "r"(A3), "r"(B0), "r"(B1))

#define MMA_F16(D, a0,a1,a2,a3, b0,b1) \
    asm volatile("mma.sync.aligned.m16n8k16.row.col.f32.f16.f16.f32 " \
                 "{%0,%1,%2,%3},{%4,%5,%6,%7},{%8,%9},{%0,%1,%2,%3};" \
                 : "+f"((D)[0]), "+f"((D)[1]), "+f"((D)[2]), "+f"((D)[3]) \
                 : "r"(a0), "r"(a1), "r"(a2), "r"(a3), "r"(b0), "r"(b1))

__device__ __forceinline__ void cp16(void* smem, const void* g) {
    uint32_t sa = (uint32_t)__cvta_generic_to_shared(smem);
    asm volatile("cp.async.ca.shared.global [%0], [%1], 16;" :: "r"(sa), "l"(g));
}
// L2-only variant: needed when re-reading data written by other SMs within
// one persistent kernel (L1 is not coherent across SMs).
__device__ __forceinline__ void cp16cg(void* smem, const void* g) {
    uint32_t sa = (uint32_t)__cvta_generic_to_shared(smem);
    asm volatile("cp.async.cg.shared.global [%0], [%1], 16;" :: "r"(sa), "l"(g));
}
#define CP_COMMIT asm volatile("cp.async.commit_group;")
#define CP_WAIT0  asm volatile("cp.async.wait_group 0;")
#define CP_WAIT1  asm volatile("cp.async.wait_group 1;")

__device__ __forceinline__ uint32_t packh2(float a, float b) {
    __half2 h = __floats2half2_rn(a, b);
    return *reinterpret_cast<uint32_t*>(&h);
}

__device__ __forceinline__ void ldsm4(uint32_t* r, const __half* p) {
    uint32_t a = (uint32_t)__cvta_generic_to_shared(p);
    asm volatile("ldmatrix.sync.aligned.m8n8.x4.shared.b16 {%0,%1,%2,%3}, [%4];"
                 : "=r"(r[0]), "=r"(r[1]), "=r"(r[2]), "=r"(r[3]) : "r"(a));
}
__device__ __forceinline__ void ldsm4t(uint32_t* r, const __half* p) {
    uint32_t a = (uint32_t)__cvta_generic_to_shared(p);
    asm volatile("ldmatrix.sync.aligned.m8n8.x4.trans.shared.b16 {%0,%1,%2,%3}, [%4];"
                 : "=r"(r[0]), "=r"(r[1]), "=r"(r[2]), "=r"(r[3]) : "r"(a));
}

// ================= fp16 batched GEMM — 512 threads, warp tile 32x32 =====
template<int BN, int PREC>
__global__ void __launch_bounds__(512, 1)
gemm_h3(const __half* __restrict__ Ahg, const __half* __restrict__ Alg,
        const __half* __restrict__ Bhg, const __half* __restrict__ Blg,
        int M, int N, int K, long long sA, long long sB,
        float scale, float outS,
        float* __restrict__ Cf, long long sC, const float* __restrict__ bias,
        __half* __restrict__ R1h, __half* __restrict__ R1l, long long sR1,
        __half* __restrict__ R2h, __half* __restrict__ R2l, long long sR2, float dv,
        int qkv, float qscale,
        float* __restrict__ qp, float* __restrict__ kp, float* __restrict__ vp)
{
    constexpr int NT  = BN / 32;
    constexpr int ALD = 40;
    constexpr int BLD = BN + 8;
    constexpr int ASZ = 128 * ALD;
    constexpr int BSZ = 32 * BLD;

    const int zb = blockIdx.z;
    const __half* Ah_g = Ahg + (long long)zb * sA;
    const __half* Al_g = Alg + (long long)zb * sA;
    const __half* Bh_g = Bhg + (long long)zb * sB;
    const __half* Bl_g = Blg + (long long)zb * sB;
    if (Cf)  Cf  += (long long)zb * sC;
    if (R1h) { R1h += (long long)zb * sR1; R1l += (long long)zb * sR1; }
    if (R2h) { R2h += (long long)zb * sR2; R2l += (long long)zb * sR2; }

    extern __shared__ __half hsm[];
    __half* Ash = hsm;
    __half* Asl = Ash + 3 * ASZ;
    __half* Bsh = (PREC == 3) ? (Asl + 3 * ASZ) : (Ash + 3 * ASZ);
    __half* Bsl = Bsh + 3 * BSZ;

    const int brow = blockIdx.y * 128;
    const int bcol = blockIdx.x * BN;

    const int tid  = threadIdx.x;
    const int warp = tid >> 5;
    const int lane = tid & 31;
    const int wm   = warp & 3;
    const int wn   = warp >> 2;
    const int grp  = lane >> 2;
    const int t4   = lane & 3;
    const int r8   = lane & 7;
    const int quad = lane >> 3;

    const int nk = K / 32;

    auto load_stage = [&](int s, int kt) {
        int k0 = kt * 32;
        {
            int row = tid >> 2, seg = (tid & 3) * 8;
            cp16(&Ash[(s * 128 + row) * ALD + seg], &Ah_g[(long long)(brow + row) * K + k0 + seg]);
            if (PREC == 3)
                cp16(&Asl[(s * 128 + row) * ALD + seg], &Al_g[(long long)(brow + row) * K + k0 + seg]);
        }
        if (tid < BN * 4) {
            int row = tid / (BN / 8), seg = (tid % (BN / 8)) * 8;
            cp16(&Bsh[(s * 32 + row) * BLD + seg], &Bh_g[(long long)(k0 + row) * N + bcol + seg]);
            if (PREC == 3)
                cp16(&Bsl[(s * 32 + row) * BLD + seg], &Bl_g[(long long)(k0 + row) * N + bcol + seg]);
        }
    };

    float acc[2][NT][4];
    #pragma unroll
    for (int i = 0; i < 2; i++)
        #pragma unroll
        for (int j = 0; j < NT; j++)
            #pragma unroll
            for (int l = 0; l < 4; l++) acc[i][j][l] = 0.f;

    load_stage(0, 0); CP_COMMIT;
    load_stage(1, 1); CP_COMMIT;

    for (int kt = 0; kt < nk; kt++) {
        CP_WAIT1;
        __syncthreads();
        int buf = kt % 3;
        if (kt + 2 < nk) load_stage((kt + 2) % 3, kt + 2);
        CP_COMMIT;

        #pragma unroll
        for (int ss = 0; ss < 2; ss++) {
            int kb = ss * 16;
            uint32_t ah[2][4], al[2][4];
            #pragma unroll
            for (int mt = 0; mt < 2; mt++) {
                int m0 = wm * 32 + mt * 16;
                int off = (buf * 128 + m0 + r8 + (quad & 1) * 8) * ALD + kb + (quad >> 1) * 8;
                ldsm4(ah[mt], Ash + off);
                if (PREC == 3) ldsm4(al[mt], Asl + off);
            }
            uint32_t bh[NT][2], bl[NT][2];
            #pragma unroll
            for (int np = 0; np < NT / 2; np++) {
                int n0 = wn * (BN / 4) + np * 16;
                int off = (buf * 32 + kb + (quad & 1) * 8 + r8) * BLD + n0 + (quad >> 1) * 8;
                uint32_t tb[4];
                ldsm4t(tb, Bsh + off);
                bh[np * 2][0] = tb[0]; bh[np * 2][1] = tb[1];
                bh[np * 2 + 1][0] = tb[2]; bh[np * 2 + 1][1] = tb[3];
                if (PREC == 3) {
                    ldsm4t(tb, Bsl + off);
                    bl[np * 2][0] = tb[0]; bl[np * 2][1] = tb[1];
                    bl[np * 2 + 1][0] = tb[2]; bl[np * 2 + 1][1] = tb[3];
                }
            }
            #pragma unroll
            for (int mt = 0; mt < 2; mt++)
                #pragma unroll
                for (int nt = 0; nt < NT; nt++) {
                    MMA_F16(acc[mt][nt], ah[mt][0], ah[mt][1], ah[mt][2], ah[mt][3], bh[nt][0], bh[nt][1]);
                    if (PREC == 3) {
                        MMA_F16(acc[mt][nt], ah[mt][0], ah[mt][1], ah[mt][2], ah[mt][3], bl[nt][0], bl[nt][1]);
                        MMA_F16(acc[mt][nt], al[mt][0], al[mt][1], al[mt][2], al[mt][3], bh[nt][0], bh[nt][1]);
                    }
                }
        }
    }

    #pragma unroll
    for (int mt = 0; mt < 2; mt++) {
        int r0 = brow + wm * 32 + mt * 16 + grp;
        #pragma unroll
        for (int nt = 0; nt < NT; nt++) {
            int c = bcol + wn * (BN / 4) + nt * 8 + t4 * 2;
            #pragma unroll
            for (int half_i = 0; half_i < 2; half_i++) {
                int r = r0 + half_i * 8;
                float v0 = acc[mt][nt][half_i * 2 + 0] * scale;
                float v1 = acc[mt][nt][half_i * 2 + 1] * scale;
                if (qkv) {
                    int bidx = r >> 12, nn = r & 4095;
                    int part = c / DIM, rem = c % DIM;
                    int hh = rem >> 6, dd = rem & 63;
                    long long dst = ((((long long)bidx * HEADS + hh) * NSEQ) + nn) * DH + dd;
                    float2 val;
                    if (part == 0) { val.x = v0 * qscale; val.y = v1 * qscale; *(float2*)&qp[dst] = val; }
                    else if (part == 1) { val.x = v0; val.y = v1; *(float2*)&kp[dst] = val; }
                    else { val.x = v0; val.y = v1; *(float2*)&vp[dst] = val; }
                } else {
                    if (Cf) {
                        float b0 = bias ? bias[c] : 0.f;
                        float b1 = bias ? bias[c + 1] : 0.f;
                        float2 val; val.x = v0 + b0; val.y = v1 + b1;
                        *(float2*)&Cf[(long long)r * N + c] = val;
                    }
                    if (R1h) {
                        __half h0, l0, h1, l1;
                        split_h(v0 * outS, h0, l0);
                        split_h(v1 * outS, h1, l1);
                        __half2 hp; hp.x = h0; hp.y = h1;
                        __half2 lp; lp.x = l0; lp.y = l1;
                        *(__half2*)&R1h[(long long)r * N + c] = hp;
                        *(__half2*)&R1l[(long long)r * N + c] = lp;
                    }
                    if (R2h) {
                        float tv0 = (((r == c) ? dv : 0.f) - v0) * outS;
                        float tv1 = (((r == c + 1) ? dv : 0.f) - v1) * outS;
                        __half h0, l0, h1, l1;
                        split_h(tv0, h0, l0);
                        split_h(tv1, h1, l1);
                        __half2 hp; hp.x = h0; hp.y = h1;
                        __half2 lp; lp.x = l0; lp.y = l1;
                        *(__half2*)&R2h[(long long)r * N + c] = hp;
                        *(__half2*)&R2l[(long long)r * N + c] = lp;
                    }
                }
            }
        }
    }
}

// ================= persistent pinv kernel =================
// Runs all Newton-iteration GEMM steps in ONE kernel with a grid-wide
// barrier between steps. Grid (2,2,32) = 128 blocks, all co-resident
// (1 CTA/SM at 111KB smem, 128 < 148 SMs). Loads use cp.async.cg (L2-only)
// because tiles written by other SMs are re-read across steps.
struct PinvStep {
    const __half *Ah, *Al, *Bh, *Bl;
    __half *R1h, *R1l, *R2h, *R2l;
    float dv, scale;
    int prec;
};
struct PinvPlan { PinvStep s[20]; int n; };

__global__ void bar_reset() { g_barc = 0; }

__global__ void __launch_bounds__(512, 1)
pinv_persist(PinvPlan plan)
{
    constexpr int ALD = 40, BLD = 136, ASZ = 128 * ALD, BSZ = 32 * BLD;
    extern __shared__ __half hsm[];
    __half* Ash = hsm;
    __half* Asl = Ash + 3 * ASZ;
    __half* Bsh = Asl + 3 * ASZ;
    __half* Bsl = Bsh + 3 * BSZ;

    const int tid  = threadIdx.x;
    const int warp = tid >> 5;
    const int lane = tid & 31;
    const int wm   = warp & 3;
    const int wn   = warp >> 2;
    const int grp  = lane >> 2;
    const int t4   = lane & 3;
    const int r8   = lane & 7;
    const int quad = lane >> 3;
    const int brow = blockIdx.y * 128;
    const int bcol = blockIdx.x * 128;
    const long long zoff = (long long)blockIdx.z * (NL * NL);
    const unsigned nb = gridDim.x * gridDim.y * gridDim.z;

    for (int st = 0; st < plan.n; st++) {
        const __half* Ah = plan.s[st].Ah + zoff;
        const __half* Al = plan.s[st].Al + zoff;
        const __half* Bh = plan.s[st].Bh + zoff;
        const __half* Bl = plan.s[st].Bl + zoff;
        const int prec = plan.s[st].prec;

        auto load_stage = [&](int s, int kt) {
            int k0 = kt * 32;
            {
                int row = tid >> 2, seg = (tid & 3) * 8;
                cp16cg(&Ash[(s * 128 + row) * ALD + seg], &Ah[(long long)(brow + row) * NL + k0 + seg]);
                if (prec == 3)
                    cp16cg(&Asl[(s * 128 + row) * ALD + seg], &Al[(long long)(brow + row) * NL + k0 + seg]);
            }
            {
                int row = tid >> 4, seg = (tid & 15) * 8;
                cp16cg(&Bsh[(s * 32 + row) * BLD + seg], &Bh[(long long)(k0 + row) * NL + bcol + seg]);
                if (prec == 3)
                    cp16cg(&Bsl[(s * 32 + row) * BLD + seg], &Bl[(long long)(k0 + row) * NL + bcol + seg]);
            }
        };

        float acc[2][4][4];
        #pragma unroll
        for (int i = 0; i < 2; i++)
            #pragma unroll
            for (int j = 0; j < 4; j++)
                #pragma unroll
                for (int l = 0; l < 4; l++) acc[i][j][l] = 0.f;

        load_stage(0, 0); CP_COMMIT;
        load_stage(1, 1); CP_COMMIT;

        for (int kt = 0; kt < 8; kt++) {
            CP_WAIT1;
            __syncthreads();
            int buf = kt % 3;
            if (kt + 2 < 8) load_stage((kt + 2) % 3, kt + 2);
            CP_COMMIT;

            #pragma unroll
            for (int ss = 0; ss < 2; ss++) {
                int kb = ss * 16;
                uint32_t ah[2][4], al[2][4];
                #pragma unroll
                for (int mt = 0; mt < 2; mt++) {
                    int m0 = wm * 32 + mt * 16;
                    int off = (buf * 128 + m0 + r8 + (quad & 1) * 8) * ALD + kb + (quad >> 1) * 8;
                    ldsm4(ah[mt], Ash + off);
                    if (prec == 3) ldsm4(al[mt], Asl + off);
                }
                uint32_t bh[4][2], bl[4][2];
                #pragma unroll
                for (int np = 0; np < 2; np++) {
                    int n0 = wn * 32 + np * 16;
                    int off = (buf * 32 + kb + (quad & 1) * 8 + r8) * BLD + n0 + (quad >> 1) * 8;
                    uint32_t tb[4];
                    ldsm4t(tb, Bsh + off);
                    bh[np * 2][0] = tb[0]; bh[np * 2][1] = tb[1];
                    bh[np * 2 + 1][0] = tb[2]; bh[np * 2 + 1][1] = tb[3];
                    if (prec == 3) {
                        ldsm4t(tb, Bsl + off);
                        bl[np * 2][0] = tb[0]; bl[np * 2][1] = tb[1];
                        bl[np * 2 + 1][0] = tb[2]; bl[np * 2 + 1][1] = tb[3];
                    }
                }
                #pragma unroll
                for (int mt = 0; mt < 2; mt++)
                    #pragma unroll
                    for (int nt = 0; nt < 4; nt++) {
                        MMA_F16(acc[mt][nt], ah[mt][0], ah[mt][1], ah[mt][2], ah[mt][3], bh[nt][0], bh[nt][1]);
                        if (prec == 3) {
                            MMA_F16(acc[mt][nt], ah[mt][0], ah[mt][1], ah[mt][2], ah[mt][3], bl[nt][0], bl[nt][1]);
                            MMA_F16(acc[mt][nt], al[mt][0], al[mt][1], al[mt][2], al[mt][3], bh[nt][0], bh[nt][1]);
                        }
                    }
            }
        }
        CP_WAIT0;

        const float scale = plan.s[st].scale;
        const float dv = plan.s[st].dv;
        __half* R1h = plan.s[st].R1h ? plan.s[st].R1h + zoff : nullptr;
        __half* R1l = plan.s[st].R1l ? plan.s[st].R1l + zoff : nullptr;
        __half* R2h = plan.s[st].R2h ? plan.s[st].R2h + zoff : nullptr;
        __half* R2l = plan.s[st].R2l ? plan.s[st].R2l + zoff : nullptr;

        #pragma unroll
        for (int mt = 0; mt < 2; mt++) {
            int r0 = brow + wm * 32 + mt * 16 + grp;
            #pragma unroll
            for (int nt = 0; nt < 4; nt++) {
                int c = bcol + wn * 32 + nt * 8 + t4 * 2;
                #pragma unroll
                for (int half_i = 0; half_i < 2; half_i++) {
                    int r = r0 + half_i * 8;
                    float v0 = acc[mt][nt][half_i * 2 + 0] * scale;
                    float v1 = acc[mt][nt][half_i * 2 + 1] * scale;
                    if (R1h) {
                        __half h0, l0, h1, l1;
                        split_h(v0 * S_PINV, h0, l0);
                        split_h(v1 * S_PINV, h1, l1);
                        __half2 hp; hp.x = h0; hp.y = h1;
                        __half2 lp; lp.x = l0; lp.y = l1;
                        *(__half2*)&R1h[(long long)r * NL + c] = hp;
                        *(__half2*)&R1l[(long long)r * NL + c] = lp;
                    }
                    if (R2h) {
                        float tv0 = (((r == c) ? dv : 0.f) - v0) * S_PINV;
                        float tv1 = (((r == c + 1) ? dv : 0.f) - v1) * S_PINV;
                        __half h0, l0, h1, l1;
                        split_h(tv0, h0, l0);
                        split_h(tv1, h1, l1);
                        __half2 hp; hp.x = h0; hp.y = h1;
                        __half2 lp; lp.x = l0; lp.y = l1;
                        *(__half2*)&R2h[(long long)r * NL + c] = hp;
                        *(__half2*)&R2l[(long long)r * NL + c] = lp;
                    }
                }
            }
        }

        // ---- grid barrier ----
        __syncthreads();
        __threadfence();
        if (tid == 0) {
            atomicAdd(&g_barc, 1u);
            unsigned target = (unsigned)(st + 1) * nb;
            while (*(volatile unsigned*)&g_barc < target) __nanosleep(64);
        }
        __syncthreads();
        __threadfence();
    }
}

// ================= 3xTF32 GEMM (a2 = ql @ kl^T only) =================
template<int BN, int TB>
__global__ void __launch_bounds__(256, 1)
gemm_tf32(const float* __restrict__ Ag, const float* __restrict__ Bg,
          float* __restrict__ Cg, int M, int N, int K,
          long long sA, long long sB, long long sC)
{
    constexpr int NT   = BN / 32;
    constexpr int BSZ  = TB ? BN * 20 : 16 * (BN + 8);
    constexpr int ASZ  = 128 * 20;

    extern __shared__ char dynsm[];
    float* As = (float*)dynsm;
    float* Bs = As + 3 * ASZ;

    const float* A = Ag + (long long)blockIdx.z * sA;
    const float* B = Bg + (long long)blockIdx.z * sB;
    float*       C = Cg + (long long)blockIdx.z * sC;

    const int brow = blockIdx.y * 128;
    const int bcol = blockIdx.x * BN;

    const int tid  = threadIdx.x;
    const int warp = tid >> 5;
    const int lane = tid & 31;
    const int wm   = warp & 1;
    const int wn   = warp >> 1;
    const int grp  = lane >> 2;
    const int t4   = lane & 3;

    const int a_row0 = tid >> 2;
    const int a_k    = (tid & 3) * 4;
    const int nk = K / 16;

    auto load_stage = [&](int s, int kt) {
        int k0 = kt * 16;
        cp16(&As[s * ASZ + a_row0 * 20 + a_k],        &A[(long long)(brow + a_row0) * K + k0 + a_k]);
        cp16(&As[s * ASZ + (a_row0 + 64) * 20 + a_k], &A[(long long)(brow + a_row0 + 64) * K + k0 + a_k]);
        #pragma unroll
        for (int j = 0; j < BN / 64; j++) {
            int i = tid + 256 * j;
            int n  = i >> 2;
            int kq = (i & 3) * 4;
            cp16(&Bs[s * BSZ + n * 20 + kq], &B[(long long)(bcol + n) * K + k0 + kq]);
        }
    };

    float acc[4][NT][4];
    #pragma unroll
    for (int i = 0; i < 4; i++)
        #pragma unroll
        for (int j = 0; j < NT; j++)
            #pragma unroll
            for (int l = 0; l < 4; l++) acc[i][j][l] = 0.f;

    load_stage(0, 0); CP_COMMIT;
    load_stage(1, 1); CP_COMMIT;

    for (int kt = 0; kt < nk; kt++) {
        CP_WAIT1;
        __syncthreads();
        int buf = kt % 3;
        if (kt + 2 < nk) load_stage((kt + 2) % 3, kt + 2);
        CP_COMMIT;

        #pragma unroll
        for (int ss = 0; ss < 2; ss++) {
            int kb = ss * 8;
            uint32_t ah[4][4], al[4][4];
            #pragma unroll
            for (int mt = 0; mt < 4; mt++) {
                int m = wm * 64 + mt * 16 + grp;
                float f0 = As[buf * ASZ + m * 20 + kb + t4];
                float f1 = As[buf * ASZ + (m + 8) * 20 + kb + t4];
                float f2 = As[buf * ASZ + m * 20 + kb + t4 + 4];
                float f3 = As[buf * ASZ + (m + 8) * 20 + kb + t4 + 4];
                split_tf32(f0, ah[mt][0], al[mt][0]);
                split_tf32(f1, ah[mt][1], al[mt][1]);
                split_tf32(f2, ah[mt][2], al[mt][2]);
                split_tf32(f3, ah[mt][3], al[mt][3]);
            }
            uint32_t bh[NT][2], bl[NT][2];
            #pragma unroll
            for (int nt = 0; nt < NT; nt++) {
                int n = wn * (BN / 4) + nt * 8 + grp;
                float b0 = Bs[buf * BSZ + n * 20 + kb + t4];
                float b1 = Bs[buf * BSZ + n * 20 + kb + t4 + 4];
                split_tf32(b0, bh[nt][0], bl[nt][0]);
                split_tf32(b1, bh[nt][1], bl[nt][1]);
            }
            #pragma unroll
            for (int mt = 0; mt < 4; mt++)
                #pragma unroll
                for (int nt = 0; nt < NT; nt++) {
                    MMA_TF32(acc[mt][nt], ah[mt][0], ah[mt][1], ah[mt][2], ah[mt][3], bh[nt][0], bh[nt][1]);
                    MMA_TF32(acc[mt][nt], ah[mt][0], ah[mt][1], ah[mt][2], ah[mt][3], bl[nt][0], bl[nt][1]);
                    MMA_TF32(acc[mt][nt], al[mt][0], al[mt][1], al[mt][2], al[mt][3], bh[nt][0], bh[nt][1]);
                }
        }
    }

    #pragma unroll
    for (int mt = 0; mt < 4; mt++) {
        int r0 = brow + wm * 64 + mt * 16 + grp;
        #pragma unroll
        for (int nt = 0; nt < NT; nt++) {
            int c = bcol + wn * (BN / 4) + nt * 8 + t4 * 2;
            #pragma unroll
            for (int half_i = 0; half_i < 2; half_i++) {
                int r = r0 + half_i * 8;
                float2 val;
                val.x = acc[mt][nt][half_i * 2 + 0];
                val.y = acc[mt][nt][half_i * 2 + 1];
                *(float2*)&C[(long long)r * N + c] = val;
            }
        }
    }
}

// ---------------- fused flash kernel ----------------
struct FlashSmem {
    float  qhi[128][68];
    float  qlo[128][68];
    float  raw[2][2][64][64];
    float  khi[64][68];
    float  klo[64][68];
    __half vh[64][72];
};

template<int PARTIAL>
__global__ void __launch_bounds__(256, 1)
flash_pv(const float* __restrict__ Qg, const float* __restrict__ Kg,
         const float* __restrict__ Vg, float* __restrict__ Og,
         float* __restrict__ Lg, int rows, int keys, int kvchunk)
{
    extern __shared__ char dynsm[];
    FlashSmem& sm = *reinterpret_cast<FlashSmem*>(dynsm);

    const int tid  = threadIdx.x;
    const int warp = tid >> 5;
    const int lane = tid & 31;
    const int grp  = lane >> 2;
    const int t4   = lane & 3;
    const int bh   = blockIdx.z;

    const long long qbase = ((long long)bh * rows + blockIdx.x * 128) * 64;
    const long long kbase = ((long long)bh * keys + (long long)blockIdx.y * kvchunk) * 64;

    #pragma unroll
    for (int j = 0; j < 8; j++) {
        int e = tid + 256 * j;
        int r = e >> 4, c4 = (e & 15) * 4;
        float4 qv = *(const float4*)&Qg[qbase + (long long)r * 64 + c4];
        uint32_t hi, lo;
        split_tf32(qv.x, hi, lo); sm.qhi[r][c4+0] = __uint_as_float(hi); sm.qlo[r][c4+0] = __uint_as_float(lo);
        split_tf32(qv.y, hi, lo); sm.qhi[r][c4+1] = __uint_as_float(hi); sm.qlo[r][c4+1] = __uint_as_float(lo);
        split_tf32(qv.z, hi, lo); sm.qhi[r][c4+2] = __uint_as_float(hi); sm.qlo[r][c4+2] = __uint_as_float(lo);
        split_tf32(qv.w, hi, lo); sm.qhi[r][c4+3] = __uint_as_float(hi); sm.qlo[r][c4+3] = __uint_as_float(lo);
    }

    auto stage = [&](int slot, int sub) {
        long long base = kbase + (long long)sub * 64 * 64;
        #pragma unroll
        for (int j = 0; j < 4; j++) {
            int e = tid + 256 * j;
            int r = e >> 4, c4 = (e & 15) * 4;
            cp16(&sm.raw[slot][0][r][c4], &Kg[base + (long long)r * 64 + c4]);
        }
        #pragma unroll
        for (int j = 0; j < 4; j++) {
            int e = tid + 256 * j;
            int r = e >> 4, c4 = (e & 15) * 4;
            cp16(&sm.raw[slot][1][r][c4], &Vg[base + (long long)r * 64 + c4]);
        }
    };

    const int nsub = kvchunk / 64;
    stage(0, 0); CP_COMMIT;

    float o[8][4];
    #pragma unroll
    for (int i = 0; i < 8; i++)
        #pragma unroll
        for (int j = 0; j < 4; j++) o[i][j] = 0.f;
    float l0 = 0.f, l1 = 0.f;
    const int r0s = warp * 16 + grp;

    for (int sub = 0; sub < nsub; sub++) {
        CP_WAIT0;
        __syncthreads();
        int slot = sub & 1;
        if (sub + 1 < nsub) stage(slot ^ 1, sub + 1);
        CP_COMMIT;

        #pragma unroll
        for (int j = 0; j < 4; j++) {
            int e = tid + 256 * j;
            int r = e >> 4, c4 = (e & 15) * 4;
            float4 kv = *(const float4*)&sm.raw[slot][0][r][c4];
            uint32_t hi, lo;
            split_tf32(kv.x, hi, lo); sm.khi[r][c4+0] = __uint_as_float(hi); sm.klo[r][c4+0] = __uint_as_float(lo);
            split_tf32(kv.y, hi, lo); sm.khi[r][c4+1] = __uint_as_float(hi); sm.klo[r][c4+1] = __uint_as_float(lo);
            split_tf32(kv.z, hi, lo); sm.khi[r][c4+2] = __uint_as_float(hi); sm.klo[r][c4+2] = __uint_as_float(lo);
            split_tf32(kv.w, hi, lo); sm.khi[r][c4+3] = __uint_as_float(hi); sm.klo[r][c4+3] = __uint_as_float(lo);
            float4 vv = *(const float4*)&sm.raw[slot][1][r][c4];
            sm.vh[c4+0][r] = __float2half(vv.x);
            sm.vh[c4+1][r] = __float2half(vv.y);
            sm.vh[c4+2][r] = __float2half(vv.z);
            sm.vh[c4+3][r] = __float2half(vv.w);
        }
        __syncthreads();

        float s[8][4];
        #pragma unroll
        for (int i = 0; i < 8; i++)
            #pragma unroll
            for (int j = 0; j < 4; j++) s[i][j] = 0.f;

        #pragma unroll
        for (int ks = 0; ks < 8; ks++) {
            int kk = ks * 8;
            uint32_t a0h = __float_as_uint(sm.qhi[r0s][kk + t4]);
            uint32_t a1h = __float_as_uint(sm.qhi[r0s + 8][kk + t4]);
            uint32_t a2h = __float_as_uint(sm.qhi[r0s][kk + t4 + 4]);
            uint32_t a3h = __float_as_uint(sm.qhi[r0s + 8][kk + t4 + 4]);
            uint32_t a0l = __float_as_uint(sm.qlo[r0s][kk + t4]);
            uint32_t a1l = __float_as_uint(sm.qlo[r0s + 8][kk + t4]);
            uint32_t a2l = __float_as_uint(sm.qlo[r0s][kk + t4 + 4]);
            uint32_t a3l = __float_as_uint(sm.qlo[r0s + 8][kk + t4 + 4]);
            #pragma unroll
            for (int nt = 0; nt < 8; nt++) {
                int n = nt * 8 + grp;
                uint32_t b0h = __float_as_uint(sm.khi[n][kk + t4]);
                uint32_t b1h = __float_as_uint(sm.khi[n][kk + t4 + 4]);
                uint32_t b0l = __float_as_uint(sm.klo[n][kk + t4]);
                uint32_t b1l = __float_as_uint(sm.klo[n][kk + t4 + 4]);
                MMA_TF32(s[nt], a0h, a1h, a2h, a3h, b0h, b1h);
                MMA_TF32(s[nt], a0h, a1h, a2h, a3h, b0l, b1l);
                MMA_TF32(s[nt], a0l, a1l, a2l, a3l, b0h, b1h);
            }
        }

        #pragma unroll
        for (int nt = 0; nt < 8; nt++) {
            s[nt][0] = __expf(s[nt][0]);
            s[nt][1] = __expf(s[nt][1]);
            s[nt][2] = __expf(s[nt][2]);
            s[nt][3] = __expf(s[nt][3]);
            l0 += s[nt][0] + s[nt][1];
            l1 += s[nt][2] + s[nt][3];
        }

        #pragma unroll
        for (int kg = 0; kg < 4; kg++) {
            uint32_t a0 = packh2(s[2*kg][0],   s[2*kg][1]);
            uint32_t a1 = packh2(s[2*kg][2],   s[2*kg][3]);
            uint32_t a2 = packh2(s[2*kg+1][0], s[2*kg+1][1]);
            uint32_t a3 = packh2(s[2*kg+1][2], s[2*kg+1][3]);
            #pragma unroll
            for (int dt = 0; dt < 8; dt++) {
                uint32_t b0 = *(const uint32_t*)&sm.vh[dt * 8 + grp][kg * 16 + 2 * t4];
                uint32_t b1 = *(const uint32_t*)&sm.vh[dt * 8 + grp][kg * 16 + 2 * t4 + 8];
                MMA_F16(o[dt], a0, a1, a2, a3, b0, b1);
            }
        }
    }

    l0 += __shfl_xor_sync(0xffffffffu, l0, 1);
    l0 += __shfl_xor_sync(0xffffffffu, l0, 2);
    l1 += __shfl_xor_sync(0xffffffffu, l1, 1);
    l1 += __shfl_xor_sync(0xffffffffu, l1, 2);

    const int rg0 = blockIdx.x * 128 + warp * 16 + grp;
    if (PARTIAL) {
        long long ob = (long long)(blockIdx.y * BHD + bh) * rows * 64;
        #pragma unroll
        for (int dt = 0; dt < 8; dt++) {
            int d = dt * 8 + 2 * t4;
            float2 w0; w0.x = o[dt][0]; w0.y = o[dt][1];
            float2 w1; w1.x = o[dt][2]; w1.y = o[dt][3];
            *(float2*)&Og[ob + (long long)rg0 * 64 + d] = w0;
            *(float2*)&Og[ob + (long long)(rg0 + 8) * 64 + d] = w1;
        }
        if (t4 == 0) {
            Lg[(long long)(blockIdx.y * BHD + bh) * rows + rg0]     = l0;
            Lg[(long long)(blockIdx.y * BHD + bh) * rows + rg0 + 8] = l1;
        }
    } else {
        float i0 = 1.f / l0, i1 = 1.f / l1;
        long long ob = (long long)bh * rows * 64;
        #pragma unroll
        for (int dt = 0; dt < 8; dt++) {
            int d = dt * 8 + 2 * t4;
            float2 w0; w0.x = o[dt][0] * i0; w0.y = o[dt][1] * i0;
            float2 w1; w1.x = o[dt][2] * i1; w1.y = o[dt][3] * i1;
            *(float2*)&Og[ob + (long long)rg0 * 64 + d] = w0;
            *(float2*)&Og[ob + (long long)(rg0 + 8) * 64 + d] = w1;
        }
    }
}

// combine 4 split-KV partials -> a3v row-major splits, scaled S_PINV
__global__ void combine4(const float* __restrict__ P, const float* __restrict__ L,
                         __half* __restrict__ Rh, __half* __restrict__ Rl)
{
    int idx = blockIdx.x * 256 + threadIdx.x;
    int bhr = idx >> 6;
    const int SL = BHD * NL;
    const int SD = BHD * NL * DH;
    float l = L[bhr] + L[SL + bhr] + L[2 * SL + bhr] + L[3 * SL + bhr];
    float val = (P[idx] + P[SD + idx] + P[2 * SD + idx] + P[3 * SD + idx]) / l;
    __half h, lo2;
    split_h(val * S_PINV, h, lo2);
    Rh[idx] = h; Rl[idx] = lo2;
}

// ---------------- split kernel ----------------
__global__ void split_rm(const float* __restrict__ src, __half* __restrict__ hi,
                         __half* __restrict__ lo, float S, long long n)
{
    long long idx = (long long)blockIdx.x * 256 + threadIdx.x;
    if (idx >= n) return;
    __half h, l;
    split_h(src[idx] * S, h, l);
    hi[idx] = h; lo[idx] = l;
}

// ---------------- landmark means ----------------
__global__ void landmark_mean(const float* __restrict__ src, float* __restrict__ dst)
{
    long long idx = (long long)blockIdx.x * 256 + threadIdx.x;
    int d  = idx & 63;
    int mm = (int)((idx >> 6) & 255);
    long long bh = idx >> 14;
    const float* base = src + ((bh * NSEQ) + (long long)mm * LGRP) * DH + d;
    float s = 0.f;
    #pragma unroll
    for (int t = 0; t < LGRP; t++) s += base[(long long)t * DH];
    dst[idx] = s * (1.0f / LGRP);
}

// ---------------- row softmax (a2), emits scaled splits ----------------
__global__ void softmax_rows(float* __restrict__ data, int L,
                             __half* __restrict__ sh, __half* __restrict__ sl)
{
    long long row = blockIdx.x;
    float* p = data + row * (long long)L;
    __shared__ float red[256];
    int t = threadIdx.x;

    float mx = -INFINITY;
    for (int i = t; i < L; i += 256) mx = fmaxf(mx, p[i]);
    red[t] = mx; __syncthreads();
    for (int s = 128; s > 0; s >>= 1) { if (t < s) red[t] = fmaxf(red[t], red[t + s]); __syncthreads(); }
    mx = red[0]; __syncthreads();

    float sm = 0.f;
    for (int i = t; i < L; i += 256) { float e = expf(p[i] - mx); p[i] = e; sm += e; }
    red[t] = sm; __syncthreads();
    for (int s = 128; s > 0; s >>= 1) { if (t < s) red[t] += red[t + s]; __syncthreads(); }
    float inv = 1.f / red[0];
    for (int i = t; i < L; i += 256) {
        float val = p[i] * inv;
        p[i] = val;
        __half h, l;
        split_h(val * S_PINV, h, l);
        sh[row * L + i] = h;
        sl[row * L + i] = l;
    }
}

// ---------------- pinv init scalars ----------------
__global__ void scal_init(float* scal) { scal[0] = 0.f; scal[1] = 0.f; }

__global__ void rowsum_max(const float* __restrict__ a, float* scal)
{
    int i = blockIdx.x, bh = blockIdx.y, t = threadIdx.x;
    __shared__ float red[256];
    red[t] = a[(((long long)bh * NL) + i) * NL + t];
    __syncthreads();
    for (int s = 128; s > 0; s >>= 1) { if (t < s) red[t] += red[t + s]; __syncthreads(); }
    if (t == 0) atomicMax((int*)scal, __float_as_int(red[0]));
}

__global__ void colsum_max(const float* __restrict__ a, float* scal)
{
    int j = blockIdx.x, bh = blockIdx.y, t = threadIdx.x;
    __shared__ float red[256];
    red[t] = a[(((long long)bh * NL) + t) * NL + j];
    __syncthreads();
    for (int s = 128; s > 0; s >>= 1) { if (t < s) red[t] += red[t + s]; __syncthreads(); }
    if (t == 0) atomicMax((int*)(scal + 1), __float_as_int(red[0]));
}

// z0 = a2^T / (col*row): row-major splits, scaled
__global__ void zinit(const float* __restrict__ a,
                      __half* __restrict__ zh, __half* __restrict__ zl,
                      const float* __restrict__ scal)
{
    long long idx = (long long)blockIdx.x * 256 + threadIdx.x;
    float inv = S_PINV / (scal[0] * scal[1]);
    int j = (int)(idx & 255);
    int i = (int)((idx >> 8) & 255);
    long long bh = idx >> 16;
    float val = a[(bh << 16) + ((long long)j << 8) + i] * inv;
    __half h, l;
    split_h(val, h, l);
    zh[idx] = h; zl[idx] = l;
}

// ---------------- conv residual + add + transpose -> x2 splits ----------------
__global__ void conv_add_transpose(const float* __restrict__ oh, const float* __restrict__ v,
                                   const float* __restrict__ ker,
                                   __half* __restrict__ x2h, __half* __restrict__ x2l)
{
    long long idx = (long long)blockIdx.x * 256 + threadIdx.x;
    int d  = (int)(idx & 63);
    int h  = (int)((idx >> 6) & 7);
    int nn = (int)((idx >> 9) & 4095);
    int b  = (int)(idx >> 21);
    long long bh = (long long)b * HEADS + h;
    const float* vb = v + (bh * NSEQ) * DH + d;
    float s = 0.f;
    #pragma unroll
    for (int t = 0; t < CONV_TAPS; t++) {
        int pos = nn + t - CONV_PAD;
        if (pos >= 0 && pos < NSEQ) s += vb[(long long)pos * DH] * ker[h * CONV_TAPS + t];
    }
    float val = oh[(bh * NSEQ + nn) * DH + d] + s;
    __half hh, ll;
    split_h(val, hh, ll);
    x2h[idx] = hh; x2l[idx] = ll;
}

// ---------------- host ----------------
template<int BN, int PREC>
static void launch_h3(const __half* Ah, const __half* Al, const __half* Bh, const __half* Bl,
                      int M, int N, int K, long long sA, long long sB, int batch,
                      float scale, float outS,
                      float* Cf, long long sC, const float* bias,
                      __half* R1h, __half* R1l, long long sR1,
                      __half* R2h, __half* R2l, long long sR2, float dv,
                      int qkv, float qscale, float* qp, float* kp, float* vp,
                      cudaStream_t st = 0)
{
    size_t smem = (size_t)((PREC == 3 ? 2 : 1) * 3 * (128 * 40 + 32 * (BN + 8))) * 2;
    cudaFuncSetAttribute(gemm_h3<BN, PREC>, cudaFuncAttributeMaxDynamicSharedMemorySize, (int)smem);
    dim3 grid(N / BN, M / 128, batch);
    gemm_h3<BN, PREC><<<grid, 512, smem, st>>>(Ah, Al, Bh, Bl, M, N, K, sA, sB,
                                               scale, outS, Cf, sC, bias,
                                               R1h, R1l, sR1, R2h, R2l, sR2, dv,
                                               qkv, qscale, qp, kp, vp);
}

extern "C" void kernel_launch(void* const* d_in, const int* in_sizes, int n_in,
                              void* d_out, int out_size)
{
    const float* x      = (const float*)d_in[0];
    const float* w_qkv  = (const float*)d_in[1];
    const float* w_out  = (const float*)d_in[2];
    const float* b_out  = (const float*)d_in[3];
    const float* res_k  = (const float*)d_in[4];
    float* out = (float*)d_out;

    float *q, *k, *v, *ql, *kl, *a2, *za3v, *part, *lpart, *oh, *scal;
    cudaGetSymbolAddress((void**)&q,     g_q);
    cudaGetSymbolAddress((void**)&k,     g_k);
    cudaGetSymbolAddress((void**)&v,     g_v);
    cudaGetSymbolAddress((void**)&ql,    g_ql);
    cudaGetSymbolAddress((void**)&kl,    g_kl);
    cudaGetSymbolAddress((void**)&a2,    g_a2);
    cudaGetSymbolAddress((void**)&za3v,  g_za3v);
    cudaGetSymbolAddress((void**)&part,  g_part);
    cudaGetSymbolAddress((void**)&lpart, g_lpart);
    cudaGetSymbolAddress((void**)&oh,    g_oh);
    cudaGetSymbolAddress((void**)&scal,  g_scal);

    __half *xh, *xl, *wqh, *wql, *woh, *wol, *x2h, *x2l, *a2h, *a2l;
    __half *zAh, *zAl, *zBh, *zBl, *xzh, *xzl, *T1h, *T1l, *T2h, *T2l, *a3vh, *a3vl;
    cudaGetSymbolAddress((void**)&xh,   g_xh);
    cudaGetSymbolAddress((void**)&xl,   g_xl);
    cudaGetSymbolAddress((void**)&wqh,  g_wqh);
    cudaGetSymbolAddress((void**)&wql,  g_wql);
    cudaGetSymbolAddress((void**)&woh,  g_woh);
    cudaGetSymbolAddress((void**)&wol,  g_wol);
    cudaGetSymbolAddress((void**)&x2h,  g_x2h);
    cudaGetSymbolAddress((void**)&x2l,  g_x2l);
    cudaGetSymbolAddress((void**)&a2h,  g_a2h);
    cudaGetSymbolAddress((void**)&a2l,  g_a2l);
    cudaGetSymbolAddress((void**)&zAh,  g_zAh);
    cudaGetSymbolAddress((void**)&zAl,  g_zAl);
    cudaGetSymbolAddress((void**)&zBh,  g_zBh);
    cudaGetSymbolAddress((void**)&zBl,  g_zBl);
    cudaGetSymbolAddress((void**)&xzh,  g_xzh);
    cudaGetSymbolAddress((void**)&xzl,  g_xzl);
    cudaGetSymbolAddress((void**)&T1h,  g_T1h);
    cudaGetSymbolAddress((void**)&T1l,  g_T1l);
    cudaGetSymbolAddress((void**)&T2h,  g_T2h);
    cudaGetSymbolAddress((void**)&T2l,  g_T2l);
    cudaGetSymbolAddress((void**)&a3vh, g_a3vh);
    cudaGetSymbolAddress((void**)&a3vl, g_a3vl);

    cudaFuncSetAttribute(flash_pv<0>, cudaFuncAttributeMaxDynamicSharedMemorySize, (int)sizeof(FlashSmem));
    cudaFuncSetAttribute(flash_pv<1>, cudaFuncAttributeMaxDynamicSharedMemorySize, (int)sizeof(FlashSmem));

    const size_t pp_smem = (size_t)(2 * 3 * (128 * 40 + 32 * 136)) * 2;  // 113,664 B
    cudaFuncSetAttribute(pinv_persist, cudaFuncAttributeMaxDynamicSharedMemorySize, (int)pp_smem);

    const long long sb = (long long)NL * NL;
    const long long svd = (long long)NL * DH;

    cudaStream_t s2;
    cudaStreamCreateWithFlags(&s2, cudaStreamNonBlocking);
    cudaEvent_t evFork, evJoin;
    cudaEventCreateWithFlags(&evFork, cudaEventDisableTiming);
    cudaEventCreateWithFlags(&evJoin, cudaEventDisableTiming);

    // 0) operand splits
    {
        long long n = (long long)BATCH * NSEQ * DIM;
        split_rm<<<(unsigned)((n + 255) / 256), 256>>>(x, xh, xl, 1.0f, n);
        long long nw = (long long)DIM * 3 * DIM;
        split_rm<<<(unsigned)((nw + 255) / 256), 256>>>(w_qkv, wqh, wql, S_W, nw);
        long long nw2 = (long long)DIM * DIM;
        split_rm<<<(unsigned)((nw2 + 255) / 256), 256>>>(w_out, woh, wol, S_W, nw2);
    }

    // 1) qkv projection (fp16x3, 512-thread GEMM) + scatter
    launch_h3<128, 3>(xh, xl, wqh, wql, BATCH * NSEQ, 3 * DIM, DIM, 0, 0, 1,
                      1.0f / S_W, 1.0f,
                      nullptr, 0, nullptr, nullptr, nullptr, 0,
                      nullptr, nullptr, 0, 0.f, 1, 0.125f, q, k, v);

    // 2) landmarks
    {
        long long n = (long long)BHD * NL * DH;
        landmark_mean<<<(unsigned)(n / 256), 256>>>(q, ql);
        landmark_mean<<<(unsigned)(n / 256), 256>>>(k, kl);
    }

    // ---- fork: flash1 (a3v) on s2, concurrent with a2/softmax/pinv ----
    cudaEventRecord(evFork, 0);
    cudaStreamWaitEvent(s2, evFork, 0);
    {
        dim3 grid(NL / 128, 4, BHD);
        flash_pv<1><<<grid, 256, sizeof(FlashSmem), s2>>>(ql, k, v, part, lpart, NL, NSEQ, NSEQ / 4);
        combine4<<<(BHD * NL * DH) / 256, 256, 0, s2>>>(part, lpart, a3vh, a3vl);
    }
    cudaEventRecord(evJoin, s2);

    // 3) a2 = ql @ kl^T (tf32x3, fp32) + softmax (emits splits)
    {
        size_t smem = (size_t)(3 * 128 * 20 + 3 * 128 * 20) * 4;
        cudaFuncSetAttribute(gemm_tf32<128, 1>, cudaFuncAttributeMaxDynamicSharedMemorySize, (int)smem);
        dim3 grid(NL / 128, NL / 128, BHD);
        gemm_tf32<128, 1><<<grid, 256, smem>>>(ql, kl, a2, NL, NL, DH, svd, svd, sb);
    }
    softmax_rows<<<BHD * NL, 256>>>(a2, NL, a2h, a2l);

    // 4) pinv init
    scal_init<<<1, 1>>>(scal);
    {
        dim3 g(NL, BHD);
        rowsum_max<<<g, 256>>>(a2, scal);
        colsum_max<<<g, 256>>>(a2, scal);
    }
    zinit<<<(unsigned)((long long)BHD * NL * NL / 256), 256>>>(a2, zAh, zAl, scal);

    // 5) Newton iterations — ONE persistent kernel, grid barrier between
    //    steps. 5 iterations: 4 cheap (1-pass fp16) + 1 full (3-pass),
    //    justified by the iteration's 3rd-order contraction.
    __half *zch = zAh, *zcl = zAl, *znh = zBh, *znl = zBl;
    const float sa2 = 1.0f / (S_PINV * S_PINV);
    {
        PinvPlan plan;
        int idx = 0;
        const int NITER = 5;
        for (int it = 0; it < NITER; it++) {
            int prec = (it < NITER - 1) ? 1 : 3;
            // xz = a2 @ z : R1 = xz, R2 = 7I - xz
            plan.s[idx++] = { a2h, a2l, zch, zcl, xzh, xzl, T1h, T1l, 7.0f, sa2, prec };
            // t1 = xz @ e7 : R2 = 15I - t1
            plan.s[idx++] = { xzh, xzl, T1h, T1l, nullptr, nullptr, T2h, T2l, 15.0f, sa2, prec };
            // t2 = xz @ s15 : R2 = 13I - t2
            plan.s[idx++] = { xzh, xzl, T2h, T2l, nullptr, nullptr, T1h, T1l, 13.0f, sa2, prec };
            // z' = 0.25 z @ s13 : R1 = z'
            plan.s[idx++] = { zch, zcl, T1h, T1l, znh, znl, nullptr, nullptr, 0.f, 0.25f * sa2, prec };
            __half* t;
            t = zch; zch = znh; znh = t;
            t = zcl; zcl = znl; znl = t;
        }
        plan.n = idx;
        bar_reset<<<1, 1>>>();
        dim3 grid(2, 2, BHD);
        pinv_persist<<<grid, 512, pp_smem>>>(plan);
    }

    // ---- join: za3v needs a3v from s2 ----
    cudaStreamWaitEvent(0, evJoin, 0);

    // 7) za3v = z @ a3v (fp16x3) -> fp32
    launch_h3<64, 3>(zch, zcl, a3vh, a3vl, NL, DH, NL, sb, svd, BHD,
                     sa2, 1.0f, za3v, svd, nullptr,
                     nullptr, nullptr, 0, nullptr, nullptr, 0, 0.f,
                     0, 0.f, nullptr, nullptr, nullptr);

    // 8) oh = softmax(q @ kl^T) @ za3v — flash
    {
        dim3 grid(NSEQ / 128, 1, BHD);
        flash_pv<0><<<grid, 256, sizeof(FlashSmem)>>>(q, kl, za3v, oh, nullptr, NSEQ, NL, NL);
    }

    // 9) conv residual + add + transpose -> x2 splits
    conv_add_transpose<<<(unsigned)((long long)BATCH * NSEQ * HEADS * DH / 256), 256>>>(oh, v, res_k, x2h, x2l);

    // 10) out = x2 @ w_out + b_out (fp16x3)
    launch_h3<128, 3>(x2h, x2l, woh, wol, BATCH * NSEQ, DIM, DIM, 0, 0, 1,
                      1.0f / S_W, 1.0f,
                      out, 0, b_out, nullptr, nullptr, 0,
                      nullptr, nullptr, 0, 0.f, 0, 0.f, nullptr, nullptr, nullptr);

    cudaEventDestroy(evFork);
    cudaEventDestroy(evJoin);
    cudaStreamDestroy(s2);
}

// round 12
// speedup vs baseline: 1.0108x; 1.0108x over previous
#include <cuda_runtime.h>
#include <cuda_fp16.h>
#include <math.h>
#include <stdint.h>

// ---------------- problem constants ----------------
#define BATCH 4
#define HEADS 8
#define NSEQ  4096
#define DH    64
#define DIM   512
#define NL    256
#define LGRP  16
#define BHD   (BATCH*HEADS)
#define CONV_TAPS 33
#define CONV_PAD 16

#define S_PINV 64.0f
#define S_W    256.0f

// ---------------- scratch (fp32) ----------------
__device__ float g_q [(size_t)BHD*NSEQ*DH];
__device__ float g_k [(size_t)BHD*NSEQ*DH];
__device__ float g_v [(size_t)BHD*NSEQ*DH];
__device__ float g_ql[(size_t)BHD*NL*DH];
__device__ float g_kl[(size_t)BHD*NL*DH];
__device__ float g_a2[(size_t)BHD*NL*NL];
__device__ float g_za3v[(size_t)BHD*NL*DH];
__device__ float g_part[(size_t)4*BHD*NL*DH];
__device__ float g_lpart[(size_t)4*BHD*NL];
__device__ float g_oh [(size_t)BHD*NSEQ*DH];
__device__ float g_scal[2];
__device__ unsigned g_barz[BHD];

// ---------------- scratch (half splits; all row-major) ----------------
__device__ __half g_xh [(size_t)BATCH*NSEQ*DIM];
__device__ __half g_xl [(size_t)BATCH*NSEQ*DIM];
__device__ __half g_wqh[(size_t)DIM*3*DIM];
__device__ __half g_wql[(size_t)DIM*3*DIM];
__device__ __half g_woh[(size_t)DIM*DIM];
__device__ __half g_wol[(size_t)DIM*DIM];
__device__ __half g_x2h[(size_t)BATCH*NSEQ*DIM];
__device__ __half g_x2l[(size_t)BATCH*NSEQ*DIM];
__device__ __half g_a2h[(size_t)BHD*NL*NL];
__device__ __half g_a2l[(size_t)BHD*NL*NL];
__device__ __half g_zAh[(size_t)BHD*NL*NL];
__device__ __half g_zAl[(size_t)BHD*NL*NL];
__device__ __half g_zBh[(size_t)BHD*NL*NL];
__device__ __half g_zBl[(size_t)BHD*NL*NL];
__device__ __half g_xzh[(size_t)BHD*NL*NL];
__device__ __half g_xzl[(size_t)BHD*NL*NL];
__device__ __half g_T1h[(size_t)BHD*NL*NL];
__device__ __half g_T1l[(size_t)BHD*NL*NL];
__device__ __half g_T2h[(size_t)BHD*NL*NL];
__device__ __half g_T2l[(size_t)BHD*NL*NL];
__device__ __half g_a3vh[(size_t)BHD*NL*DH];
__device__ __half g_a3vl[(size_t)BHD*NL*DH];

// ---------------- helpers ----------------
__device__ __forceinline__ void split_tf32(float v, uint32_t &hi, uint32_t &lo) {
    asm("cvt.rna.tf32.f32 %0, %1;" : "=r"(hi) : "f"(v));
    float r = v - __uint_as_float(hi);
    asm("cvt.rna.tf32.f32 %0, %1;" : "=r"(lo) : "f"(r));
}

__device__ __forceinline__ void split_h(float v, __half &hi, __half &lo) {
    hi = __float2half_rn(v);
    lo = __float2half_rn(v - __half2float(hi));
}

#define MMA_TF32(D, A0,A1,A2,A3, B0,B1) \
    asm volatile("mma.sync.aligned.m16n8k8.row.col.f32.tf32.tf32.f32 " \
                 "{%0,%1,%2,%3},{%4,%5,%6,%7},{%8,%9},{%0,%1,%2,%3};" \
                 : "+f"((D)[0]), "+f"((D)[1]), "+f"((D)[2]), "+f"((D)[3]) \
                 : "r"(A0), "r"(A1), "r"(A2), "r"(A3), "r"(B0), "r"(B1))

#define MMA_F16(D, a0,a1,a2,a3, b0,b1) \
    asm volatile("mma.sync.aligned.m16n8k16.row.col.f32.f16.f16.f32 " \
                 "{%0,%1,%2,%3},{%4,%5,%6,%7},{%8,%9},{%0,%1,%2,%3};" \
                 : "+f"((D)[0]), "+f"((D)[1]), "+f"((D)[2]), "+f"((D)[3]) \
                 : "r"(a0), "r"(a1), "r"(a2), "r"(a3), "r"(b0), "r"(b1))

__device__ __forceinline__ void cp16(void* smem, const void* g) {
    uint32_t sa = (uint32_t)__cvta_generic_to_shared(smem);
    asm volatile("cp.async.ca.shared.global [%0], [%1], 16;" :: "r"(sa), "l"(g));
}
// L2-only variant: required when re-reading buffers rewritten by other SMs
// within one persistent kernel (L1 is not coherent and not invalidated).
__device__ __forceinline__ void cp16cg(void* smem, const void* g) {
    uint32_t sa = (uint32_t)__cvta_generic_to_shared(smem);
    asm volatile("cp.async.cg.shared.global [%0], [%1], 16;" :: "r"(sa), "l"(g));
}
#define CP_COMMIT asm volatile("cp.async.commit_group;")
#define CP_WAIT0  asm volatile("cp.async.wait_group 0;")
#define CP_WAIT1  asm volatile("cp.async.wait_group 1;")

__device__ __forceinline__ uint32_t packh2(float a, float b) {
    __half2 h = __floats2half2_rn(a, b);
    return *reinterpret_cast<uint32_t*>(&h);
}

__device__ __forceinline__ void ldsm4(uint32_t* r, const __half* p) {
    uint32_t a = (uint32_t)__cvta_generic_to_shared(p);
    asm volatile("ldmatrix.sync.aligned.m8n8.x4.shared.b16 {%0,%1,%2,%3}, [%4];"
                 : "=r"(r[0]), "=r"(r[1]), "=r"(r[2]), "=r"(r[3]) : "r"(a));
}
__device__ __forceinline__ void ldsm4t(uint32_t* r, const __half* p) {
    uint32_t a = (uint32_t)__cvta_generic_to_shared(p);
    asm volatile("ldmatrix.sync.aligned.m8n8.x4.trans.shared.b16 {%0,%1,%2,%3}, [%4];"
                 : "=r"(r[0]), "=r"(r[1]), "=r"(r[2]), "=r"(r[3]) : "r"(a));
}

// ================= fp16 batched GEMM — 512 threads, warp tile 32x32 =====
template<int BN, int PREC>
__global__ void __launch_bounds__(512, 1)
gemm_h3(const __half* __restrict__ Ahg, const __half* __restrict__ Alg,
        const __half* __restrict__ Bhg, const __half* __restrict__ Blg,
        int M, int N, int K, long long sA, long long sB,
        float scale, float outS,
        float* __restrict__ Cf, long long sC, const float* __restrict__ bias,
        __half* __restrict__ R1h, __half* __restrict__ R1l, long long sR1,
        __half* __restrict__ R2h, __half* __restrict__ R2l, long long sR2, float dv,
        int qkv, float qscale,
        float* __restrict__ qp, float* __restrict__ kp, float* __restrict__ vp)
{
    constexpr int NT  = BN / 32;
    constexpr int ALD = 40;
    constexpr int BLD = BN + 8;
    constexpr int ASZ = 128 * ALD;
    constexpr int BSZ = 32 * BLD;

    const int zb = blockIdx.z;
    const __half* Ah_g = Ahg + (long long)zb * sA;
    const __half* Al_g = Alg + (long long)zb * sA;
    const __half* Bh_g = Bhg + (long long)zb * sB;
    const __half* Bl_g = Blg + (long long)zb * sB;
    if (Cf)  Cf  += (long long)zb * sC;
    if (R1h) { R1h += (long long)zb * sR1; R1l += (long long)zb * sR1; }
    if (R2h) { R2h += (long long)zb * sR2; R2l += (long long)zb * sR2; }

    extern __shared__ __half hsm[];
    __half* Ash = hsm;
    __half* Asl = Ash + 3 * ASZ;
    __half* Bsh = (PREC == 3) ? (Asl + 3 * ASZ) : (Ash + 3 * ASZ);
    __half* Bsl = Bsh + 3 * BSZ;

    const int brow = blockIdx.y * 128;
    const int bcol = blockIdx.x * BN;

    const int tid  = threadIdx.x;
    const int warp = tid >> 5;
    const int lane = tid & 31;
    const int wm   = warp & 3;
    const int wn   = warp >> 2;
    const int grp  = lane >> 2;
    const int t4   = lane & 3;
    const int r8   = lane & 7;
    const int quad = lane >> 3;

    const int nk = K / 32;

    auto load_stage = [&](int s, int kt) {
        int k0 = kt * 32;
        {
            int row = tid >> 2, seg = (tid & 3) * 8;
            cp16(&Ash[(s * 128 + row) * ALD + seg], &Ah_g[(long long)(brow + row) * K + k0 + seg]);
            if (PREC == 3)
                cp16(&Asl[(s * 128 + row) * ALD + seg], &Al_g[(long long)(brow + row) * K + k0 + seg]);
        }
        if (tid < BN * 4) {
            int row = tid / (BN / 8), seg = (tid % (BN / 8)) * 8;
            cp16(&Bsh[(s * 32 + row) * BLD + seg], &Bh_g[(long long)(k0 + row) * N + bcol + seg]);
            if (PREC == 3)
                cp16(&Bsl[(s * 32 + row) * BLD + seg], &Bl_g[(long long)(k0 + row) * N + bcol + seg]);
        }
    };

    float acc[2][NT][4];
    #pragma unroll
    for (int i = 0; i < 2; i++)
        #pragma unroll
        for (int j = 0; j < NT; j++)
            #pragma unroll
            for (int l = 0; l < 4; l++) acc[i][j][l] = 0.f;

    load_stage(0, 0); CP_COMMIT;
    load_stage(1, 1); CP_COMMIT;

    for (int kt = 0; kt < nk; kt++) {
        CP_WAIT1;
        __syncthreads();
        int buf = kt % 3;
        if (kt + 2 < nk) load_stage((kt + 2) % 3, kt + 2);
        CP_COMMIT;

        #pragma unroll
        for (int ss = 0; ss < 2; ss++) {
            int kb = ss * 16;
            uint32_t ah[2][4], al[2][4];
            #pragma unroll
            for (int mt = 0; mt < 2; mt++) {
                int m0 = wm * 32 + mt * 16;
                int off = (buf * 128 + m0 + r8 + (quad & 1) * 8) * ALD + kb + (quad >> 1) * 8;
                ldsm4(ah[mt], Ash + off);
                if (PREC == 3) ldsm4(al[mt], Asl + off);
            }
            uint32_t bh[NT][2], bl[NT][2];
            #pragma unroll
            for (int np = 0; np < NT / 2; np++) {
                int n0 = wn * (BN / 4) + np * 16;
                int off = (buf * 32 + kb + (quad & 1) * 8 + r8) * BLD + n0 + (quad >> 1) * 8;
                uint32_t tb[4];
                ldsm4t(tb, Bsh + off);
                bh[np * 2][0] = tb[0]; bh[np * 2][1] = tb[1];
                bh[np * 2 + 1][0] = tb[2]; bh[np * 2 + 1][1] = tb[3];
                if (PREC == 3) {
                    ldsm4t(tb, Bsl + off);
                    bl[np * 2][0] = tb[0]; bl[np * 2][1] = tb[1];
                    bl[np * 2 + 1][0] = tb[2]; bl[np * 2 + 1][1] = tb[3];
                }
            }
            #pragma unroll
            for (int mt = 0; mt < 2; mt++)
                #pragma unroll
                for (int nt = 0; nt < NT; nt++) {
                    MMA_F16(acc[mt][nt], ah[mt][0], ah[mt][1], ah[mt][2], ah[mt][3], bh[nt][0], bh[nt][1]);
                    if (PREC == 3) {
                        MMA_F16(acc[mt][nt], ah[mt][0], ah[mt][1], ah[mt][2], ah[mt][3], bl[nt][0], bl[nt][1]);
                        MMA_F16(acc[mt][nt], al[mt][0], al[mt][1], al[mt][2], al[mt][3], bh[nt][0], bh[nt][1]);
                    }
                }
        }
    }

    #pragma unroll
    for (int mt = 0; mt < 2; mt++) {
        int r0 = brow + wm * 32 + mt * 16 + grp;
        #pragma unroll
        for (int nt = 0; nt < NT; nt++) {
            int c = bcol + wn * (BN / 4) + nt * 8 + t4 * 2;
            #pragma unroll
            for (int half_i = 0; half_i < 2; half_i++) {
                int r = r0 + half_i * 8;
                float v0 = acc[mt][nt][half_i * 2 + 0] * scale;
                float v1 = acc[mt][nt][half_i * 2 + 1] * scale;
                if (qkv) {
                    int bidx = r >> 12, nn = r & 4095;
                    int part = c / DIM, rem = c % DIM;
                    int hh = rem >> 6, dd = rem & 63;
                    long long dst = ((((long long)bidx * HEADS + hh) * NSEQ) + nn) * DH + dd;
                    float2 val;
                    if (part == 0) { val.x = v0 * qscale; val.y = v1 * qscale; *(float2*)&qp[dst] = val; }
                    else if (part == 1) { val.x = v0; val.y = v1; *(float2*)&kp[dst] = val; }
                    else { val.x = v0; val.y = v1; *(float2*)&vp[dst] = val; }
                } else {
                    if (Cf) {
                        float b0 = bias ? bias[c] : 0.f;
                        float b1 = bias ? bias[c + 1] : 0.f;
                        float2 val; val.x = v0 + b0; val.y = v1 + b1;
                        *(float2*)&Cf[(long long)r * N + c] = val;
                    }
                    if (R1h) {
                        __half h0, l0, h1, l1;
                        split_h(v0 * outS, h0, l0);
                        split_h(v1 * outS, h1, l1);
                        __half2 hp; hp.x = h0; hp.y = h1;
                        __half2 lp; lp.x = l0; lp.y = l1;
                        *(__half2*)&R1h[(long long)r * N + c] = hp;
                        *(__half2*)&R1l[(long long)r * N + c] = lp;
                    }
                    if (R2h) {
                        float tv0 = (((r == c) ? dv : 0.f) - v0) * outS;
                        float tv1 = (((r == c + 1) ? dv : 0.f) - v1) * outS;
                        __half h0, l0, h1, l1;
                        split_h(tv0, h0, l0);
                        split_h(tv1, h1, l1);
                        __half2 hp; hp.x = h0; hp.y = h1;
                        __half2 lp; lp.x = l0; lp.y = l1;
                        *(__half2*)&R2h[(long long)r * N + c] = hp;
                        *(__half2*)&R2l[(long long)r * N + c] = lp;
                    }
                }
            }
        }
    }
}

// ================= persistent pinv kernel (per-z barriers) =================
// 20 GEMM steps in ONE kernel. Grid (2,2,32) = 128 blocks, all co-resident.
// Cross-step dependencies exist only among the 4 blocks sharing one z (bh),
// so sync is a 4-block counter per z — no global skew coupling.
// Loads use cp.async.cg (L2-only): buffers are rewritten by other SMs
// between steps and L1 would serve stale lines.
struct PinvStep {
    const __half *Ah, *Al, *Bh, *Bl;
    __half *R1h, *R1l, *R2h, *R2l;
    float dv, scale;
    int prec;
};
struct PinvPlan { PinvStep s[20]; int n; };

__global__ void bar_reset() { if (threadIdx.x < BHD) g_barz[threadIdx.x] = 0; }

__global__ void __launch_bounds__(512, 1)
pinv_persist(PinvPlan plan)
{
    constexpr int ALD = 40, BLD = 136, ASZ = 128 * ALD, BSZ = 32 * BLD;
    extern __shared__ __half hsm[];
    __half* Ash = hsm;
    __half* Asl = Ash + 3 * ASZ;
    __half* Bsh = Asl + 3 * ASZ;
    __half* Bsl = Bsh + 3 * BSZ;

    const int tid  = threadIdx.x;
    const int warp = tid >> 5;
    const int lane = tid & 31;
    const int wm   = warp & 3;
    const int wn   = warp >> 2;
    const int grp  = lane >> 2;
    const int t4   = lane & 3;
    const int r8   = lane & 7;
    const int quad = lane >> 3;
    const int brow = blockIdx.y * 128;
    const int bcol = blockIdx.x * 128;
    const int z    = blockIdx.z;
    const long long zoff = (long long)z * (NL * NL);

    for (int st = 0; st < plan.n; st++) {
        const __half* Ah = plan.s[st].Ah + zoff;
        const __half* Al = plan.s[st].Al + zoff;
        const __half* Bh = plan.s[st].Bh + zoff;
        const __half* Bl = plan.s[st].Bl + zoff;
        const int prec = plan.s[st].prec;

        auto load_stage = [&](int s, int kt) {
            int k0 = kt * 32;
            {
                int row = tid >> 2, seg = (tid & 3) * 8;
                cp16cg(&Ash[(s * 128 + row) * ALD + seg], &Ah[(long long)(brow + row) * NL + k0 + seg]);
                if (prec == 3)
                    cp16cg(&Asl[(s * 128 + row) * ALD + seg], &Al[(long long)(brow + row) * NL + k0 + seg]);
            }
            {
                int row = tid >> 4, seg = (tid & 15) * 8;
                cp16cg(&Bsh[(s * 32 + row) * BLD + seg], &Bh[(long long)(k0 + row) * NL + bcol + seg]);
                if (prec == 3)
                    cp16cg(&Bsl[(s * 32 + row) * BLD + seg], &Bl[(long long)(k0 + row) * NL + bcol + seg]);
            }
        };

        float acc[2][4][4];
        #pragma unroll
        for (int i = 0; i < 2; i++)
            #pragma unroll
            for (int j = 0; j < 4; j++)
                #pragma unroll
                for (int l = 0; l < 4; l++) acc[i][j][l] = 0.f;

        load_stage(0, 0); CP_COMMIT;
        load_stage(1, 1); CP_COMMIT;

        for (int kt = 0; kt < 8; kt++) {
            CP_WAIT1;
            __syncthreads();
            int buf = kt % 3;
            if (kt + 2 < 8) load_stage((kt + 2) % 3, kt + 2);
            CP_COMMIT;

            #pragma unroll
            for (int ss = 0; ss < 2; ss++) {
                int kb = ss * 16;
                uint32_t ah[2][4], al[2][4];
                #pragma unroll
                for (int mt = 0; mt < 2; mt++) {
                    int m0 = wm * 32 + mt * 16;
                    int off = (buf * 128 + m0 + r8 + (quad & 1) * 8) * ALD + kb + (quad >> 1) * 8;
                    ldsm4(ah[mt], Ash + off);
                    if (prec == 3) ldsm4(al[mt], Asl + off);
                }
                uint32_t bh[4][2], bl[4][2];
                #pragma unroll
                for (int np = 0; np < 2; np++) {
                    int n0 = wn * 32 + np * 16;
                    int off = (buf * 32 + kb + (quad & 1) * 8 + r8) * BLD + n0 + (quad >> 1) * 8;
                    uint32_t tb[4];
                    ldsm4t(tb, Bsh + off);
                    bh[np * 2][0] = tb[0]; bh[np * 2][1] = tb[1];
                    bh[np * 2 + 1][0] = tb[2]; bh[np * 2 + 1][1] = tb[3];
                    if (prec == 3) {
                        ldsm4t(tb, Bsl + off);
                        bl[np * 2][0] = tb[0]; bl[np * 2][1] = tb[1];
                        bl[np * 2 + 1][0] = tb[2]; bl[np * 2 + 1][1] = tb[3];
                    }
                }
                #pragma unroll
                for (int mt = 0; mt < 2; mt++)
                    #pragma unroll
                    for (int nt = 0; nt < 4; nt++) {
                        MMA_F16(acc[mt][nt], ah[mt][0], ah[mt][1], ah[mt][2], ah[mt][3], bh[nt][0], bh[nt][1]);
                        if (prec == 3) {
                            MMA_F16(acc[mt][nt], ah[mt][0], ah[mt][1], ah[mt][2], ah[mt][3], bl[nt][0], bl[nt][1]);
                            MMA_F16(acc[mt][nt], al[mt][0], al[mt][1], al[mt][2], al[mt][3], bh[nt][0], bh[nt][1]);
                        }
                    }
            }
        }
        CP_WAIT0;

        const float scale = plan.s[st].scale;
        const float dv = plan.s[st].dv;
        __half* R1h = plan.s[st].R1h ? plan.s[st].R1h + zoff : nullptr;
        __half* R1l = plan.s[st].R1l ? plan.s[st].R1l + zoff : nullptr;
        __half* R2h = plan.s[st].R2h ? plan.s[st].R2h + zoff : nullptr;
        __half* R2l = plan.s[st].R2l ? plan.s[st].R2l + zoff : nullptr;

        #pragma unroll
        for (int mt = 0; mt < 2; mt++) {
            int r0 = brow + wm * 32 + mt * 16 + grp;
            #pragma unroll
            for (int nt = 0; nt < 4; nt++) {
                int c = bcol + wn * 32 + nt * 8 + t4 * 2;
                #pragma unroll
                for (int half_i = 0; half_i < 2; half_i++) {
                    int r = r0 + half_i * 8;
                    float v0 = acc[mt][nt][half_i * 2 + 0] * scale;
                    float v1 = acc[mt][nt][half_i * 2 + 1] * scale;
                    if (R1h) {
                        __half h0, l0, h1, l1;
                        split_h(v0 * S_PINV, h0, l0);
                        split_h(v1 * S_PINV, h1, l1);
                        __half2 hp; hp.x = h0; hp.y = h1;
                        __half2 lp; lp.x = l0; lp.y = l1;
                        *(__half2*)&R1h[(long long)r * NL + c] = hp;
                        *(__half2*)&R1l[(long long)r * NL + c] = lp;
                    }
                    if (R2h) {
                        float tv0 = (((r == c) ? dv : 0.f) - v0) * S_PINV;
                        float tv1 = (((r == c + 1) ? dv : 0.f) - v1) * S_PINV;
                        __half h0, l0, h1, l1;
                        split_h(tv0, h0, l0);
                        split_h(tv1, h1, l1);
                        __half2 hp; hp.x = h0; hp.y = h1;
                        __half2 lp; lp.x = l0; lp.y = l1;
                        *(__half2*)&R2h[(long long)r * NL + c] = hp;
                        *(__half2*)&R2l[(long long)r * NL + c] = lp;
                    }
                }
            }
        }

        // ---- per-z barrier (4 blocks) ----
        __syncthreads();
        __threadfence();
        if (tid == 0) {
            atomicAdd(&g_barz[z], 1u);
            unsigned target = (unsigned)(st + 1) * 4u;
            while (*(volatile unsigned*)&g_barz[z] < target) __nanosleep(32);
        }
        __syncthreads();
        __threadfence();
    }
}

// ================= 3xTF32 GEMM (a2 = ql @ kl^T only) =================
template<int BN, int TB>
__global__ void __launch_bounds__(256, 1)
gemm_tf32(const float* __restrict__ Ag, const float* __restrict__ Bg,
          float* __restrict__ Cg, int M, int N, int K,
          long long sA, long long sB, long long sC)
{
    constexpr int NT   = BN / 32;
    constexpr int BSZ  = TB ? BN * 20 : 16 * (BN + 8);
    constexpr int ASZ  = 128 * 20;

    extern __shared__ char dynsm[];
    float* As = (float*)dynsm;
    float* Bs = As + 3 * ASZ;

    const float* A = Ag + (long long)blockIdx.z * sA;
    const float* B = Bg + (long long)blockIdx.z * sB;
    float*       C = Cg + (long long)blockIdx.z * sC;

    const int brow = blockIdx.y * 128;
    const int bcol = blockIdx.x * BN;

    const int tid  = threadIdx.x;
    const int warp = tid >> 5;
    const int lane = tid & 31;
    const int wm   = warp & 1;
    const int wn   = warp >> 1;
    const int grp  = lane >> 2;
    const int t4   = lane & 3;

    const int a_row0 = tid >> 2;
    const int a_k    = (tid & 3) * 4;
    const int nk = K / 16;

    auto load_stage = [&](int s, int kt) {
        int k0 = kt * 16;
        cp16(&As[s * ASZ + a_row0 * 20 + a_k],        &A[(long long)(brow + a_row0) * K + k0 + a_k]);
        cp16(&As[s * ASZ + (a_row0 + 64) * 20 + a_k], &A[(long long)(brow + a_row0 + 64) * K + k0 + a_k]);
        #pragma unroll
        for (int j = 0; j < BN / 64; j++) {
            int i = tid + 256 * j;
            int n  = i >> 2;
            int kq = (i & 3) * 4;
            cp16(&Bs[s * BSZ + n * 20 + kq], &B[(long long)(bcol + n) * K + k0 + kq]);
        }
    };

    float acc[4][NT][4];
    #pragma unroll
    for (int i = 0; i < 4; i++)
        #pragma unroll
        for (int j = 0; j < NT; j++)
            #pragma unroll
            for (int l = 0; l < 4; l++) acc[i][j][l] = 0.f;

    load_stage(0, 0); CP_COMMIT;
    load_stage(1, 1); CP_COMMIT;

    for (int kt = 0; kt < nk; kt++) {
        CP_WAIT1;
        __syncthreads();
        int buf = kt % 3;
        if (kt + 2 < nk) load_stage((kt + 2) % 3, kt + 2);
        CP_COMMIT;

        #pragma unroll
        for (int ss = 0; ss < 2; ss++) {
            int kb = ss * 8;
            uint32_t ah[4][4], al[4][4];
            #pragma unroll
            for (int mt = 0; mt < 4; mt++) {
                int m = wm * 64 + mt * 16 + grp;
                float f0 = As[buf * ASZ + m * 20 + kb + t4];
                float f1 = As[buf * ASZ + (m + 8) * 20 + kb + t4];
                float f2 = As[buf * ASZ + m * 20 + kb + t4 + 4];
                float f3 = As[buf * ASZ + (m + 8) * 20 + kb + t4 + 4];
                split_tf32(f0, ah[mt][0], al[mt][0]);
                split_tf32(f1, ah[mt][1], al[mt][1]);
                split_tf32(f2, ah[mt][2], al[mt][2]);
                split_tf32(f3, ah[mt][3], al[mt][3]);
            }
            uint32_t bh[NT][2], bl[NT][2];
            #pragma unroll
            for (int nt = 0; nt < NT; nt++) {
                int n = wn * (BN / 4) + nt * 8 + grp;
                float b0 = Bs[buf * BSZ + n * 20 + kb + t4];
                float b1 = Bs[buf * BSZ + n * 20 + kb + t4 + 4];
                split_tf32(b0, bh[nt][0], bl[nt][0]);
                split_tf32(b1, bh[nt][1], bl[nt][1]);
            }
            #pragma unroll
            for (int mt = 0; mt < 4; mt++)
                #pragma unroll
                for (int nt = 0; nt < NT; nt++) {
                    MMA_TF32(acc[mt][nt], ah[mt][0], ah[mt][1], ah[mt][2], ah[mt][3], bh[nt][0], bh[nt][1]);
                    MMA_TF32(acc[mt][nt], ah[mt][0], ah[mt][1], ah[mt][2], ah[mt][3], bl[nt][0], bl[nt][1]);
                    MMA_TF32(acc[mt][nt], al[mt][0], al[mt][1], al[mt][2], al[mt][3], bh[nt][0], bh[nt][1]);
                }
        }
    }

    #pragma unroll
    for (int mt = 0; mt < 4; mt++) {
        int r0 = brow + wm * 64 + mt * 16 + grp;
        #pragma unroll
        for (int nt = 0; nt < NT; nt++) {
            int c = bcol + wn * (BN / 4) + nt * 8 + t4 * 2;
            #pragma unroll
            for (int half_i = 0; half_i < 2; half_i++) {
                int r = r0 + half_i * 8;
                float2 val;
                val.x = acc[mt][nt][half_i * 2 + 0];
                val.y = acc[mt][nt][half_i * 2 + 1];
                *(float2*)&C[(long long)r * N + c] = val;
            }
        }
    }
}

// ---------------- fused flash kernel ----------------
struct FlashSmem {
    float  qhi[128][68];
    float  qlo[128][68];
    float  raw[2][2][64][64];
    float  khi[64][68];
    float  klo[64][68];
    __half vh[64][72];
};

template<int PARTIAL>
__global__ void __launch_bounds__(256, 1)
flash_pv(const float* __restrict__ Qg, const float* __restrict__ Kg,
         const float* __restrict__ Vg, float* __restrict__ Og,
         float* __restrict__ Lg, int rows, int keys, int kvchunk)
{
    extern __shared__ char dynsm[];
    FlashSmem& sm = *reinterpret_cast<FlashSmem*>(dynsm);

    const int tid  = threadIdx.x;
    const int warp = tid >> 5;
    const int lane = tid & 31;
    const int grp  = lane >> 2;
    const int t4   = lane & 3;
    const int bh   = blockIdx.z;

    const long long qbase = ((long long)bh * rows + blockIdx.x * 128) * 64;
    const long long kbase = ((long long)bh * keys + (long long)blockIdx.y * kvchunk) * 64;

    #pragma unroll
    for (int j = 0; j < 8; j++) {
        int e = tid + 256 * j;
        int r = e >> 4, c4 = (e & 15) * 4;
        float4 qv = *(const float4*)&Qg[qbase + (long long)r * 64 + c4];
        uint32_t hi, lo;
        split_tf32(qv.x, hi, lo); sm.qhi[r][c4+0] = __uint_as_float(hi); sm.qlo[r][c4+0] = __uint_as_float(lo);
        split_tf32(qv.y, hi, lo); sm.qhi[r][c4+1] = __uint_as_float(hi); sm.qlo[r][c4+1] = __uint_as_float(lo);
        split_tf32(qv.z, hi, lo); sm.qhi[r][c4+2] = __uint_as_float(hi); sm.qlo[r][c4+2] = __uint_as_float(lo);
        split_tf32(qv.w, hi, lo); sm.qhi[r][c4+3] = __uint_as_float(hi); sm.qlo[r][c4+3] = __uint_as_float(lo);
    }

    auto stage = [&](int slot, int sub) {
        long long base = kbase + (long long)sub * 64 * 64;
        #pragma unroll
        for (int j = 0; j < 4; j++) {
            int e = tid + 256 * j;
            int r = e >> 4, c4 = (e & 15) * 4;
            cp16(&sm.raw[slot][0][r][c4], &Kg[base + (long long)r * 64 + c4]);
        }
        #pragma unroll
        for (int j = 0; j < 4; j++) {
            int e = tid + 256 * j;
            int r = e >> 4, c4 = (e & 15) * 4;
            cp16(&sm.raw[slot][1][r][c4], &Vg[base + (long long)r * 64 + c4]);
        }
    };

    const int nsub = kvchunk / 64;
    stage(0, 0); CP_COMMIT;

    float o[8][4];
    #pragma unroll
    for (int i = 0; i < 8; i++)
        #pragma unroll
        for (int j = 0; j < 4; j++) o[i][j] = 0.f;
    float l0 = 0.f, l1 = 0.f;
    const int r0s = warp * 16 + grp;

    for (int sub = 0; sub < nsub; sub++) {
        CP_WAIT0;
        __syncthreads();
        int slot = sub & 1;
        if (sub + 1 < nsub) stage(slot ^ 1, sub + 1);
        CP_COMMIT;

        #pragma unroll
        for (int j = 0; j < 4; j++) {
            int e = tid + 256 * j;
            int r = e >> 4, c4 = (e & 15) * 4;
            float4 kv = *(const float4*)&sm.raw[slot][0][r][c4];
            uint32_t hi, lo;
            split_tf32(kv.x, hi, lo); sm.khi[r][c4+0] = __uint_as_float(hi); sm.klo[r][c4+0] = __uint_as_float(lo);
            split_tf32(kv.y, hi, lo); sm.khi[r][c4+1] = __uint_as_float(hi); sm.klo[r][c4+1] = __uint_as_float(lo);
            split_tf32(kv.z, hi, lo); sm.khi[r][c4+2] = __uint_as_float(hi); sm.klo[r][c4+2] = __uint_as_float(lo);
            split_tf32(kv.w, hi, lo); sm.khi[r][c4+3] = __uint_as_float(hi); sm.klo[r][c4+3] = __uint_as_float(lo);
            float4 vv = *(const float4*)&sm.raw[slot][1][r][c4];
            sm.vh[c4+0][r] = __float2half(vv.x);
            sm.vh[c4+1][r] = __float2half(vv.y);
            sm.vh[c4+2][r] = __float2half(vv.z);
            sm.vh[c4+3][r] = __float2half(vv.w);
        }
        __syncthreads();

        float s[8][4];
        #pragma unroll
        for (int i = 0; i < 8; i++)
            #pragma unroll
            for (int j = 0; j < 4; j++) s[i][j] = 0.f;

        #pragma unroll
        for (int ks = 0; ks < 8; ks++) {
            int kk = ks * 8;
            uint32_t a0h = __float_as_uint(sm.qhi[r0s][kk + t4]);
            uint32_t a1h = __float_as_uint(sm.qhi[r0s + 8][kk + t4]);
            uint32_t a2h = __float_as_uint(sm.qhi[r0s][kk + t4 + 4]);
            uint32_t a3h = __float_as_uint(sm.qhi[r0s + 8][kk + t4 + 4]);
            uint32_t a0l = __float_as_uint(sm.qlo[r0s][kk + t4]);
            uint32_t a1l = __float_as_uint(sm.qlo[r0s + 8][kk + t4]);
            uint32_t a2l = __float_as_uint(sm.qlo[r0s][kk + t4 + 4]);
            uint32_t a3l = __float_as_uint(sm.qlo[r0s + 8][kk + t4 + 4]);
            #pragma unroll
            for (int nt = 0; nt < 8; nt++) {
                int n = nt * 8 + grp;
                uint32_t b0h = __float_as_uint(sm.khi[n][kk + t4]);
                uint32_t b1h = __float_as_uint(sm.khi[n][kk + t4 + 4]);
                uint32_t b0l = __float_as_uint(sm.klo[n][kk + t4]);
                uint32_t b1l = __float_as_uint(sm.klo[n][kk + t4 + 4]);
                MMA_TF32(s[nt], a0h, a1h, a2h, a3h, b0h, b1h);
                MMA_TF32(s[nt], a0h, a1h, a2h, a3h, b0l, b1l);
                MMA_TF32(s[nt], a0l, a1l, a2l, a3l, b0h, b1h);
            }
        }

        #pragma unroll
        for (int nt = 0; nt < 8; nt++) {
            s[nt][0] = __expf(s[nt][0]);
            s[nt][1] = __expf(s[nt][1]);
            s[nt][2] = __expf(s[nt][2]);
            s[nt][3] = __expf(s[nt][3]);
            l0 += s[nt][0] + s[nt][1];
            l1 += s[nt][2] + s[nt][3];
        }

        #pragma unroll
        for (int kg = 0; kg < 4; kg++) {
            uint32_t a0 = packh2(s[2*kg][0],   s[2*kg][1]);
            uint32_t a1 = packh2(s[2*kg][2],   s[2*kg][3]);
            uint32_t a2 = packh2(s[2*kg+1][0], s[2*kg+1][1]);
            uint32_t a3 = packh2(s[2*kg+1][2], s[2*kg+1][3]);
            #pragma unroll
            for (int dt = 0; dt < 8; dt++) {
                uint32_t b0 = *(const uint32_t*)&sm.vh[dt * 8 + grp][kg * 16 + 2 * t4];
                uint32_t b1 = *(const uint32_t*)&sm.vh[dt * 8 + grp][kg * 16 + 2 * t4 + 8];
                MMA_F16(o[dt], a0, a1, a2, a3, b0, b1);
            }
        }
    }

    l0 += __shfl_xor_sync(0xffffffffu, l0, 1);
    l0 += __shfl_xor_sync(0xffffffffu, l0, 2);
    l1 += __shfl_xor_sync(0xffffffffu, l1, 1);
    l1 += __shfl_xor_sync(0xffffffffu, l1, 2);

    const int rg0 = blockIdx.x * 128 + warp * 16 + grp;
    if (PARTIAL) {
        long long ob = (long long)(blockIdx.y * BHD + bh) * rows * 64;
        #pragma unroll
        for (int dt = 0; dt < 8; dt++) {
            int d = dt * 8 + 2 * t4;
            float2 w0; w0.x = o[dt][0]; w0.y = o[dt][1];
            float2 w1; w1.x = o[dt][2]; w1.y = o[dt][3];
            *(float2*)&Og[ob + (long long)rg0 * 64 + d] = w0;
            *(float2*)&Og[ob + (long long)(rg0 + 8) * 64 + d] = w1;
        }
        if (t4 == 0) {
            Lg[(long long)(blockIdx.y * BHD + bh) * rows + rg0]     = l0;
            Lg[(long long)(blockIdx.y * BHD + bh) * rows + rg0 + 8] = l1;
        }
    } else {
        float i0 = 1.f / l0, i1 = 1.f / l1;
        long long ob = (long long)bh * rows * 64;
        #pragma unroll
        for (int dt = 0; dt < 8; dt++) {
            int d = dt * 8 + 2 * t4;
            float2 w0; w0.x = o[dt][0] * i0; w0.y = o[dt][1] * i0;
            float2 w1; w1.x = o[dt][2] * i1; w1.y = o[dt][3] * i1;
            *(float2*)&Og[ob + (long long)rg0 * 64 + d] = w0;
            *(float2*)&Og[ob + (long long)(rg0 + 8) * 64 + d] = w1;
        }
    }
}

// combine 4 split-KV partials -> a3v row-major splits, scaled S_PINV
__global__ void combine4(const float* __restrict__ P, const float* __restrict__ L,
                         __half* __restrict__ Rh, __half* __restrict__ Rl)
{
    int idx = blockIdx.x * 256 + threadIdx.x;
    int bhr = idx >> 6;
    const int SL = BHD * NL;
    const int SD = BHD * NL * DH;
    float l = L[bhr] + L[SL + bhr] + L[2 * SL + bhr] + L[3 * SL + bhr];
    float val = (P[idx] + P[SD + idx] + P[2 * SD + idx] + P[3 * SD + idx]) / l;
    __half h, lo2;
    split_h(val * S_PINV, h, lo2);
    Rh[idx] = h; Rl[idx] = lo2;
}

// ---------------- split kernel ----------------
__global__ void split_rm(const float* __restrict__ src, __half* __restrict__ hi,
                         __half* __restrict__ lo, float S, long long n)
{
    long long idx = (long long)blockIdx.x * 256 + threadIdx.x;
    if (idx >= n) return;
    __half h, l;
    split_h(src[idx] * S, h, l);
    hi[idx] = h; lo[idx] = l;
}

// ---------------- landmark means ----------------
__global__ void landmark_mean(const float* __restrict__ src, float* __restrict__ dst)
{
    long long idx = (long long)blockIdx.x * 256 + threadIdx.x;
    int d  = idx & 63;
    int mm = (int)((idx >> 6) & 255);
    long long bh = idx >> 14;
    const float* base = src + ((bh * NSEQ) + (long long)mm * LGRP) * DH + d;
    float s = 0.f;
    #pragma unroll
    for (int t = 0; t < LGRP; t++) s += base[(long long)t * DH];
    dst[idx] = s * (1.0f / LGRP);
}

// ---------------- row softmax (a2), emits scaled splits ----------------
__global__ void softmax_rows(float* __restrict__ data, int L,
                             __half* __restrict__ sh, __half* __restrict__ sl)
{
    long long row = blockIdx.x;
    float* p = data + row * (long long)L;
    __shared__ float red[256];
    int t = threadIdx.x;

    float mx = -INFINITY;
    for (int i = t; i < L; i += 256) mx = fmaxf(mx, p[i]);
    red[t] = mx; __syncthreads();
    for (int s = 128; s > 0; s >>= 1) { if (t < s) red[t] = fmaxf(red[t], red[t + s]); __syncthreads(); }
    mx = red[0]; __syncthreads();

    float sm = 0.f;
    for (int i = t; i < L; i += 256) { float e = expf(p[i] - mx); p[i] = e; sm += e; }
    red[t] = sm; __syncthreads();
    for (int s = 128; s > 0; s >>= 1) { if (t < s) red[t] += red[t + s]; __syncthreads(); }
    float inv = 1.f / red[0];
    for (int i = t; i < L; i += 256) {
        float val = p[i] * inv;
        p[i] = val;
        __half h, l;
        split_h(val * S_PINV, h, l);
        sh[row * L + i] = h;
        sl[row * L + i] = l;
    }
}

// ---------------- pinv init scalars ----------------
// Rows of softmaxed a2 sum to exactly 1 => col = max(rowsums) = 1. Only
// the column-sum max is data-dependent.
__global__ void scal_init(float* scal) { scal[0] = 1.0f; scal[1] = 0.f; }

__global__ void colsum_max(const float* __restrict__ a, float* scal)
{
    int j = blockIdx.x, bh = blockIdx.y, t = threadIdx.x;
    __shared__ float red[256];
    red[t] = a[(((long long)bh * NL) + t) * NL + j];
    __syncthreads();
    for (int s = 128; s > 0; s >>= 1) { if (t < s) red[t] += red[t + s]; __syncthreads(); }
    if (t == 0) atomicMax((int*)(scal + 1), __float_as_int(red[0]));
}

// z0 = a2^T / (col*row): row-major splits, scaled
__global__ void zinit(const float* __restrict__ a,
                      __half* __restrict__ zh, __half* __restrict__ zl,
                      const float* __restrict__ scal)
{
    long long idx = (long long)blockIdx.x * 256 + threadIdx.x;
    float inv = S_PINV / (scal[0] * scal[1]);
    int j = (int)(idx & 255);
    int i = (int)((idx >> 8) & 255);
    long long bh = idx >> 16;
    float val = a[(bh << 16) + ((long long)j << 8) + i] * inv;
    __half h, l;
    split_h(val, h, l);
    zh[idx] = h; zl[idx] = l;
}

// ---------------- conv residual + add + transpose -> x2 splits ----------------
__global__ void conv_add_transpose(const float* __restrict__ oh, const float* __restrict__ v,
                                   const float* __restrict__ ker,
                                   __half* __restrict__ x2h, __half* __restrict__ x2l)
{
    long long idx = (long long)blockIdx.x * 256 + threadIdx.x;
    int d  = (int)(idx & 63);
    int h  = (int)((idx >> 6) & 7);
    int nn = (int)((idx >> 9) & 4095);
    int b  = (int)(idx >> 21);
    long long bh = (long long)b * HEADS + h;
    const float* vb = v + (bh * NSEQ) * DH + d;
    float s = 0.f;
    #pragma unroll
    for (int t = 0; t < CONV_TAPS; t++) {
        int pos = nn + t - CONV_PAD;
        if (pos >= 0 && pos < NSEQ) s += vb[(long long)pos * DH] * ker[h * CONV_TAPS + t];
    }
    float val = oh[(bh * NSEQ + nn) * DH + d] + s;
    __half hh, ll;
    split_h(val, hh, ll);
    x2h[idx] = hh; x2l[idx] = ll;
}

// ---------------- host ----------------
template<int BN, int PREC>
static void launch_h3(const __half* Ah, const __half* Al, const __half* Bh, const __half* Bl,
                      int M, int N, int K, long long sA, long long sB, int batch,
                      float scale, float outS,
                      float* Cf, long long sC, const float* bias,
                      __half* R1h, __half* R1l, long long sR1,
                      __half* R2h, __half* R2l, long long sR2, float dv,
                      int qkv, float qscale, float* qp, float* kp, float* vp,
                      cudaStream_t st = 0)
{
    size_t smem = (size_t)((PREC == 3 ? 2 : 1) * 3 * (128 * 40 + 32 * (BN + 8))) * 2;
    cudaFuncSetAttribute(gemm_h3<BN, PREC>, cudaFuncAttributeMaxDynamicSharedMemorySize, (int)smem);
    dim3 grid(N / BN, M / 128, batch);
    gemm_h3<BN, PREC><<<grid, 512, smem, st>>>(Ah, Al, Bh, Bl, M, N, K, sA, sB,
                                               scale, outS, Cf, sC, bias,
                                               R1h, R1l, sR1, R2h, R2l, sR2, dv,
                                               qkv, qscale, qp, kp, vp);
}

extern "C" void kernel_launch(void* const* d_in, const int* in_sizes, int n_in,
                              void* d_out, int out_size)
{
    const float* x      = (const float*)d_in[0];
    const float* w_qkv  = (const float*)d_in[1];
    const float* w_out  = (const float*)d_in[2];
    const float* b_out  = (const float*)d_in[3];
    const float* res_k  = (const float*)d_in[4];
    float* out = (float*)d_out;

    float *q, *k, *v, *ql, *kl, *a2, *za3v, *part, *lpart, *oh, *scal;
    cudaGetSymbolAddress((void**)&q,     g_q);
    cudaGetSymbolAddress((void**)&k,     g_k);
    cudaGetSymbolAddress((void**)&v,     g_v);
    cudaGetSymbolAddress((void**)&ql,    g_ql);
    cudaGetSymbolAddress((void**)&kl,    g_kl);
    cudaGetSymbolAddress((void**)&a2,    g_a2);
    cudaGetSymbolAddress((void**)&za3v,  g_za3v);
    cudaGetSymbolAddress((void**)&part,  g_part);
    cudaGetSymbolAddress((void**)&lpart, g_lpart);
    cudaGetSymbolAddress((void**)&oh,    g_oh);
    cudaGetSymbolAddress((void**)&scal,  g_scal);

    __half *xh, *xl, *wqh, *wql, *woh, *wol, *x2h, *x2l, *a2h, *a2l;
    __half *zAh, *zAl, *zBh, *zBl, *xzh, *xzl, *T1h, *T1l, *T2h, *T2l, *a3vh, *a3vl;
    cudaGetSymbolAddress((void**)&xh,   g_xh);
    cudaGetSymbolAddress((void**)&xl,   g_xl);
    cudaGetSymbolAddress((void**)&wqh,  g_wqh);
    cudaGetSymbolAddress((void**)&wql,  g_wql);
    cudaGetSymbolAddress((void**)&woh,  g_woh);
    cudaGetSymbolAddress((void**)&wol,  g_wol);
    cudaGetSymbolAddress((void**)&x2h,  g_x2h);
    cudaGetSymbolAddress((void**)&x2l,  g_x2l);
    cudaGetSymbolAddress((void**)&a2h,  g_a2h);
    cudaGetSymbolAddress((void**)&a2l,  g_a2l);
    cudaGetSymbolAddress((void**)&zAh,  g_zAh);
    cudaGetSymbolAddress((void**)&zAl,  g_zAl);
    cudaGetSymbolAddress((void**)&zBh,  g_zBh);
    cudaGetSymbolAddress((void**)&zBl,  g_zBl);
    cudaGetSymbolAddress((void**)&xzh,  g_xzh);
    cudaGetSymbolAddress((void**)&xzl,  g_xzl);
    cudaGetSymbolAddress((void**)&T1h,  g_T1h);
    cudaGetSymbolAddress((void**)&T1l,  g_T1l);
    cudaGetSymbolAddress((void**)&T2h,  g_T2h);
    cudaGetSymbolAddress((void**)&T2l,  g_T2l);
    cudaGetSymbolAddress((void**)&a3vh, g_a3vh);
    cudaGetSymbolAddress((void**)&a3vl, g_a3vl);

    cudaFuncSetAttribute(flash_pv<0>, cudaFuncAttributeMaxDynamicSharedMemorySize, (int)sizeof(FlashSmem));
    cudaFuncSetAttribute(flash_pv<1>, cudaFuncAttributeMaxDynamicSharedMemorySize, (int)sizeof(FlashSmem));

    const size_t pp_smem = (size_t)(2 * 3 * (128 * 40 + 32 * 136)) * 2;
    cudaFuncSetAttribute(pinv_persist, cudaFuncAttributeMaxDynamicSharedMemorySize, (int)pp_smem);

    const long long sb = (long long)NL * NL;
    const long long svd = (long long)NL * DH;

    cudaStream_t s2;
    cudaStreamCreateWithFlags(&s2, cudaStreamNonBlocking);
    cudaEvent_t evFork, evJoin;
    cudaEventCreateWithFlags(&evFork, cudaEventDisableTiming);
    cudaEventCreateWithFlags(&evJoin, cudaEventDisableTiming);

    // 0) operand splits
    {
        long long n = (long long)BATCH * NSEQ * DIM;
        split_rm<<<(unsigned)((n + 255) / 256), 256>>>(x, xh, xl, 1.0f, n);
        long long nw = (long long)DIM * 3 * DIM;
        split_rm<<<(unsigned)((nw + 255) / 256), 256>>>(w_qkv, wqh, wql, S_W, nw);
        long long nw2 = (long long)DIM * DIM;
        split_rm<<<(unsigned)((nw2 + 255) / 256), 256>>>(w_out, woh, wol, S_W, nw2);
    }

    // 1) qkv projection (fp16x3, 512-thread GEMM) + scatter
    launch_h3<128, 3>(xh, xl, wqh, wql, BATCH * NSEQ, 3 * DIM, DIM, 0, 0, 1,
                      1.0f / S_W, 1.0f,
                      nullptr, 0, nullptr, nullptr, nullptr, 0,
                      nullptr, nullptr, 0, 0.f, 1, 0.125f, q, k, v);

    // 2) landmarks
    {
        long long n = (long long)BHD * NL * DH;
        landmark_mean<<<(unsigned)(n / 256), 256>>>(q, ql);
        landmark_mean<<<(unsigned)(n / 256), 256>>>(k, kl);
    }

    // ---- fork: flash1 (a3v) on s2, concurrent with a2/softmax/pinv ----
    cudaEventRecord(evFork, 0);
    cudaStreamWaitEvent(s2, evFork, 0);
    {
        dim3 grid(NL / 128, 4, BHD);
        flash_pv<1><<<grid, 256, sizeof(FlashSmem), s2>>>(ql, k, v, part, lpart, NL, NSEQ, NSEQ / 4);
        combine4<<<(BHD * NL * DH) / 256, 256, 0, s2>>>(part, lpart, a3vh, a3vl);
    }
    cudaEventRecord(evJoin, s2);

    // 3) a2 = ql @ kl^T (tf32x3, fp32) + softmax (emits splits)
    {
        size_t smem = (size_t)(3 * 128 * 20 + 3 * 128 * 20) * 4;
        cudaFuncSetAttribute(gemm_tf32<128, 1>, cudaFuncAttributeMaxDynamicSharedMemorySize, (int)smem);
        dim3 grid(NL / 128, NL / 128, BHD);
        gemm_tf32<128, 1><<<grid, 256, smem>>>(ql, kl, a2, NL, NL, DH, svd, svd, sb);
    }
    softmax_rows<<<BHD * NL, 256>>>(a2, NL, a2h, a2l);

    // 4) pinv init (col = 1 exactly: softmax rows sum to 1)
    scal_init<<<1, 1>>>(scal);
    {
        dim3 g(NL, BHD);
        colsum_max<<<g, 256>>>(a2, scal);
    }
    zinit<<<(unsigned)((long long)BHD * NL * NL / 256), 256>>>(a2, zAh, zAl, scal);

    // 5) Newton iterations — persistent kernel with PER-Z 4-block barriers.
    //    5 iterations: 4 cheap (1-pass fp16) + 1 full (3-pass).
    __half *zch = zAh, *zcl = zAl, *znh = zBh, *znl = zBl;
    const float sa2 = 1.0f / (S_PINV * S_PINV);
    {
        PinvPlan plan;
        int idx = 0;
        const int NITER = 5;
        for (int it = 0; it < NITER; it++) {
            int prec = (it < NITER - 1) ? 1 : 3;
            plan.s[idx++] = { a2h, a2l, zch, zcl, xzh, xzl, T1h, T1l, 7.0f, sa2, prec };
            plan.s[idx++] = { xzh, xzl, T1h, T1l, nullptr, nullptr, T2h, T2l, 15.0f, sa2, prec };
            plan.s[idx++] = { xzh, xzl, T2h, T2l, nullptr, nullptr, T1h, T1l, 13.0f, sa2, prec };
            plan.s[idx++] = { zch, zcl, T1h, T1l, znh, znl, nullptr, nullptr, 0.f, 0.25f * sa2, prec };
            __half* t;
            t = zch; zch = znh; znh = t;
            t = zcl; zcl = znl; znl = t;
        }
        plan.n = idx;
        bar_reset<<<1, 32>>>();
        dim3 grid(2, 2, BHD);
        pinv_persist<<<grid, 512, pp_smem>>>(plan);
    }

    // ---- join: za3v needs a3v from s2 ----
    cudaStreamWaitEvent(0, evJoin, 0);

    // 7) za3v = z @ a3v (fp16x3) -> fp32
    launch_h3<64, 3>(zch, zcl, a3vh, a3vl, NL, DH, NL, sb, svd, BHD,
                     sa2, 1.0f, za3v, svd, nullptr,
                     nullptr, nullptr, 0, nullptr, nullptr, 0, 0.f,
                     0, 0.f, nullptr, nullptr, nullptr);

    // 8) oh = softmax(q @ kl^T) @ za3v — flash
    {
        dim3 grid(NSEQ / 128, 1, BHD);
        flash_pv<0><<<grid, 256, sizeof(FlashSmem)>>>(q, kl, za3v, oh, nullptr, NSEQ, NL, NL);
    }

    // 9) conv residual + add + transpose -> x2 splits
    conv_add_transpose<<<(unsigned)((long long)BATCH * NSEQ * HEADS * DH / 256), 256>>>(oh, v, res_k, x2h, x2l);

    // 10) out = x2 @ w_out + b_out (fp16x3)
    launch_h3<128, 3>(x2h, x2l, woh, wol, BATCH * NSEQ, DIM, DIM, 0, 0, 1,
                      1.0f / S_W, 1.0f,
                      out, 0, b_out, nullptr, nullptr, 0,
                      nullptr, nullptr, 0, 0.f, 0, 0.f, nullptr, nullptr, nullptr);

    cudaEventDestroy(evFork);
    cudaEventDestroy(evJoin);
    cudaStreamDestroy(s2);
}

// round 13
// speedup vs baseline: 1.0567x; 1.0455x over previous
#include <cuda_runtime.h>
#include <cuda_fp16.h>
#include <math.h>
#include <stdint.h>

// ---------------- problem constants ----------------
#define BATCH 4
#define HEADS 8
#define NSEQ  4096
#define DH    64
#define DIM   512
#define NL    256
#define LGRP  16
#define BHD   (BATCH*HEADS)
#define CONV_TAPS 33
#define CONV_PAD 16

#define S_PINV 64.0f
#define S_W    256.0f

// ---------------- scratch (fp32) ----------------
__device__ float g_q [(size_t)BHD*NSEQ*DH];
__device__ float g_k [(size_t)BHD*NSEQ*DH];
__device__ float g_v [(size_t)BHD*NSEQ*DH];
__device__ float g_ql[(size_t)BHD*NL*DH];
__device__ float g_kl[(size_t)BHD*NL*DH];
__device__ float g_a2[(size_t)BHD*NL*NL];
__device__ float g_za3v[(size_t)BHD*NL*DH];
__device__ float g_part[(size_t)4*BHD*NL*DH];
__device__ float g_lpart[(size_t)4*BHD*NL];
__device__ float g_oh [(size_t)BHD*NSEQ*DH];
__device__ float g_cv [(size_t)BATCH*NSEQ*HEADS*DH];
__device__ float g_scal[2];

// ---------------- scratch (half splits; all row-major) ----------------
__device__ __half g_xh [(size_t)BATCH*NSEQ*DIM];
__device__ __half g_xl [(size_t)BATCH*NSEQ*DIM];
__device__ __half g_wqh[(size_t)DIM*3*DIM];
__device__ __half g_wql[(size_t)DIM*3*DIM];
__device__ __half g_woh[(size_t)DIM*DIM];
__device__ __half g_wol[(size_t)DIM*DIM];
__device__ __half g_x2h[(size_t)BATCH*NSEQ*DIM];
__device__ __half g_x2l[(size_t)BATCH*NSEQ*DIM];
__device__ __half g_a2h[(size_t)BHD*NL*NL];
__device__ __half g_a2l[(size_t)BHD*NL*NL];
__device__ __half g_zAh[(size_t)BHD*NL*NL];
__device__ __half g_zAl[(size_t)BHD*NL*NL];
__device__ __half g_zBh[(size_t)BHD*NL*NL];
__device__ __half g_zBl[(size_t)BHD*NL*NL];
__device__ __half g_xzh[(size_t)BHD*NL*NL];
__device__ __half g_xzl[(size_t)BHD*NL*NL];
__device__ __half g_T1h[(size_t)BHD*NL*NL];
__device__ __half g_T1l[(size_t)BHD*NL*NL];
__device__ __half g_T2h[(size_t)BHD*NL*NL];
__device__ __half g_T2l[(size_t)BHD*NL*NL];
__device__ __half g_a3vh[(size_t)BHD*NL*DH];
__device__ __half g_a3vl[(size_t)BHD*NL*DH];

// ---------------- helpers ----------------
__device__ __forceinline__ void split_tf32(float v, uint32_t &hi, uint32_t &lo) {
    asm("cvt.rna.tf32.f32 %0, %1;" : "=r"(hi) : "f"(v));
    float r = v - __uint_as_float(hi);
    asm("cvt.rna.tf32.f32 %0, %1;" : "=r"(lo) : "f"(r));
}

__device__ __forceinline__ void split_h(float v, __half &hi, __half &lo) {
    hi = __float2half_rn(v);
    lo = __float2half_rn(v - __half2float(hi));
}

#define MMA_TF32(D, A0,A1,A2,A3, B0,B1) \
    asm volatile("mma.sync.aligned.m16n8k8.row.col.f32.tf32.tf32.f32 " \
                 "{%0,%1,%2,%3},{%4,%5,%6,%7},{%8,%9},{%0,%1,%2,%3};" \
                 : "+f"((D)[0]), "+f"((D)[1]), "+f"((D)[2]), "+f"((D)[3]) \
                 : "r"(A0), "r"(A1), "r"(A2), "r"(A3), "r"(B0), "r"(B1))

#define MMA_F16(D, a0,a1,a2,a3, b0,b1) \
    asm volatile("mma.sync.aligned.m16n8k16.row.col.f32.f16.f16.f32 " \
                 "{%0,%1,%2,%3},{%4,%5,%6,%7},{%8,%9},{%0,%1,%2,%3};" \
                 : "+f"((D)[0]), "+f"((D)[1]), "+f"((D)[2]), "+f"((D)[3]) \
                 : "r"(a0), "r"(a1), "r"(a2), "r"(a3), "r"(b0), "r"(b1))

__device__ __forceinline__ void cp16(void* smem, const void* g) {
    uint32_t sa = (uint32_t)__cvta_generic_to_shared(smem);
    asm volatile("cp.async.ca.shared.global [%0], [%1], 16;" :: "r"(sa), "l"(g));
}
#define CP_COMMIT asm volatile("cp.async.commit_group;")
#define CP_WAIT0  asm volatile("cp.async.wait_group 0;")
#define CP_WAIT1  asm volatile("cp.async.wait_group 1;")

__device__ __forceinline__ uint32_t packh2(float a, float b) {
    __half2 h = __floats2half2_rn(a, b);
    return *reinterpret_cast<uint32_t*>(&h);
}

__device__ __forceinline__ void ldsm4(uint32_t* r, const __half* p) {
    uint32_t a = (uint32_t)__cvta_generic_to_shared(p);
    asm volatile("ldmatrix.sync.aligned.m8n8.x4.shared.b16 {%0,%1,%2,%3}, [%4];"
                 : "=r"(r[0]), "=r"(r[1]), "=r"(r[2]), "=r"(r[3]) : "r"(a));
}
__device__ __forceinline__ void ldsm4t(uint32_t* r, const __half* p) {
    uint32_t a = (uint32_t)__cvta_generic_to_shared(p);
    asm volatile("ldmatrix.sync.aligned.m8n8.x4.trans.shared.b16 {%0,%1,%2,%3}, [%4];"
                 : "=r"(r[0]), "=r"(r[1]), "=r"(r[2]), "=r"(r[3]) : "r"(a));
}

// ================= fp16 batched GEMM — 512 threads, warp tile 32x32 =====
// PREC=3: 3-product error-compensated (hh+hl+lh). PREC=1: plain hi*hi.
// Block tile 128 x BN, 16 warps (4 m-groups x 4 n-groups).
template<int BN, int PREC>
__global__ void __launch_bounds__(512, 1)
gemm_h3(const __half* __restrict__ Ahg, const __half* __restrict__ Alg,
        const __half* __restrict__ Bhg, const __half* __restrict__ Blg,
        int M, int N, int K, long long sA, long long sB,
        float scale, float outS,
        float* __restrict__ Cf, long long sC, const float* __restrict__ bias,
        __half* __restrict__ R1h, __half* __restrict__ R1l, long long sR1,
        __half* __restrict__ R2h, __half* __restrict__ R2l, long long sR2, float dv,
        int qkv, float qscale,
        float* __restrict__ qp, float* __restrict__ kp, float* __restrict__ vp)
{
    constexpr int NT  = BN / 32;
    constexpr int ALD = 40;
    constexpr int BLD = BN + 8;
    constexpr int ASZ = 128 * ALD;
    constexpr int BSZ = 32 * BLD;

    const int zb = blockIdx.z;
    const __half* Ah_g = Ahg + (long long)zb * sA;
    const __half* Al_g = Alg + (long long)zb * sA;
    const __half* Bh_g = Bhg + (long long)zb * sB;
    const __half* Bl_g = Blg + (long long)zb * sB;
    if (Cf)  Cf  += (long long)zb * sC;
    if (R1h) { R1h += (long long)zb * sR1; R1l += (long long)zb * sR1; }
    if (R2h) { R2h += (long long)zb * sR2; R2l += (long long)zb * sR2; }

    extern __shared__ __half hsm[];
    __half* Ash = hsm;
    __half* Asl = Ash + 3 * ASZ;
    __half* Bsh = (PREC == 3) ? (Asl + 3 * ASZ) : (Ash + 3 * ASZ);
    __half* Bsl = Bsh + 3 * BSZ;

    const int brow = blockIdx.y * 128;
    const int bcol = blockIdx.x * BN;

    const int tid  = threadIdx.x;
    const int warp = tid >> 5;
    const int lane = tid & 31;
    const int wm   = warp & 3;
    const int wn   = warp >> 2;
    const int grp  = lane >> 2;
    const int t4   = lane & 3;
    const int r8   = lane & 7;
    const int quad = lane >> 3;

    const int nk = K / 32;

    auto load_stage = [&](int s, int kt) {
        int k0 = kt * 32;
        {
            int row = tid >> 2, seg = (tid & 3) * 8;
            cp16(&Ash[(s * 128 + row) * ALD + seg], &Ah_g[(long long)(brow + row) * K + k0 + seg]);
            if (PREC == 3)
                cp16(&Asl[(s * 128 + row) * ALD + seg], &Al_g[(long long)(brow + row) * K + k0 + seg]);
        }
        if (tid < BN * 4) {
            int row = tid / (BN / 8), seg = (tid % (BN / 8)) * 8;
            cp16(&Bsh[(s * 32 + row) * BLD + seg], &Bh_g[(long long)(k0 + row) * N + bcol + seg]);
            if (PREC == 3)
                cp16(&Bsl[(s * 32 + row) * BLD + seg], &Bl_g[(long long)(k0 + row) * N + bcol + seg]);
        }
    };

    float acc[2][NT][4];
    #pragma unroll
    for (int i = 0; i < 2; i++)
        #pragma unroll
        for (int j = 0; j < NT; j++)
            #pragma unroll
            for (int l = 0; l < 4; l++) acc[i][j][l] = 0.f;

    load_stage(0, 0); CP_COMMIT;
    load_stage(1, 1); CP_COMMIT;

    for (int kt = 0; kt < nk; kt++) {
        CP_WAIT1;
        __syncthreads();
        int buf = kt % 3;
        if (kt + 2 < nk) load_stage((kt + 2) % 3, kt + 2);
        CP_COMMIT;

        #pragma unroll
        for (int ss = 0; ss < 2; ss++) {
            int kb = ss * 16;
            uint32_t ah[2][4], al[2][4];
            #pragma unroll
            for (int mt = 0; mt < 2; mt++) {
                int m0 = wm * 32 + mt * 16;
                int off = (buf * 128 + m0 + r8 + (quad & 1) * 8) * ALD + kb + (quad >> 1) * 8;
                ldsm4(ah[mt], Ash + off);
                if (PREC == 3) ldsm4(al[mt], Asl + off);
            }
            uint32_t bh[NT][2], bl[NT][2];
            #pragma unroll
            for (int np = 0; np < NT / 2; np++) {
                int n0 = wn * (BN / 4) + np * 16;
                int off = (buf * 32 + kb + (quad & 1) * 8 + r8) * BLD + n0 + (quad >> 1) * 8;
                uint32_t tb[4];
                ldsm4t(tb, Bsh + off);
                bh[np * 2][0] = tb[0]; bh[np * 2][1] = tb[1];
                bh[np * 2 + 1][0] = tb[2]; bh[np * 2 + 1][1] = tb[3];
                if (PREC == 3) {
                    ldsm4t(tb, Bsl + off);
                    bl[np * 2][0] = tb[0]; bl[np * 2][1] = tb[1];
                    bl[np * 2 + 1][0] = tb[2]; bl[np * 2 + 1][1] = tb[3];
                }
            }
            #pragma unroll
            for (int mt = 0; mt < 2; mt++)
                #pragma unroll
                for (int nt = 0; nt < NT; nt++) {
                    MMA_F16(acc[mt][nt], ah[mt][0], ah[mt][1], ah[mt][2], ah[mt][3], bh[nt][0], bh[nt][1]);
                    if (PREC == 3) {
                        MMA_F16(acc[mt][nt], ah[mt][0], ah[mt][1], ah[mt][2], ah[mt][3], bl[nt][0], bl[nt][1]);
                        MMA_F16(acc[mt][nt], al[mt][0], al[mt][1], al[mt][2], al[mt][3], bh[nt][0], bh[nt][1]);
                    }
                }
        }
    }

    #pragma unroll
    for (int mt = 0; mt < 2; mt++) {
        int r0 = brow + wm * 32 + mt * 16 + grp;
        #pragma unroll
        for (int nt = 0; nt < NT; nt++) {
            int c = bcol + wn * (BN / 4) + nt * 8 + t4 * 2;
            #pragma unroll
            for (int half_i = 0; half_i < 2; half_i++) {
                int r = r0 + half_i * 8;
                float v0 = acc[mt][nt][half_i * 2 + 0] * scale;
                float v1 = acc[mt][nt][half_i * 2 + 1] * scale;
                if (qkv) {
                    int bidx = r >> 12, nn = r & 4095;
                    int part = c / DIM, rem = c % DIM;
                    int hh = rem >> 6, dd = rem & 63;
                    long long dst = ((((long long)bidx * HEADS + hh) * NSEQ) + nn) * DH + dd;
                    float2 val;
                    if (part == 0) { val.x = v0 * qscale; val.y = v1 * qscale; *(float2*)&qp[dst] = val; }
                    else if (part == 1) { val.x = v0; val.y = v1; *(float2*)&kp[dst] = val; }
                    else { val.x = v0; val.y = v1; *(float2*)&vp[dst] = val; }
                } else {
                    if (Cf) {
                        float b0 = bias ? bias[c] : 0.f;
                        float b1 = bias ? bias[c + 1] : 0.f;
                        float2 val; val.x = v0 + b0; val.y = v1 + b1;
                        *(float2*)&Cf[(long long)r * N + c] = val;
                    }
                    if (R1h) {
                        __half h0, l0, h1, l1;
                        split_h(v0 * outS, h0, l0);
                        split_h(v1 * outS, h1, l1);
                        __half2 hp; hp.x = h0; hp.y = h1;
                        __half2 lp; lp.x = l0; lp.y = l1;
                        *(__half2*)&R1h[(long long)r * N + c] = hp;
                        *(__half2*)&R1l[(long long)r * N + c] = lp;
                    }
                    if (R2h) {
                        float tv0 = (((r == c) ? dv : 0.f) - v0) * outS;
                        float tv1 = (((r == c + 1) ? dv : 0.f) - v1) * outS;
                        __half h0, l0, h1, l1;
                        split_h(tv0, h0, l0);
                        split_h(tv1, h1, l1);
                        __half2 hp; hp.x = h0; hp.y = h1;
                        __half2 lp; lp.x = l0; lp.y = l1;
                        *(__half2*)&R2h[(long long)r * N + c] = hp;
                        *(__half2*)&R2l[(long long)r * N + c] = lp;
                    }
                }
            }
        }
    }
}

// ================= 3xTF32 GEMM (a2 = ql @ kl^T only) =================
template<int BN, int TB>
__global__ void __launch_bounds__(256, 1)
gemm_tf32(const float* __restrict__ Ag, const float* __restrict__ Bg,
          float* __restrict__ Cg, int M, int N, int K,
          long long sA, long long sB, long long sC)
{
    constexpr int NT   = BN / 32;
    constexpr int BSZ  = TB ? BN * 20 : 16 * (BN + 8);
    constexpr int ASZ  = 128 * 20;

    extern __shared__ char dynsm[];
    float* As = (float*)dynsm;
    float* Bs = As + 3 * ASZ;

    const float* A = Ag + (long long)blockIdx.z * sA;
    const float* B = Bg + (long long)blockIdx.z * sB;
    float*       C = Cg + (long long)blockIdx.z * sC;

    const int brow = blockIdx.y * 128;
    const int bcol = blockIdx.x * BN;

    const int tid  = threadIdx.x;
    const int warp = tid >> 5;
    const int lane = tid & 31;
    const int wm   = warp & 1;
    const int wn   = warp >> 1;
    const int grp  = lane >> 2;
    const int t4   = lane & 3;

    const int a_row0 = tid >> 2;
    const int a_k    = (tid & 3) * 4;
    const int nk = K / 16;

    auto load_stage = [&](int s, int kt) {
        int k0 = kt * 16;
        cp16(&As[s * ASZ + a_row0 * 20 + a_k],        &A[(long long)(brow + a_row0) * K + k0 + a_k]);
        cp16(&As[s * ASZ + (a_row0 + 64) * 20 + a_k], &A[(long long)(brow + a_row0 + 64) * K + k0 + a_k]);
        #pragma unroll
        for (int j = 0; j < BN / 64; j++) {
            int i = tid + 256 * j;
            int n  = i >> 2;
            int kq = (i & 3) * 4;
            cp16(&Bs[s * BSZ + n * 20 + kq], &B[(long long)(bcol + n) * K + k0 + kq]);
        }
    };

    float acc[4][NT][4];
    #pragma unroll
    for (int i = 0; i < 4; i++)
        #pragma unroll
        for (int j = 0; j < NT; j++)
            #pragma unroll
            for (int l = 0; l < 4; l++) acc[i][j][l] = 0.f;

    load_stage(0, 0); CP_COMMIT;
    load_stage(1, 1); CP_COMMIT;

    for (int kt = 0; kt < nk; kt++) {
        CP_WAIT1;
        __syncthreads();
        int buf = kt % 3;
        if (kt + 2 < nk) load_stage((kt + 2) % 3, kt + 2);
        CP_COMMIT;

        #pragma unroll
        for (int ss = 0; ss < 2; ss++) {
            int kb = ss * 8;
            uint32_t ah[4][4], al[4][4];
            #pragma unroll
            for (int mt = 0; mt < 4; mt++) {
                int m = wm * 64 + mt * 16 + grp;
                float f0 = As[buf * ASZ + m * 20 + kb + t4];
                float f1 = As[buf * ASZ + (m + 8) * 20 + kb + t4];
                float f2 = As[buf * ASZ + m * 20 + kb + t4 + 4];
                float f3 = As[buf * ASZ + (m + 8) * 20 + kb + t4 + 4];
                split_tf32(f0, ah[mt][0], al[mt][0]);
                split_tf32(f1, ah[mt][1], al[mt][1]);
                split_tf32(f2, ah[mt][2], al[mt][2]);
                split_tf32(f3, ah[mt][3], al[mt][3]);
            }
            uint32_t bh[NT][2], bl[NT][2];
            #pragma unroll
            for (int nt = 0; nt < NT; nt++) {
                int n = wn * (BN / 4) + nt * 8 + grp;
                float b0 = Bs[buf * BSZ + n * 20 + kb + t4];
                float b1 = Bs[buf * BSZ + n * 20 + kb + t4 + 4];
                split_tf32(b0, bh[nt][0], bl[nt][0]);
                split_tf32(b1, bh[nt][1], bl[nt][1]);
            }
            #pragma unroll
            for (int mt = 0; mt < 4; mt++)
                #pragma unroll
                for (int nt = 0; nt < NT; nt++) {
                    MMA_TF32(acc[mt][nt], ah[mt][0], ah[mt][1], ah[mt][2], ah[mt][3], bh[nt][0], bh[nt][1]);
                    MMA_TF32(acc[mt][nt], ah[mt][0], ah[mt][1], ah[mt][2], ah[mt][3], bl[nt][0], bl[nt][1]);
                    MMA_TF32(acc[mt][nt], al[mt][0], al[mt][1], al[mt][2], al[mt][3], bh[nt][0], bh[nt][1]);
                }
        }
    }

    #pragma unroll
    for (int mt = 0; mt < 4; mt++) {
        int r0 = brow + wm * 64 + mt * 16 + grp;
        #pragma unroll
        for (int nt = 0; nt < NT; nt++) {
            int c = bcol + wn * (BN / 4) + nt * 8 + t4 * 2;
            #pragma unroll
            for (int half_i = 0; half_i < 2; half_i++) {
                int r = r0 + half_i * 8;
                float2 val;
                val.x = acc[mt][nt][half_i * 2 + 0];
                val.y = acc[mt][nt][half_i * 2 + 1];
                *(float2*)&C[(long long)r * N + c] = val;
            }
        }
    }
}

// ---------------- fused flash kernel ----------------
struct FlashSmem {
    float  qhi[128][68];
    float  qlo[128][68];
    float  raw[2][2][64][64];
    float  khi[64][68];
    float  klo[64][68];
    __half vh[64][72];
};

template<int PARTIAL>
__global__ void __launch_bounds__(256, 1)
flash_pv(const float* __restrict__ Qg, const float* __restrict__ Kg,
         const float* __restrict__ Vg, float* __restrict__ Og,
         float* __restrict__ Lg, int rows, int keys, int kvchunk)
{
    extern __shared__ char dynsm[];
    FlashSmem& sm = *reinterpret_cast<FlashSmem*>(dynsm);

    const int tid  = threadIdx.x;
    const int warp = tid >> 5;
    const int lane = tid & 31;
    const int grp  = lane >> 2;
    const int t4   = lane & 3;
    const int bh   = blockIdx.z;

    const long long qbase = ((long long)bh * rows + blockIdx.x * 128) * 64;
    const long long kbase = ((long long)bh * keys + (long long)blockIdx.y * kvchunk) * 64;

    #pragma unroll
    for (int j = 0; j < 8; j++) {
        int e = tid + 256 * j;
        int r = e >> 4, c4 = (e & 15) * 4;
        float4 qv = *(const float4*)&Qg[qbase + (long long)r * 64 + c4];
        uint32_t hi, lo;
        split_tf32(qv.x, hi, lo); sm.qhi[r][c4+0] = __uint_as_float(hi); sm.qlo[r][c4+0] = __uint_as_float(lo);
        split_tf32(qv.y, hi, lo); sm.qhi[r][c4+1] = __uint_as_float(hi); sm.qlo[r][c4+1] = __uint_as_float(lo);
        split_tf32(qv.z, hi, lo); sm.qhi[r][c4+2] = __uint_as_float(hi); sm.qlo[r][c4+2] = __uint_as_float(lo);
        split_tf32(qv.w, hi, lo); sm.qhi[r][c4+3] = __uint_as_float(hi); sm.qlo[r][c4+3] = __uint_as_float(lo);
    }

    auto stage = [&](int slot, int sub) {
        long long base = kbase + (long long)sub * 64 * 64;
        #pragma unroll
        for (int j = 0; j < 4; j++) {
            int e = tid + 256 * j;
            int r = e >> 4, c4 = (e & 15) * 4;
            cp16(&sm.raw[slot][0][r][c4], &Kg[base + (long long)r * 64 + c4]);
        }
        #pragma unroll
        for (int j = 0; j < 4; j++) {
            int e = tid + 256 * j;
            int r = e >> 4, c4 = (e & 15) * 4;
            cp16(&sm.raw[slot][1][r][c4], &Vg[base + (long long)r * 64 + c4]);
        }
    };

    const int nsub = kvchunk / 64;
    stage(0, 0); CP_COMMIT;

    float o[8][4];
    #pragma unroll
    for (int i = 0; i < 8; i++)
        #pragma unroll
        for (int j = 0; j < 4; j++) o[i][j] = 0.f;
    float l0 = 0.f, l1 = 0.f;
    const int r0s = warp * 16 + grp;

    for (int sub = 0; sub < nsub; sub++) {
        CP_WAIT0;
        __syncthreads();
        int slot = sub & 1;
        if (sub + 1 < nsub) stage(slot ^ 1, sub + 1);
        CP_COMMIT;

        #pragma unroll
        for (int j = 0; j < 4; j++) {
            int e = tid + 256 * j;
            int r = e >> 4, c4 = (e & 15) * 4;
            float4 kv = *(const float4*)&sm.raw[slot][0][r][c4];
            uint32_t hi, lo;
            split_tf32(kv.x, hi, lo); sm.khi[r][c4+0] = __uint_as_float(hi); sm.klo[r][c4+0] = __uint_as_float(lo);
            split_tf32(kv.y, hi, lo); sm.khi[r][c4+1] = __uint_as_float(hi); sm.klo[r][c4+1] = __uint_as_float(lo);
            split_tf32(kv.z, hi, lo); sm.khi[r][c4+2] = __uint_as_float(hi); sm.klo[r][c4+2] = __uint_as_float(lo);
            split_tf32(kv.w, hi, lo); sm.khi[r][c4+3] = __uint_as_float(hi); sm.klo[r][c4+3] = __uint_as_float(lo);
            float4 vv = *(const float4*)&sm.raw[slot][1][r][c4];
            sm.vh[c4+0][r] = __float2half(vv.x);
            sm.vh[c4+1][r] = __float2half(vv.y);
            sm.vh[c4+2][r] = __float2half(vv.z);
            sm.vh[c4+3][r] = __float2half(vv.w);
        }
        __syncthreads();

        float s[8][4];
        #pragma unroll
        for (int i = 0; i < 8; i++)
            #pragma unroll
            for (int j = 0; j < 4; j++) s[i][j] = 0.f;

        #pragma unroll
        for (int ks = 0; ks < 8; ks++) {
            int kk = ks * 8;
            uint32_t a0h = __float_as_uint(sm.qhi[r0s][kk + t4]);
            uint32_t a1h = __float_as_uint(sm.qhi[r0s + 8][kk + t4]);
            uint32_t a2h = __float_as_uint(sm.qhi[r0s][kk + t4 + 4]);
            uint32_t a3h = __float_as_uint(sm.qhi[r0s + 8][kk + t4 + 4]);
            uint32_t a0l = __float_as_uint(sm.qlo[r0s][kk + t4]);
            uint32_t a1l = __float_as_uint(sm.qlo[r0s + 8][kk + t4]);
            uint32_t a2l = __float_as_uint(sm.qlo[r0s][kk + t4 + 4]);
            uint32_t a3l = __float_as_uint(sm.qlo[r0s + 8][kk + t4 + 4]);
            #pragma unroll
            for (int nt = 0; nt < 8; nt++) {
                int n = nt * 8 + grp;
                uint32_t b0h = __float_as_uint(sm.khi[n][kk + t4]);
                uint32_t b1h = __float_as_uint(sm.khi[n][kk + t4 + 4]);
                uint32_t b0l = __float_as_uint(sm.klo[n][kk + t4]);
                uint32_t b1l = __float_as_uint(sm.klo[n][kk + t4 + 4]);
                MMA_TF32(s[nt], a0h, a1h, a2h, a3h, b0h, b1h);
                MMA_TF32(s[nt], a0h, a1h, a2h, a3h, b0l, b1l);
                MMA_TF32(s[nt], a0l, a1l, a2l, a3l, b0h, b1h);
            }
        }

        #pragma unroll
        for (int nt = 0; nt < 8; nt++) {
            s[nt][0] = __expf(s[nt][0]);
            s[nt][1] = __expf(s[nt][1]);
            s[nt][2] = __expf(s[nt][2]);
            s[nt][3] = __expf(s[nt][3]);
            l0 += s[nt][0] + s[nt][1];
            l1 += s[nt][2] + s[nt][3];
        }

        #pragma unroll
        for (int kg = 0; kg < 4; kg++) {
            uint32_t a0 = packh2(s[2*kg][0],   s[2*kg][1]);
            uint32_t a1 = packh2(s[2*kg][2],   s[2*kg][3]);
            uint32_t a2 = packh2(s[2*kg+1][0], s[2*kg+1][1]);
            uint32_t a3 = packh2(s[2*kg+1][2], s[2*kg+1][3]);
            #pragma unroll
            for (int dt = 0; dt < 8; dt++) {
                uint32_t b0 = *(const uint32_t*)&sm.vh[dt * 8 + grp][kg * 16 + 2 * t4];
                uint32_t b1 = *(const uint32_t*)&sm.vh[dt * 8 + grp][kg * 16 + 2 * t4 + 8];
                MMA_F16(o[dt], a0, a1, a2, a3, b0, b1);
            }
        }
    }

    l0 += __shfl_xor_sync(0xffffffffu, l0, 1);
    l0 += __shfl_xor_sync(0xffffffffu, l0, 2);
    l1 += __shfl_xor_sync(0xffffffffu, l1, 1);
    l1 += __shfl_xor_sync(0xffffffffu, l1, 2);

    const int rg0 = blockIdx.x * 128 + warp * 16 + grp;
    if (PARTIAL) {
        long long ob = (long long)(blockIdx.y * BHD + bh) * rows * 64;
        #pragma unroll
        for (int dt = 0; dt < 8; dt++) {
            int d = dt * 8 + 2 * t4;
            float2 w0; w0.x = o[dt][0]; w0.y = o[dt][1];
            float2 w1; w1.x = o[dt][2]; w1.y = o[dt][3];
            *(float2*)&Og[ob + (long long)rg0 * 64 + d] = w0;
            *(float2*)&Og[ob + (long long)(rg0 + 8) * 64 + d] = w1;
        }
        if (t4 == 0) {
            Lg[(long long)(blockIdx.y * BHD + bh) * rows + rg0]     = l0;
            Lg[(long long)(blockIdx.y * BHD + bh) * rows + rg0 + 8] = l1;
        }
    } else {
        float i0 = 1.f / l0, i1 = 1.f / l1;
        long long ob = (long long)bh * rows * 64;
        #pragma unroll
        for (int dt = 0; dt < 8; dt++) {
            int d = dt * 8 + 2 * t4;
            float2 w0; w0.x = o[dt][0] * i0; w0.y = o[dt][1] * i0;
            float2 w1; w1.x = o[dt][2] * i1; w1.y = o[dt][3] * i1;
            *(float2*)&Og[ob + (long long)rg0 * 64 + d] = w0;
            *(float2*)&Og[ob + (long long)(rg0 + 8) * 64 + d] = w1;
        }
    }
}

// combine 4 split-KV partials -> a3v row-major splits, scaled S_PINV
__global__ void combine4(const float* __restrict__ P, const float* __restrict__ L,
                         __half* __restrict__ Rh, __half* __restrict__ Rl)
{
    int idx = blockIdx.x * 256 + threadIdx.x;
    int bhr = idx >> 6;
    const int SL = BHD * NL;
    const int SD = BHD * NL * DH;
    float l = L[bhr] + L[SL + bhr] + L[2 * SL + bhr] + L[3 * SL + bhr];
    float val = (P[idx] + P[SD + idx] + P[2 * SD + idx] + P[3 * SD + idx]) / l;
    __half h, lo2;
    split_h(val * S_PINV, h, lo2);
    Rh[idx] = h; Rl[idx] = lo2;
}

// ---------------- split kernel ----------------
__global__ void split_rm(const float* __restrict__ src, __half* __restrict__ hi,
                         __half* __restrict__ lo, float S, long long n)
{
    long long idx = (long long)blockIdx.x * 256 + threadIdx.x;
    if (idx >= n) return;
    __half h, l;
    split_h(src[idx] * S, h, l);
    hi[idx] = h; lo[idx] = l;
}

// ---------------- landmark means ----------------
__global__ void landmark_mean(const float* __restrict__ src, float* __restrict__ dst)
{
    long long idx = (long long)blockIdx.x * 256 + threadIdx.x;
    int d  = idx & 63;
    int mm = (int)((idx >> 6) & 255);
    long long bh = idx >> 14;
    const float* base = src + ((bh * NSEQ) + (long long)mm * LGRP) * DH + d;
    float s = 0.f;
    #pragma unroll
    for (int t = 0; t < LGRP; t++) s += base[(long long)t * DH];
    dst[idx] = s * (1.0f / LGRP);
}

// ---------------- row softmax (a2), emits scaled splits ----------------
__global__ void softmax_rows(float* __restrict__ data, int L,
                             __half* __restrict__ sh, __half* __restrict__ sl)
{
    long long row = blockIdx.x;
    float* p = data + row * (long long)L;
    __shared__ float red[256];
    int t = threadIdx.x;

    float mx = -INFINITY;
    for (int i = t; i < L; i += 256) mx = fmaxf(mx, p[i]);
    red[t] = mx; __syncthreads();
    for (int s = 128; s > 0; s >>= 1) { if (t < s) red[t] = fmaxf(red[t], red[t + s]); __syncthreads(); }
    mx = red[0]; __syncthreads();

    float sm = 0.f;
    for (int i = t; i < L; i += 256) { float e = expf(p[i] - mx); p[i] = e; sm += e; }
    red[t] = sm; __syncthreads();
    for (int s = 128; s > 0; s >>= 1) { if (t < s) red[t] += red[t + s]; __syncthreads(); }
    float inv = 1.f / red[0];
    for (int i = t; i < L; i += 256) {
        float val = p[i] * inv;
        p[i] = val;
        __half h, l;
        split_h(val * S_PINV, h, l);
        sh[row * L + i] = h;
        sl[row * L + i] = l;
    }
}

// ---------------- pinv init scalars ----------------
// Rows of softmaxed a2 sum to exactly 1 => row-sum max = 1 identically;
// only the column-sum max is data-dependent.
__global__ void scal_init(float* scal) { scal[0] = 1.0f; scal[1] = 0.f; }

__global__ void colsum_max(const float* __restrict__ a, float* scal)
{
    int j = blockIdx.x, bh = blockIdx.y, t = threadIdx.x;
    __shared__ float red[256];
    red[t] = a[(((long long)bh * NL) + t) * NL + j];
    __syncthreads();
    for (int s = 128; s > 0; s >>= 1) { if (t < s) red[t] += red[t + s]; __syncthreads(); }
    if (t == 0) atomicMax((int*)(scal + 1), __float_as_int(red[0]));
}

// z0 = a2^T / (col*row): row-major splits, scaled
__global__ void zinit(const float* __restrict__ a,
                      __half* __restrict__ zh, __half* __restrict__ zl,
                      const float* __restrict__ scal)
{
    long long idx = (long long)blockIdx.x * 256 + threadIdx.x;
    float inv = S_PINV / (scal[0] * scal[1]);
    int j = (int)(idx & 255);
    int i = (int)((idx >> 8) & 255);
    long long bh = idx >> 16;
    float val = a[(bh << 16) + ((long long)j << 8) + i] * inv;
    __half h, l;
    split_h(val, h, l);
    zh[idx] = h; zl[idx] = l;
}

// ---------------- depthwise conv of v (runs early, overlapped) ----------------
__global__ void conv_pre(const float* __restrict__ v, const float* __restrict__ ker,
                         float* __restrict__ cv)
{
    long long idx = (long long)blockIdx.x * 256 + threadIdx.x;
    int d  = (int)(idx & 63);
    int h  = (int)((idx >> 6) & 7);
    int nn = (int)((idx >> 9) & 4095);
    int b  = (int)(idx >> 21);
    long long bh = (long long)b * HEADS + h;
    const float* vb = v + (bh * NSEQ) * DH + d;
    float s = 0.f;
    #pragma unroll
    for (int t = 0; t < CONV_TAPS; t++) {
        int pos = nn + t - CONV_PAD;
        if (pos >= 0 && pos < NSEQ) s += vb[(long long)pos * DH] * ker[h * CONV_TAPS + t];
    }
    cv[idx] = s;
}

// ---------------- tail: oh + cv -> x2 splits ----------------
__global__ void add_split(const float* __restrict__ oh, const float* __restrict__ cv,
                          __half* __restrict__ x2h, __half* __restrict__ x2l)
{
    long long idx = (long long)blockIdx.x * 256 + threadIdx.x;
    int d  = (int)(idx & 63);
    int h  = (int)((idx >> 6) & 7);
    int nn = (int)((idx >> 9) & 4095);
    int b  = (int)(idx >> 21);
    long long bh = (long long)b * HEADS + h;
    float val = oh[(bh * NSEQ + nn) * DH + d] + cv[idx];
    __half hh, ll;
    split_h(val, hh, ll);
    x2h[idx] = hh; x2l[idx] = ll;
}

// ---------------- host ----------------
template<int BN, int PREC>
static void launch_h3(const __half* Ah, const __half* Al, const __half* Bh, const __half* Bl,
                      int M, int N, int K, long long sA, long long sB, int batch,
                      float scale, float outS,
                      float* Cf, long long sC, const float* bias,
                      __half* R1h, __half* R1l, long long sR1,
                      __half* R2h, __half* R2l, long long sR2, float dv,
                      int qkv, float qscale, float* qp, float* kp, float* vp,
                      cudaStream_t st = 0)
{
    size_t smem = (size_t)((PREC == 3 ? 2 : 1) * 3 * (128 * 40 + 32 * (BN + 8))) * 2;
    cudaFuncSetAttribute(gemm_h3<BN, PREC>, cudaFuncAttributeMaxDynamicSharedMemorySize, (int)smem);
    dim3 grid(N / BN, M / 128, batch);
    gemm_h3<BN, PREC><<<grid, 512, smem, st>>>(Ah, Al, Bh, Bl, M, N, K, sA, sB,
                                               scale, outS, Cf, sC, bias,
                                               R1h, R1l, sR1, R2h, R2l, sR2, dv,
                                               qkv, qscale, qp, kp, vp);
}

extern "C" void kernel_launch(void* const* d_in, const int* in_sizes, int n_in,
                              void* d_out, int out_size)
{
    const float* x      = (const float*)d_in[0];
    const float* w_qkv  = (const float*)d_in[1];
    const float* w_out  = (const float*)d_in[2];
    const float* b_out  = (const float*)d_in[3];
    const float* res_k  = (const float*)d_in[4];
    float* out = (float*)d_out;

    float *q, *k, *v, *ql, *kl, *a2, *za3v, *part, *lpart, *oh, *cv, *scal;
    cudaGetSymbolAddress((void**)&q,     g_q);
    cudaGetSymbolAddress((void**)&k,     g_k);
    cudaGetSymbolAddress((void**)&v,     g_v);
    cudaGetSymbolAddress((void**)&ql,    g_ql);
    cudaGetSymbolAddress((void**)&kl,    g_kl);
    cudaGetSymbolAddress((void**)&a2,    g_a2);
    cudaGetSymbolAddress((void**)&za3v,  g_za3v);
    cudaGetSymbolAddress((void**)&part,  g_part);
    cudaGetSymbolAddress((void**)&lpart, g_lpart);
    cudaGetSymbolAddress((void**)&oh,    g_oh);
    cudaGetSymbolAddress((void**)&cv,    g_cv);
    cudaGetSymbolAddress((void**)&scal,  g_scal);

    __half *xh, *xl, *wqh, *wql, *woh, *wol, *x2h, *x2l, *a2h, *a2l;
    __half *zAh, *zAl, *zBh, *zBl, *xzh, *xzl, *T1h, *T1l, *T2h, *T2l, *a3vh, *a3vl;
    cudaGetSymbolAddress((void**)&xh,   g_xh);
    cudaGetSymbolAddress((void**)&xl,   g_xl);
    cudaGetSymbolAddress((void**)&wqh,  g_wqh);
    cudaGetSymbolAddress((void**)&wql,  g_wql);
    cudaGetSymbolAddress((void**)&woh,  g_woh);
    cudaGetSymbolAddress((void**)&wol,  g_wol);
    cudaGetSymbolAddress((void**)&x2h,  g_x2h);
    cudaGetSymbolAddress((void**)&x2l,  g_x2l);
    cudaGetSymbolAddress((void**)&a2h,  g_a2h);
    cudaGetSymbolAddress((void**)&a2l,  g_a2l);
    cudaGetSymbolAddress((void**)&zAh,  g_zAh);
    cudaGetSymbolAddress((void**)&zAl,  g_zAl);
    cudaGetSymbolAddress((void**)&zBh,  g_zBh);
    cudaGetSymbolAddress((void**)&zBl,  g_zBl);
    cudaGetSymbolAddress((void**)&xzh,  g_xzh);
    cudaGetSymbolAddress((void**)&xzl,  g_xzl);
    cudaGetSymbolAddress((void**)&T1h,  g_T1h);
    cudaGetSymbolAddress((void**)&T1l,  g_T1l);
    cudaGetSymbolAddress((void**)&T2h,  g_T2h);
    cudaGetSymbolAddress((void**)&T2l,  g_T2l);
    cudaGetSymbolAddress((void**)&a3vh, g_a3vh);
    cudaGetSymbolAddress((void**)&a3vl, g_a3vl);

    cudaFuncSetAttribute(flash_pv<0>, cudaFuncAttributeMaxDynamicSharedMemorySize, (int)sizeof(FlashSmem));
    cudaFuncSetAttribute(flash_pv<1>, cudaFuncAttributeMaxDynamicSharedMemorySize, (int)sizeof(FlashSmem));

    const long long sb = (long long)NL * NL;
    const long long svd = (long long)NL * DH;

    cudaStream_t s2;
    cudaStreamCreateWithFlags(&s2, cudaStreamNonBlocking);
    cudaEvent_t evFork, evJoin;
    cudaEventCreateWithFlags(&evFork, cudaEventDisableTiming);
    cudaEventCreateWithFlags(&evJoin, cudaEventDisableTiming);

    // 0) operand splits
    {
        long long n = (long long)BATCH * NSEQ * DIM;
        split_rm<<<(unsigned)((n + 255) / 256), 256>>>(x, xh, xl, 1.0f, n);
        long long nw = (long long)DIM * 3 * DIM;
        split_rm<<<(unsigned)((nw + 255) / 256), 256>>>(w_qkv, wqh, wql, S_W, nw);
        long long nw2 = (long long)DIM * DIM;
        split_rm<<<(unsigned)((nw2 + 255) / 256), 256>>>(w_out, woh, wol, S_W, nw2);
    }

    // 1) qkv projection (fp16x3, 512-thread GEMM) + scatter
    launch_h3<128, 3>(xh, xl, wqh, wql, BATCH * NSEQ, 3 * DIM, DIM, 0, 0, 1,
                      1.0f / S_W, 1.0f,
                      nullptr, 0, nullptr, nullptr, nullptr, 0,
                      nullptr, nullptr, 0, 0.f, 1, 0.125f, q, k, v);

    // 2) landmarks
    {
        long long n = (long long)BHD * NL * DH;
        landmark_mean<<<(unsigned)(n / 256), 256>>>(q, ql);
        landmark_mean<<<(unsigned)(n / 256), 256>>>(k, kl);
    }

    // ---- fork: flash1 (a3v) + conv(v) on s2, concurrent with a2/pinv ----
    cudaEventRecord(evFork, 0);
    cudaStreamWaitEvent(s2, evFork, 0);
    {
        dim3 grid(NL / 128, 4, BHD);
        flash_pv<1><<<grid, 256, sizeof(FlashSmem), s2>>>(ql, k, v, part, lpart, NL, NSEQ, NSEQ / 4);
        combine4<<<(BHD * NL * DH) / 256, 256, 0, s2>>>(part, lpart, a3vh, a3vl);
        conv_pre<<<(unsigned)((long long)BATCH * NSEQ * HEADS * DH / 256), 256, 0, s2>>>(v, res_k, cv);
    }
    cudaEventRecord(evJoin, s2);

    // 3) a2 = ql @ kl^T (tf32x3, fp32) + softmax (emits splits)
    {
        size_t smem = (size_t)(3 * 128 * 20 + 3 * 128 * 20) * 4;
        cudaFuncSetAttribute(gemm_tf32<128, 1>, cudaFuncAttributeMaxDynamicSharedMemorySize, (int)smem);
        dim3 grid(NL / 128, NL / 128, BHD);
        gemm_tf32<128, 1><<<grid, 256, smem>>>(ql, kl, a2, NL, NL, DH, svd, svd, sb);
    }
    softmax_rows<<<BHD * NL, 256>>>(a2, NL, a2h, a2l);

    // 4) pinv init (row-sum max = 1 exactly for softmax output)
    scal_init<<<1, 1>>>(scal);
    {
        dim3 g(NL, BHD);
        colsum_max<<<g, 256>>>(a2, scal);
    }
    zinit<<<(unsigned)((long long)BHD * NL * NL / 256), 256>>>(a2, zAh, zAl, scal);

    // 5) Newton iterations (launch-based; persistent-kernel variants measured
    //    slower twice). 5 iterations: 4 cheap (1-pass fp16) + 1 full (3-pass),
    //    justified by the iteration's 3rd-order contraction.
    __half *zch = zAh, *zcl = zAl, *znh = zBh, *znl = zBl;
    const float sa2 = 1.0f / (S_PINV * S_PINV);
    const int NITER = 5;
    for (int it = 0; it < NITER; it++) {
        bool cheap = (it < NITER - 1);
        #define PINV_STEP(PREC_) \
            launch_h3<128, PREC_>(a2h, a2l, zch, zcl, NL, NL, NL, sb, sb, BHD, \
                           sa2, S_PINV, nullptr, 0, nullptr, \
                           xzh, xzl, sb, T1h, T1l, sb, 7.0f, \
                           0, 0.f, nullptr, nullptr, nullptr); \
            launch_h3<128, PREC_>(xzh, xzl, T1h, T1l, NL, NL, NL, sb, sb, BHD, \
                           sa2, S_PINV, nullptr, 0, nullptr, \
                           nullptr, nullptr, 0, T2h, T2l, sb, 15.0f, \
                           0, 0.f, nullptr, nullptr, nullptr); \
            launch_h3<128, PREC_>(xzh, xzl, T2h, T2l, NL, NL, NL, sb, sb, BHD, \
                           sa2, S_PINV, nullptr, 0, nullptr, \
                           nullptr, nullptr, 0, T1h, T1l, sb, 13.0f, \
                           0, 0.f, nullptr, nullptr, nullptr); \
            launch_h3<128, PREC_>(zch, zcl, T1h, T1l, NL, NL, NL, sb, sb, BHD, \
                           0.25f * sa2, S_PINV, nullptr, 0, nullptr, \
                           znh, znl, sb, nullptr, nullptr, 0, 0.f, \
                           0, 0.f, nullptr, nullptr, nullptr);
        if (cheap) { PINV_STEP(1) } else { PINV_STEP(3) }
        #undef PINV_STEP
        __half* t;
        t = zch; zch = znh; znh = t;
        t = zcl; zcl = znl; znl = t;
    }

    // ---- join: za3v needs a3v (and later add_split needs cv) from s2 ----
    cudaStreamWaitEvent(0, evJoin, 0);

    // 7) za3v = z @ a3v (fp16x3) -> fp32
    launch_h3<64, 3>(zch, zcl, a3vh, a3vl, NL, DH, NL, sb, svd, BHD,
                     sa2, 1.0f, za3v, svd, nullptr,
                     nullptr, nullptr, 0, nullptr, nullptr, 0, 0.f,
                     0, 0.f, nullptr, nullptr, nullptr);

    // 8) oh = softmax(q @ kl^T) @ za3v — flash
    {
        dim3 grid(NSEQ / 128, 1, BHD);
        flash_pv<0><<<grid, 256, sizeof(FlashSmem)>>>(q, kl, za3v, oh, nullptr, NSEQ, NL, NL);
    }

    // 9) tail: oh + precomputed conv -> x2 splits
    add_split<<<(unsigned)((long long)BATCH * NSEQ * HEADS * DH / 256), 256>>>(oh, cv, x2h, x2l);

    // 10) out = x2 @ w_out + b_out (fp16x3)
    launch_h3<128, 3>(x2h, x2l, woh, wol, BATCH * NSEQ, DIM, DIM, 0, 0, 1,
                      1.0f / S_W, 1.0f,
                      out, 0, b_out, nullptr, nullptr, 0,
                      nullptr, nullptr, 0, 0.f, 0, 0.f, nullptr, nullptr, nullptr);

    cudaEventDestroy(evFork);
    cudaEventDestroy(evJoin);
    cudaStreamDestroy(s2);
}

// round 14
// speedup vs baseline: 1.0717x; 1.0141x over previous
#include <cuda_runtime.h>
#include <cuda_fp16.h>
#include <math.h>
#include <stdint.h>

// ---------------- problem constants ----------------
#define BATCH 4
#define HEADS 8
#define NSEQ  4096
#define DH    64
#define DIM   512
#define NL    256
#define LGRP  16
#define BHD   (BATCH*HEADS)
#define CONV_TAPS 33
#define CONV_PAD 16

#define S_PINV 64.0f
#define S_W    256.0f

// ---------------- scratch (fp32) ----------------
__device__ float g_q [(size_t)BHD*NSEQ*DH];
__device__ float g_k [(size_t)BHD*NSEQ*DH];
__device__ float g_v [(size_t)BHD*NSEQ*DH];
__device__ float g_ql[(size_t)BHD*NL*DH];
__device__ float g_kl[(size_t)BHD*NL*DH];
__device__ float g_a2[(size_t)BHD*NL*NL];
__device__ float g_part[(size_t)4*BHD*NL*DH];
__device__ float g_lpart[(size_t)4*BHD*NL];
__device__ float g_oh [(size_t)BHD*NSEQ*DH];
__device__ float g_Lf [(size_t)BHD*NSEQ];
__device__ float g_scal[2];

// ---------------- scratch (half splits; all row-major) ----------------
__device__ __half g_xh [(size_t)BATCH*NSEQ*DIM];
__device__ __half g_xl [(size_t)BATCH*NSEQ*DIM];
__device__ __half g_wqh[(size_t)DIM*3*DIM];
__device__ __half g_wql[(size_t)DIM*3*DIM];
__device__ __half g_woh[(size_t)DIM*DIM];
__device__ __half g_wol[(size_t)DIM*DIM];
__device__ __half g_x2h[(size_t)BATCH*NSEQ*DIM];
__device__ __half g_x2l[(size_t)BATCH*NSEQ*DIM];
__device__ __half g_a2h[(size_t)BHD*NL*NL];
__device__ __half g_a2l[(size_t)BHD*NL*NL];
__device__ __half g_zAh[(size_t)BHD*NL*NL];
__device__ __half g_zAl[(size_t)BHD*NL*NL];
__device__ __half g_zBh[(size_t)BHD*NL*NL];
__device__ __half g_zBl[(size_t)BHD*NL*NL];
__device__ __half g_xzh[(size_t)BHD*NL*NL];
__device__ __half g_xzl[(size_t)BHD*NL*NL];
__device__ __half g_T1h[(size_t)BHD*NL*NL];
__device__ __half g_T1l[(size_t)BHD*NL*NL];
__device__ __half g_T2h[(size_t)BHD*NL*NL];
__device__ __half g_T2l[(size_t)BHD*NL*NL];
__device__ __half g_a3vh[(size_t)BHD*NL*DH];
__device__ __half g_a3vl[(size_t)BHD*NL*DH];
__device__ __half g_za3vh[(size_t)BHD*NL*DH];
__device__ __half g_za3vl[(size_t)BHD*NL*DH];
__device__ __half g_P  [(size_t)BHD*NSEQ*NL];   // unnormalized exp scores

// ---------------- helpers ----------------
__device__ __forceinline__ void split_tf32(float v, uint32_t &hi, uint32_t &lo) {
    asm("cvt.rna.tf32.f32 %0, %1;" : "=r"(hi) : "f"(v));
    float r = v - __uint_as_float(hi);
    asm("cvt.rna.tf32.f32 %0, %1;" : "=r"(lo) : "f"(r));
}

__device__ __forceinline__ void split_h(float v, __half &hi, __half &lo) {
    hi = __float2half_rn(v);
    lo = __float2half_rn(v - __half2float(hi));
}

#define MMA_TF32(D, A0,A1,A2,A3, B0,B1) \
    asm volatile("mma.sync.aligned.m16n8k8.row.col.f32.tf32.tf32.f32 " \
                 "{%0,%1,%2,%3},{%4,%5,%6,%7},{%8,%9},{%0,%1,%2,%3};" \
                 : "+f"((D)[0]), "+f"((D)[1]), "+f"((D)[2]), "+f"((D)[3]) \
                 : "r"(A0), "r"(A1), "r"(A2), "r"(A3), "r"(B0), "r"(B1))

#define MMA_F16(D, a0,a1,a2,a3, b0,b1) \
    asm volatile("mma.sync.aligned.m16n8k16.row.col.f32.f16.f16.f32 " \
                 "{%0,%1,%2,%3},{%4,%5,%6,%7},{%8,%9},{%0,%1,%2,%3};" \
                 : "+f"((D)[0]), "+f"((D)[1]), "+f"((D)[2]), "+f"((D)[3]) \
                 : "r"(a0), "r"(a1), "r"(a2), "r"(a3), "r"(b0), "r"(b1))

__device__ __forceinline__ void cp16(void* smem, const void* g) {
    uint32_t sa = (uint32_t)__cvta_generic_to_shared(smem);
    asm volatile("cp.async.ca.shared.global [%0], [%1], 16;" :: "r"(sa), "l"(g));
}
#define CP_COMMIT asm volatile("cp.async.commit_group;")
#define CP_WAIT0  asm volatile("cp.async.wait_group 0;")
#define CP_WAIT1  asm volatile("cp.async.wait_group 1;")

__device__ __forceinline__ uint32_t packh2(float a, float b) {
    __half2 h = __floats2half2_rn(a, b);
    return *reinterpret_cast<uint32_t*>(&h);
}

__device__ __forceinline__ void ldsm4(uint32_t* r, const __half* p) {
    uint32_t a = (uint32_t)__cvta_generic_to_shared(p);
    asm volatile("ldmatrix.sync.aligned.m8n8.x4.shared.b16 {%0,%1,%2,%3}, [%4];"
                 : "=r"(r[0]), "=r"(r[1]), "=r"(r[2]), "=r"(r[3]) : "r"(a));
}
__device__ __forceinline__ void ldsm4t(uint32_t* r, const __half* p) {
    uint32_t a = (uint32_t)__cvta_generic_to_shared(p);
    asm volatile("ldmatrix.sync.aligned.m8n8.x4.trans.shared.b16 {%0,%1,%2,%3}, [%4];"
                 : "=r"(r[0]), "=r"(r[1]), "=r"(r[2]), "=r"(r[3]) : "r"(a));
}

// ================= fp16 batched GEMM — 512 threads, warp tile 32x32 =====
template<int BN, int PREC>
__global__ void __launch_bounds__(512, 1)
gemm_h3(const __half* __restrict__ Ahg, const __half* __restrict__ Alg,
        const __half* __restrict__ Bhg, const __half* __restrict__ Blg,
        int M, int N, int K, long long sA, long long sB,
        float scale, float outS,
        float* __restrict__ Cf, long long sC, const float* __restrict__ bias,
        __half* __restrict__ R1h, __half* __restrict__ R1l, long long sR1,
        __half* __restrict__ R2h, __half* __restrict__ R2l, long long sR2, float dv,
        int qkv, float qscale,
        float* __restrict__ qp, float* __restrict__ kp, float* __restrict__ vp)
{
    constexpr int NT  = BN / 32;
    constexpr int ALD = 40;
    constexpr int BLD = BN + 8;
    constexpr int ASZ = 128 * ALD;
    constexpr int BSZ = 32 * BLD;

    const int zb = blockIdx.z;
    const __half* Ah_g = Ahg + (long long)zb * sA;
    const __half* Al_g = Alg + (long long)zb * sA;
    const __half* Bh_g = Bhg + (long long)zb * sB;
    const __half* Bl_g = Blg + (long long)zb * sB;
    if (Cf)  Cf  += (long long)zb * sC;
    if (R1h) { R1h += (long long)zb * sR1; R1l += (long long)zb * sR1; }
    if (R2h) { R2h += (long long)zb * sR2; R2l += (long long)zb * sR2; }

    extern __shared__ __half hsm[];
    __half* Ash = hsm;
    __half* Asl = Ash + 3 * ASZ;
    __half* Bsh = (PREC == 3) ? (Asl + 3 * ASZ) : (Ash + 3 * ASZ);
    __half* Bsl = Bsh + 3 * BSZ;

    const int brow = blockIdx.y * 128;
    const int bcol = blockIdx.x * BN;

    const int tid  = threadIdx.x;
    const int warp = tid >> 5;
    const int lane = tid & 31;
    const int wm   = warp & 3;
    const int wn   = warp >> 2;
    const int grp  = lane >> 2;
    const int t4   = lane & 3;
    const int r8   = lane & 7;
    const int quad = lane >> 3;

    const int nk = K / 32;

    auto load_stage = [&](int s, int kt) {
        int k0 = kt * 32;
        {
            int row = tid >> 2, seg = (tid & 3) * 8;
            cp16(&Ash[(s * 128 + row) * ALD + seg], &Ah_g[(long long)(brow + row) * K + k0 + seg]);
            if (PREC == 3)
                cp16(&Asl[(s * 128 + row) * ALD + seg], &Al_g[(long long)(brow + row) * K + k0 + seg]);
        }
        if (tid < BN * 4) {
            int row = tid / (BN / 8), seg = (tid % (BN / 8)) * 8;
            cp16(&Bsh[(s * 32 + row) * BLD + seg], &Bh_g[(long long)(k0 + row) * N + bcol + seg]);
            if (PREC == 3)
                cp16(&Bsl[(s * 32 + row) * BLD + seg], &Bl_g[(long long)(k0 + row) * N + bcol + seg]);
        }
    };

    float acc[2][NT][4];
    #pragma unroll
    for (int i = 0; i < 2; i++)
        #pragma unroll
        for (int j = 0; j < NT; j++)
            #pragma unroll
            for (int l = 0; l < 4; l++) acc[i][j][l] = 0.f;

    load_stage(0, 0); CP_COMMIT;
    load_stage(1, 1); CP_COMMIT;

    for (int kt = 0; kt < nk; kt++) {
        CP_WAIT1;
        __syncthreads();
        int buf = kt % 3;
        if (kt + 2 < nk) load_stage((kt + 2) % 3, kt + 2);
        CP_COMMIT;

        #pragma unroll
        for (int ss = 0; ss < 2; ss++) {
            int kb = ss * 16;
            uint32_t ah[2][4], al[2][4];
            #pragma unroll
            for (int mt = 0; mt < 2; mt++) {
                int m0 = wm * 32 + mt * 16;
                int off = (buf * 128 + m0 + r8 + (quad & 1) * 8) * ALD + kb + (quad >> 1) * 8;
                ldsm4(ah[mt], Ash + off);
                if (PREC == 3) ldsm4(al[mt], Asl + off);
            }
            uint32_t bh[NT][2], bl[NT][2];
            #pragma unroll
            for (int np = 0; np < NT / 2; np++) {
                int n0 = wn * (BN / 4) + np * 16;
                int off = (buf * 32 + kb + (quad & 1) * 8 + r8) * BLD + n0 + (quad >> 1) * 8;
                uint32_t tb[4];
                ldsm4t(tb, Bsh + off);
                bh[np * 2][0] = tb[0]; bh[np * 2][1] = tb[1];
                bh[np * 2 + 1][0] = tb[2]; bh[np * 2 + 1][1] = tb[3];
                if (PREC == 3) {
                    ldsm4t(tb, Bsl + off);
                    bl[np * 2][0] = tb[0]; bl[np * 2][1] = tb[1];
                    bl[np * 2 + 1][0] = tb[2]; bl[np * 2 + 1][1] = tb[3];
                }
            }
            #pragma unroll
            for (int mt = 0; mt < 2; mt++)
                #pragma unroll
                for (int nt = 0; nt < NT; nt++) {
                    MMA_F16(acc[mt][nt], ah[mt][0], ah[mt][1], ah[mt][2], ah[mt][3], bh[nt][0], bh[nt][1]);
                    if (PREC == 3) {
                        MMA_F16(acc[mt][nt], ah[mt][0], ah[mt][1], ah[mt][2], ah[mt][3], bl[nt][0], bl[nt][1]);
                        MMA_F16(acc[mt][nt], al[mt][0], al[mt][1], al[mt][2], al[mt][3], bh[nt][0], bh[nt][1]);
                    }
                }
        }
    }

    #pragma unroll
    for (int mt = 0; mt < 2; mt++) {
        int r0 = brow + wm * 32 + mt * 16 + grp;
        #pragma unroll
        for (int nt = 0; nt < NT; nt++) {
            int c = bcol + wn * (BN / 4) + nt * 8 + t4 * 2;
            #pragma unroll
            for (int half_i = 0; half_i < 2; half_i++) {
                int r = r0 + half_i * 8;
                float v0 = acc[mt][nt][half_i * 2 + 0] * scale;
                float v1 = acc[mt][nt][half_i * 2 + 1] * scale;
                if (qkv) {
                    int bidx = r >> 12, nn = r & 4095;
                    int part = c / DIM, rem = c % DIM;
                    int hh = rem >> 6, dd = rem & 63;
                    long long dst = ((((long long)bidx * HEADS + hh) * NSEQ) + nn) * DH + dd;
                    float2 val;
                    if (part == 0) { val.x = v0 * qscale; val.y = v1 * qscale; *(float2*)&qp[dst] = val; }
                    else if (part == 1) { val.x = v0; val.y = v1; *(float2*)&kp[dst] = val; }
                    else { val.x = v0; val.y = v1; *(float2*)&vp[dst] = val; }
                } else {
                    if (Cf) {
                        float b0 = bias ? bias[c] : 0.f;
                        float b1 = bias ? bias[c + 1] : 0.f;
                        float2 val; val.x = v0 + b0; val.y = v1 + b1;
                        *(float2*)&Cf[(long long)r * N + c] = val;
                    }
                    if (R1h) {
                        __half h0, l0, h1, l1;
                        split_h(v0 * outS, h0, l0);
                        split_h(v1 * outS, h1, l1);
                        __half2 hp; hp.x = h0; hp.y = h1;
                        __half2 lp; lp.x = l0; lp.y = l1;
                        *(__half2*)&R1h[(long long)r * N + c] = hp;
                        *(__half2*)&R1l[(long long)r * N + c] = lp;
                    }
                    if (R2h) {
                        float tv0 = (((r == c) ? dv : 0.f) - v0) * outS;
                        float tv1 = (((r == c + 1) ? dv : 0.f) - v1) * outS;
                        __half h0, l0, h1, l1;
                        split_h(tv0, h0, l0);
                        split_h(tv1, h1, l1);
                        __half2 hp; hp.x = h0; hp.y = h1;
                        __half2 lp; lp.x = l0; lp.y = l1;
                        *(__half2*)&R2h[(long long)r * N + c] = hp;
                        *(__half2*)&R2l[(long long)r * N + c] = lp;
                    }
                }
            }
        }
    }
}

// ================= 3xTF32 GEMM (a2 = ql @ kl^T only) =================
template<int BN, int TB>
__global__ void __launch_bounds__(256, 1)
gemm_tf32(const float* __restrict__ Ag, const float* __restrict__ Bg,
          float* __restrict__ Cg, int M, int N, int K,
          long long sA, long long sB, long long sC)
{
    constexpr int NT   = BN / 32;
    constexpr int BSZ  = TB ? BN * 20 : 16 * (BN + 8);
    constexpr int ASZ  = 128 * 20;

    extern __shared__ char dynsm[];
    float* As = (float*)dynsm;
    float* Bs = As + 3 * ASZ;

    const float* A = Ag + (long long)blockIdx.z * sA;
    const float* B = Bg + (long long)blockIdx.z * sB;
    float*       C = Cg + (long long)blockIdx.z * sC;

    const int brow = blockIdx.y * 128;
    const int bcol = blockIdx.x * BN;

    const int tid  = threadIdx.x;
    const int warp = tid >> 5;
    const int lane = tid & 31;
    const int wm   = warp & 1;
    const int wn   = warp >> 1;
    const int grp  = lane >> 2;
    const int t4   = lane & 3;

    const int a_row0 = tid >> 2;
    const int a_k    = (tid & 3) * 4;
    const int nk = K / 16;

    auto load_stage = [&](int s, int kt) {
        int k0 = kt * 16;
        cp16(&As[s * ASZ + a_row0 * 20 + a_k],        &A[(long long)(brow + a_row0) * K + k0 + a_k]);
        cp16(&As[s * ASZ + (a_row0 + 64) * 20 + a_k], &A[(long long)(brow + a_row0 + 64) * K + k0 + a_k]);
        #pragma unroll
        for (int j = 0; j < BN / 64; j++) {
            int i = tid + 256 * j;
            int n  = i >> 2;
            int kq = (i & 3) * 4;
            cp16(&Bs[s * BSZ + n * 20 + kq], &B[(long long)(bcol + n) * K + k0 + kq]);
        }
    };

    float acc[4][NT][4];
    #pragma unroll
    for (int i = 0; i < 4; i++)
        #pragma unroll
        for (int j = 0; j < NT; j++)
            #pragma unroll
            for (int l = 0; l < 4; l++) acc[i][j][l] = 0.f;

    load_stage(0, 0); CP_COMMIT;
    load_stage(1, 1); CP_COMMIT;

    for (int kt = 0; kt < nk; kt++) {
        CP_WAIT1;
        __syncthreads();
        int buf = kt % 3;
        if (kt + 2 < nk) load_stage((kt + 2) % 3, kt + 2);
        CP_COMMIT;

        #pragma unroll
        for (int ss = 0; ss < 2; ss++) {
            int kb = ss * 8;
            uint32_t ah[4][4], al[4][4];
            #pragma unroll
            for (int mt = 0; mt < 4; mt++) {
                int m = wm * 64 + mt * 16 + grp;
                float f0 = As[buf * ASZ + m * 20 + kb + t4];
                float f1 = As[buf * ASZ + (m + 8) * 20 + kb + t4];
                float f2 = As[buf * ASZ + m * 20 + kb + t4 + 4];
                float f3 = As[buf * ASZ + (m + 8) * 20 + kb + t4 + 4];
                split_tf32(f0, ah[mt][0], al[mt][0]);
                split_tf32(f1, ah[mt][1], al[mt][1]);
                split_tf32(f2, ah[mt][2], al[mt][2]);
                split_tf32(f3, ah[mt][3], al[mt][3]);
            }
            uint32_t bh[NT][2], bl[NT][2];
            #pragma unroll
            for (int nt = 0; nt < NT; nt++) {
                int n = wn * (BN / 4) + nt * 8 + grp;
                float b0 = Bs[buf * BSZ + n * 20 + kb + t4];
                float b1 = Bs[buf * BSZ + n * 20 + kb + t4 + 4];
                split_tf32(b0, bh[nt][0], bl[nt][0]);
                split_tf32(b1, bh[nt][1], bl[nt][1]);
            }
            #pragma unroll
            for (int mt = 0; mt < 4; mt++)
                #pragma unroll
                for (int nt = 0; nt < NT; nt++) {
                    MMA_TF32(acc[mt][nt], ah[mt][0], ah[mt][1], ah[mt][2], ah[mt][3], bh[nt][0], bh[nt][1]);
                    MMA_TF32(acc[mt][nt], ah[mt][0], ah[mt][1], ah[mt][2], ah[mt][3], bl[nt][0], bl[nt][1]);
                    MMA_TF32(acc[mt][nt], al[mt][0], al[mt][1], al[mt][2], al[mt][3], bh[nt][0], bh[nt][1]);
                }
        }
    }

    #pragma unroll
    for (int mt = 0; mt < 4; mt++) {
        int r0 = brow + wm * 64 + mt * 16 + grp;
        #pragma unroll
        for (int nt = 0; nt < NT; nt++) {
            int c = bcol + wn * (BN / 4) + nt * 8 + t4 * 2;
            #pragma unroll
            for (int half_i = 0; half_i < 2; half_i++) {
                int r = r0 + half_i * 8;
                float2 val;
                val.x = acc[mt][nt][half_i * 2 + 0];
                val.y = acc[mt][nt][half_i * 2 + 1];
                *(float2*)&C[(long long)r * N + c] = val;
            }
        }
    }
}

// ---------------- fused flash kernel (flash1 / a3v only) ----------------
struct FlashSmem {
    float  qhi[128][68];
    float  qlo[128][68];
    float  raw[2][2][64][64];
    float  khi[64][68];
    float  klo[64][68];
    __half vh[64][72];
};

template<int PARTIAL>
__global__ void __launch_bounds__(256, 1)
flash_pv(const float* __restrict__ Qg, const float* __restrict__ Kg,
         const float* __restrict__ Vg, float* __restrict__ Og,
         float* __restrict__ Lg, int rows, int keys, int kvchunk)
{
    extern __shared__ char dynsm[];
    FlashSmem& sm = *reinterpret_cast<FlashSmem*>(dynsm);

    const int tid  = threadIdx.x;
    const int warp = tid >> 5;
    const int lane = tid & 31;
    const int grp  = lane >> 2;
    const int t4   = lane & 3;
    const int bh   = blockIdx.z;

    const long long qbase = ((long long)bh * rows + blockIdx.x * 128) * 64;
    const long long kbase = ((long long)bh * keys + (long long)blockIdx.y * kvchunk) * 64;

    #pragma unroll
    for (int j = 0; j < 8; j++) {
        int e = tid + 256 * j;
        int r = e >> 4, c4 = (e & 15) * 4;
        float4 qv = *(const float4*)&Qg[qbase + (long long)r * 64 + c4];
        uint32_t hi, lo;
        split_tf32(qv.x, hi, lo); sm.qhi[r][c4+0] = __uint_as_float(hi); sm.qlo[r][c4+0] = __uint_as_float(lo);
        split_tf32(qv.y, hi, lo); sm.qhi[r][c4+1] = __uint_as_float(hi); sm.qlo[r][c4+1] = __uint_as_float(lo);
        split_tf32(qv.z, hi, lo); sm.qhi[r][c4+2] = __uint_as_float(hi); sm.qlo[r][c4+2] = __uint_as_float(lo);
        split_tf32(qv.w, hi, lo); sm.qhi[r][c4+3] = __uint_as_float(hi); sm.qlo[r][c4+3] = __uint_as_float(lo);
    }

    auto stage = [&](int slot, int sub) {
        long long base = kbase + (long long)sub * 64 * 64;
        #pragma unroll
        for (int j = 0; j < 4; j++) {
            int e = tid + 256 * j;
            int r = e >> 4, c4 = (e & 15) * 4;
            cp16(&sm.raw[slot][0][r][c4], &Kg[base + (long long)r * 64 + c4]);
        }
        #pragma unroll
        for (int j = 0; j < 4; j++) {
            int e = tid + 256 * j;
            int r = e >> 4, c4 = (e & 15) * 4;
            cp16(&sm.raw[slot][1][r][c4], &Vg[base + (long long)r * 64 + c4]);
        }
    };

    const int nsub = kvchunk / 64;
    stage(0, 0); CP_COMMIT;

    float o[8][4];
    #pragma unroll
    for (int i = 0; i < 8; i++)
        #pragma unroll
        for (int j = 0; j < 4; j++) o[i][j] = 0.f;
    float l0 = 0.f, l1 = 0.f;
    const int r0s = warp * 16 + grp;

    for (int sub = 0; sub < nsub; sub++) {
        CP_WAIT0;
        __syncthreads();
        int slot = sub & 1;
        if (sub + 1 < nsub) stage(slot ^ 1, sub + 1);
        CP_COMMIT;

        #pragma unroll
        for (int j = 0; j < 4; j++) {
            int e = tid + 256 * j;
            int r = e >> 4, c4 = (e & 15) * 4;
            float4 kv = *(const float4*)&sm.raw[slot][0][r][c4];
            uint32_t hi, lo;
            split_tf32(kv.x, hi, lo); sm.khi[r][c4+0] = __uint_as_float(hi); sm.klo[r][c4+0] = __uint_as_float(lo);
            split_tf32(kv.y, hi, lo); sm.khi[r][c4+1] = __uint_as_float(hi); sm.klo[r][c4+1] = __uint_as_float(lo);
            split_tf32(kv.z, hi, lo); sm.khi[r][c4+2] = __uint_as_float(hi); sm.klo[r][c4+2] = __uint_as_float(lo);
            split_tf32(kv.w, hi, lo); sm.khi[r][c4+3] = __uint_as_float(hi); sm.klo[r][c4+3] = __uint_as_float(lo);
            float4 vv = *(const float4*)&sm.raw[slot][1][r][c4];
            sm.vh[c4+0][r] = __float2half(vv.x);
            sm.vh[c4+1][r] = __float2half(vv.y);
            sm.vh[c4+2][r] = __float2half(vv.z);
            sm.vh[c4+3][r] = __float2half(vv.w);
        }
        __syncthreads();

        float s[8][4];
        #pragma unroll
        for (int i = 0; i < 8; i++)
            #pragma unroll
            for (int j = 0; j < 4; j++) s[i][j] = 0.f;

        #pragma unroll
        for (int ks = 0; ks < 8; ks++) {
            int kk = ks * 8;
            uint32_t a0h = __float_as_uint(sm.qhi[r0s][kk + t4]);
            uint32_t a1h = __float_as_uint(sm.qhi[r0s + 8][kk + t4]);
            uint32_t a2h = __float_as_uint(sm.qhi[r0s][kk + t4 + 4]);
            uint32_t a3h = __float_as_uint(sm.qhi[r0s + 8][kk + t4 + 4]);
            uint32_t a0l = __float_as_uint(sm.qlo[r0s][kk + t4]);
            uint32_t a1l = __float_as_uint(sm.qlo[r0s + 8][kk + t4]);
            uint32_t a2l = __float_as_uint(sm.qlo[r0s][kk + t4 + 4]);
            uint32_t a3l = __float_as_uint(sm.qlo[r0s + 8][kk + t4 + 4]);
            #pragma unroll
            for (int nt = 0; nt < 8; nt++) {
                int n = nt * 8 + grp;
                uint32_t b0h = __float_as_uint(sm.khi[n][kk + t4]);
                uint32_t b1h = __float_as_uint(sm.khi[n][kk + t4 + 4]);
                uint32_t b0l = __float_as_uint(sm.klo[n][kk + t4]);
                uint32_t b1l = __float_as_uint(sm.klo[n][kk + t4 + 4]);
                MMA_TF32(s[nt], a0h, a1h, a2h, a3h, b0h, b1h);
                MMA_TF32(s[nt], a0h, a1h, a2h, a3h, b0l, b1l);
                MMA_TF32(s[nt], a0l, a1l, a2l, a3l, b0h, b1h);
            }
        }

        #pragma unroll
        for (int nt = 0; nt < 8; nt++) {
            s[nt][0] = __expf(s[nt][0]);
            s[nt][1] = __expf(s[nt][1]);
            s[nt][2] = __expf(s[nt][2]);
            s[nt][3] = __expf(s[nt][3]);
            l0 += s[nt][0] + s[nt][1];
            l1 += s[nt][2] + s[nt][3];
        }

        #pragma unroll
        for (int kg = 0; kg < 4; kg++) {
            uint32_t a0 = packh2(s[2*kg][0],   s[2*kg][1]);
            uint32_t a1 = packh2(s[2*kg][2],   s[2*kg][3]);
            uint32_t a2 = packh2(s[2*kg+1][0], s[2*kg+1][1]);
            uint32_t a3 = packh2(s[2*kg+1][2], s[2*kg+1][3]);
            #pragma unroll
            for (int dt = 0; dt < 8; dt++) {
                uint32_t b0 = *(const uint32_t*)&sm.vh[dt * 8 + grp][kg * 16 + 2 * t4];
                uint32_t b1 = *(const uint32_t*)&sm.vh[dt * 8 + grp][kg * 16 + 2 * t4 + 8];
                MMA_F16(o[dt], a0, a1, a2, a3, b0, b1);
            }
        }
    }

    l0 += __shfl_xor_sync(0xffffffffu, l0, 1);
    l0 += __shfl_xor_sync(0xffffffffu, l0, 2);
    l1 += __shfl_xor_sync(0xffffffffu, l1, 1);
    l1 += __shfl_xor_sync(0xffffffffu, l1, 2);

    const int rg0 = blockIdx.x * 128 + warp * 16 + grp;
    if (PARTIAL) {
        long long ob = (long long)(blockIdx.y * BHD + bh) * rows * 64;
        #pragma unroll
        for (int dt = 0; dt < 8; dt++) {
            int d = dt * 8 + 2 * t4;
            float2 w0; w0.x = o[dt][0]; w0.y = o[dt][1];
            float2 w1; w1.x = o[dt][2]; w1.y = o[dt][3];
            *(float2*)&Og[ob + (long long)rg0 * 64 + d] = w0;
            *(float2*)&Og[ob + (long long)(rg0 + 8) * 64 + d] = w1;
        }
        if (t4 == 0) {
            Lg[(long long)(blockIdx.y * BHD + bh) * rows + rg0]     = l0;
            Lg[(long long)(blockIdx.y * BHD + bh) * rows + rg0 + 8] = l1;
        }
    } else {
        float i0 = 1.f / l0, i1 = 1.f / l1;
        long long ob = (long long)bh * rows * 64;
        #pragma unroll
        for (int dt = 0; dt < 8; dt++) {
            int d = dt * 8 + 2 * t4;
            float2 w0; w0.x = o[dt][0] * i0; w0.y = o[dt][1] * i0;
            float2 w1; w1.x = o[dt][2] * i1; w1.y = o[dt][3] * i1;
            *(float2*)&Og[ob + (long long)rg0 * 64 + d] = w0;
            *(float2*)&Og[ob + (long long)(rg0 + 8) * 64 + d] = w1;
        }
    }
}

// ---------------- flash_p: P = exp(q @ kl^T) (unnormalized) + row sums ----
struct PSmem {
    float qhi[128][68];
    float qlo[128][68];
    float khi[64][68];
    float klo[64][68];
};

__global__ void __launch_bounds__(256, 1)
flash_p(const float* __restrict__ Qg, const float* __restrict__ Kg,
        __half* __restrict__ P, float* __restrict__ Lg)
{
    extern __shared__ char dynsm[];
    PSmem& sm = *reinterpret_cast<PSmem*>(dynsm);

    const int tid  = threadIdx.x;
    const int warp = tid >> 5;
    const int lane = tid & 31;
    const int grp  = lane >> 2;
    const int t4   = lane & 3;
    const int bh   = blockIdx.z;

    const long long qbase = ((long long)bh * NSEQ + blockIdx.x * 128) * 64;
    const long long kbase = (long long)bh * NL * 64;

    #pragma unroll
    for (int j = 0; j < 8; j++) {
        int e = tid + 256 * j;
        int r = e >> 4, c4 = (e & 15) * 4;
        float4 qv = *(const float4*)&Qg[qbase + (long long)r * 64 + c4];
        uint32_t hi, lo;
        split_tf32(qv.x, hi, lo); sm.qhi[r][c4+0] = __uint_as_float(hi); sm.qlo[r][c4+0] = __uint_as_float(lo);
        split_tf32(qv.y, hi, lo); sm.qhi[r][c4+1] = __uint_as_float(hi); sm.qlo[r][c4+1] = __uint_as_float(lo);
        split_tf32(qv.z, hi, lo); sm.qhi[r][c4+2] = __uint_as_float(hi); sm.qlo[r][c4+2] = __uint_as_float(lo);
        split_tf32(qv.w, hi, lo); sm.qhi[r][c4+3] = __uint_as_float(hi); sm.qlo[r][c4+3] = __uint_as_float(lo);
    }

    float l0 = 0.f, l1 = 0.f;
    const int r0s = warp * 16 + grp;
    const int rg0 = blockIdx.x * 128 + warp * 16 + grp;

    for (int sub = 0; sub < 4; sub++) {
        __syncthreads();
        #pragma unroll
        for (int j = 0; j < 4; j++) {
            int e = tid + 256 * j;
            int r = e >> 4, c4 = (e & 15) * 4;
            float4 kv = *(const float4*)&Kg[kbase + (long long)(sub * 64 + r) * 64 + c4];
            uint32_t hi, lo;
            split_tf32(kv.x, hi, lo); sm.khi[r][c4+0] = __uint_as_float(hi); sm.klo[r][c4+0] = __uint_as_float(lo);
            split_tf32(kv.y, hi, lo); sm.khi[r][c4+1] = __uint_as_float(hi); sm.klo[r][c4+1] = __uint_as_float(lo);
            split_tf32(kv.z, hi, lo); sm.khi[r][c4+2] = __uint_as_float(hi); sm.klo[r][c4+2] = __uint_as_float(lo);
            split_tf32(kv.w, hi, lo); sm.khi[r][c4+3] = __uint_as_float(hi); sm.klo[r][c4+3] = __uint_as_float(lo);
        }
        __syncthreads();

        float s[8][4];
        #pragma unroll
        for (int i = 0; i < 8; i++)
            #pragma unroll
            for (int j = 0; j < 4; j++) s[i][j] = 0.f;

        #pragma unroll
        for (int ks = 0; ks < 8; ks++) {
            int kk = ks * 8;
            uint32_t a0h = __float_as_uint(sm.qhi[r0s][kk + t4]);
            uint32_t a1h = __float_as_uint(sm.qhi[r0s + 8][kk + t4]);
            uint32_t a2h = __float_as_uint(sm.qhi[r0s][kk + t4 + 4]);
            uint32_t a3h = __float_as_uint(sm.qhi[r0s + 8][kk + t4 + 4]);
            uint32_t a0l = __float_as_uint(sm.qlo[r0s][kk + t4]);
            uint32_t a1l = __float_as_uint(sm.qlo[r0s + 8][kk + t4]);
            uint32_t a2l = __float_as_uint(sm.qlo[r0s][kk + t4 + 4]);
            uint32_t a3l = __float_as_uint(sm.qlo[r0s + 8][kk + t4 + 4]);
            #pragma unroll
            for (int nt = 0; nt < 8; nt++) {
                int n = nt * 8 + grp;
                uint32_t b0h = __float_as_uint(sm.khi[n][kk + t4]);
                uint32_t b1h = __float_as_uint(sm.khi[n][kk + t4 + 4]);
                uint32_t b0l = __float_as_uint(sm.klo[n][kk + t4]);
                uint32_t b1l = __float_as_uint(sm.klo[n][kk + t4 + 4]);
                MMA_TF32(s[nt], a0h, a1h, a2h, a3h, b0h, b1h);
                MMA_TF32(s[nt], a0h, a1h, a2h, a3h, b0l, b1l);
                MMA_TF32(s[nt], a0l, a1l, a2l, a3l, b0h, b1h);
            }
        }

        long long pbase = ((long long)bh * NSEQ) * NL;
        #pragma unroll
        for (int nt = 0; nt < 8; nt++) {
            s[nt][0] = __expf(s[nt][0]);
            s[nt][1] = __expf(s[nt][1]);
            s[nt][2] = __expf(s[nt][2]);
            s[nt][3] = __expf(s[nt][3]);
            l0 += s[nt][0] + s[nt][1];
            l1 += s[nt][2] + s[nt][3];
            int c = sub * 64 + nt * 8 + t4 * 2;
            __half2 p0 = __floats2half2_rn(s[nt][0], s[nt][1]);
            __half2 p1 = __floats2half2_rn(s[nt][2], s[nt][3]);
            *(__half2*)&P[pbase + (long long)rg0 * NL + c] = p0;
            *(__half2*)&P[pbase + (long long)(rg0 + 8) * NL + c] = p1;
        }
    }

    l0 += __shfl_xor_sync(0xffffffffu, l0, 1);
    l0 += __shfl_xor_sync(0xffffffffu, l0, 2);
    l1 += __shfl_xor_sync(0xffffffffu, l1, 1);
    l1 += __shfl_xor_sync(0xffffffffu, l1, 2);
    if (t4 == 0) {
        Lg[(long long)bh * NSEQ + rg0]     = l0;
        Lg[(long long)bh * NSEQ + rg0 + 8] = l1;
    }
}

// combine 4 split-KV partials -> a3v row-major splits, scaled S_PINV
__global__ void combine4(const float* __restrict__ P, const float* __restrict__ L,
                         __half* __restrict__ Rh, __half* __restrict__ Rl)
{
    int idx = blockIdx.x * 256 + threadIdx.x;
    int bhr = idx >> 6;
    const int SL = BHD * NL;
    const int SD = BHD * NL * DH;
    float l = L[bhr] + L[SL + bhr] + L[2 * SL + bhr] + L[3 * SL + bhr];
    float val = (P[idx] + P[SD + idx] + P[2 * SD + idx] + P[3 * SD + idx]) / l;
    __half h, lo2;
    split_h(val * S_PINV, h, lo2);
    Rh[idx] = h; Rl[idx] = lo2;
}

// ---------------- split kernel ----------------
__global__ void split_rm(const float* __restrict__ src, __half* __restrict__ hi,
                         __half* __restrict__ lo, float S, long long n)
{
    long long idx = (long long)blockIdx.x * 256 + threadIdx.x;
    if (idx >= n) return;
    __half h, l;
    split_h(src[idx] * S, h, l);
    hi[idx] = h; lo[idx] = l;
}

// ---------------- landmark means ----------------
__global__ void landmark_mean(const float* __restrict__ src, float* __restrict__ dst)
{
    long long idx = (long long)blockIdx.x * 256 + threadIdx.x;
    int d  = idx & 63;
    int mm = (int)((idx >> 6) & 255);
    long long bh = idx >> 14;
    const float* base = src + ((bh * NSEQ) + (long long)mm * LGRP) * DH + d;
    float s = 0.f;
    #pragma unroll
    for (int t = 0; t < LGRP; t++) s += base[(long long)t * DH];
    dst[idx] = s * (1.0f / LGRP);
}

// ---------------- row softmax (a2), emits scaled splits ----------------
__global__ void softmax_rows(float* __restrict__ data, int L,
                             __half* __restrict__ sh, __half* __restrict__ sl)
{
    long long row = blockIdx.x;
    float* p = data + row * (long long)L;
    __shared__ float red[256];
    int t = threadIdx.x;

    float mx = -INFINITY;
    for (int i = t; i < L; i += 256) mx = fmaxf(mx, p[i]);
    red[t] = mx; __syncthreads();
    for (int s = 128; s > 0; s >>= 1) { if (t < s) red[t] = fmaxf(red[t], red[t + s]); __syncthreads(); }
    mx = red[0]; __syncthreads();

    float sm = 0.f;
    for (int i = t; i < L; i += 256) { float e = expf(p[i] - mx); p[i] = e; sm += e; }
    red[t] = sm; __syncthreads();
    for (int s = 128; s > 0; s >>= 1) { if (t < s) red[t] += red[t + s]; __syncthreads(); }
    float inv = 1.f / red[0];
    for (int i = t; i < L; i += 256) {
        float val = p[i] * inv;
        p[i] = val;
        __half h, l;
        split_h(val * S_PINV, h, l);
        sh[row * L + i] = h;
        sl[row * L + i] = l;
    }
}

// ---------------- pinv init scalars ----------------
// Rows of softmaxed a2 sum to exactly 1 => row-sum max = 1 identically.
__global__ void scal_init(float* scal) { scal[0] = 1.0f; scal[1] = 0.f; }

__global__ void colsum_max(const float* __restrict__ a, float* scal)
{
    int j = blockIdx.x, bh = blockIdx.y, t = threadIdx.x;
    __shared__ float red[256];
    red[t] = a[(((long long)bh * NL) + t) * NL + j];
    __syncthreads();
    for (int s = 128; s > 0; s >>= 1) { if (t < s) red[t] += red[t + s]; __syncthreads(); }
    if (t == 0) atomicMax((int*)(scal + 1), __float_as_int(red[0]));
}

// z0 = a2^T / (col*row): row-major splits, scaled
__global__ void zinit(const float* __restrict__ a,
                      __half* __restrict__ zh, __half* __restrict__ zl,
                      const float* __restrict__ scal)
{
    long long idx = (long long)blockIdx.x * 256 + threadIdx.x;
    float inv = S_PINV / (scal[0] * scal[1]);
    int j = (int)(idx & 255);
    int i = (int)((idx >> 8) & 255);
    long long bh = idx >> 16;
    float val = a[(bh << 16) + ((long long)j << 8) + i] * inv;
    __half h, l;
    split_h(val, h, l);
    zh[idx] = h; zl[idx] = l;
}

// ---------------- tail: oh/L + conv(v) -> x2 splits ----------------
__global__ void conv_add_norm(const float* __restrict__ oh, const float* __restrict__ Lr,
                              const float* __restrict__ v, const float* __restrict__ ker,
                              __half* __restrict__ x2h, __half* __restrict__ x2l)
{
    long long idx = (long long)blockIdx.x * 256 + threadIdx.x;
    int d  = (int)(idx & 63);
    int h  = (int)((idx >> 6) & 7);
    int nn = (int)((idx >> 9) & 4095);
    int b  = (int)(idx >> 21);
    long long bh = (long long)b * HEADS + h;
    const float* vb = v + (bh * NSEQ) * DH + d;
    float s = 0.f;
    #pragma unroll
    for (int t = 0; t < CONV_TAPS; t++) {
        int pos = nn + t - CONV_PAD;
        if (pos >= 0 && pos < NSEQ) s += vb[(long long)pos * DH] * ker[h * CONV_TAPS + t];
    }
    float val = oh[(bh * NSEQ + nn) * DH + d] / Lr[bh * NSEQ + nn] + s;
    __half hh, ll;
    split_h(val, hh, ll);
    x2h[idx] = hh; x2l[idx] = ll;
}

// ---------------- host ----------------
template<int BN, int PREC>
static void launch_h3(const __half* Ah, const __half* Al, const __half* Bh, const __half* Bl,
                      int M, int N, int K, long long sA, long long sB, int batch,
                      float scale, float outS,
                      float* Cf, long long sC, const float* bias,
                      __half* R1h, __half* R1l, long long sR1,
                      __half* R2h, __half* R2l, long long sR2, float dv,
                      int qkv, float qscale, float* qp, float* kp, float* vp,
                      cudaStream_t st = 0)
{
    size_t smem = (size_t)((PREC == 3 ? 2 : 1) * 3 * (128 * 40 + 32 * (BN + 8))) * 2;
    cudaFuncSetAttribute(gemm_h3<BN, PREC>, cudaFuncAttributeMaxDynamicSharedMemorySize, (int)smem);
    dim3 grid(N / BN, M / 128, batch);
    gemm_h3<BN, PREC><<<grid, 512, smem, st>>>(Ah, Al, Bh, Bl, M, N, K, sA, sB,
                                               scale, outS, Cf, sC, bias,
                                               R1h, R1l, sR1, R2h, R2l, sR2, dv,
                                               qkv, qscale, qp, kp, vp);
}

extern "C" void kernel_launch(void* const* d_in, const int* in_sizes, int n_in,
                              void* d_out, int out_size)
{
    const float* x      = (const float*)d_in[0];
    const float* w_qkv  = (const float*)d_in[1];
    const float* w_out  = (const float*)d_in[2];
    const float* b_out  = (const float*)d_in[3];
    const float* res_k  = (const float*)d_in[4];
    float* out = (float*)d_out;

    float *q, *k, *v, *ql, *kl, *a2, *part, *lpart, *oh, *Lf, *scal;
    cudaGetSymbolAddress((void**)&q,     g_q);
    cudaGetSymbolAddress((void**)&k,     g_k);
    cudaGetSymbolAddress((void**)&v,     g_v);
    cudaGetSymbolAddress((void**)&ql,    g_ql);
    cudaGetSymbolAddress((void**)&kl,    g_kl);
    cudaGetSymbolAddress((void**)&a2,    g_a2);
    cudaGetSymbolAddress((void**)&part,  g_part);
    cudaGetSymbolAddress((void**)&lpart, g_lpart);
    cudaGetSymbolAddress((void**)&oh,    g_oh);
    cudaGetSymbolAddress((void**)&Lf,    g_Lf);
    cudaGetSymbolAddress((void**)&scal,  g_scal);

    __half *xh, *xl, *wqh, *wql, *woh, *wol, *x2h, *x2l, *a2h, *a2l;
    __half *zAh, *zAl, *zBh, *zBl, *xzh, *xzl, *T1h, *T1l, *T2h, *T2l;
    __half *a3vh, *a3vl, *za3vh, *za3vl, *Pm;
    cudaGetSymbolAddress((void**)&xh,    g_xh);
    cudaGetSymbolAddress((void**)&xl,    g_xl);
    cudaGetSymbolAddress((void**)&wqh,   g_wqh);
    cudaGetSymbolAddress((void**)&wql,   g_wql);
    cudaGetSymbolAddress((void**)&woh,   g_woh);
    cudaGetSymbolAddress((void**)&wol,   g_wol);
    cudaGetSymbolAddress((void**)&x2h,   g_x2h);
    cudaGetSymbolAddress((void**)&x2l,   g_x2l);
    cudaGetSymbolAddress((void**)&a2h,   g_a2h);
    cudaGetSymbolAddress((void**)&a2l,   g_a2l);
    cudaGetSymbolAddress((void**)&zAh,   g_zAh);
    cudaGetSymbolAddress((void**)&zAl,   g_zAl);
    cudaGetSymbolAddress((void**)&zBh,   g_zBh);
    cudaGetSymbolAddress((void**)&zBl,   g_zBl);
    cudaGetSymbolAddress((void**)&xzh,   g_xzh);
    cudaGetSymbolAddress((void**)&xzl,   g_xzl);
    cudaGetSymbolAddress((void**)&T1h,   g_T1h);
    cudaGetSymbolAddress((void**)&T1l,   g_T1l);
    cudaGetSymbolAddress((void**)&T2h,   g_T2h);
    cudaGetSymbolAddress((void**)&T2l,   g_T2l);
    cudaGetSymbolAddress((void**)&a3vh,  g_a3vh);
    cudaGetSymbolAddress((void**)&a3vl,  g_a3vl);
    cudaGetSymbolAddress((void**)&za3vh, g_za3vh);
    cudaGetSymbolAddress((void**)&za3vl, g_za3vl);
    cudaGetSymbolAddress((void**)&Pm,    g_P);

    cudaFuncSetAttribute(flash_pv<1>, cudaFuncAttributeMaxDynamicSharedMemorySize, (int)sizeof(FlashSmem));
    cudaFuncSetAttribute(flash_p, cudaFuncAttributeMaxDynamicSharedMemorySize, (int)sizeof(PSmem));

    const long long sb = (long long)NL * NL;
    const long long svd = (long long)NL * DH;

    cudaStream_t s2;
    cudaStreamCreateWithFlags(&s2, cudaStreamNonBlocking);
    cudaEvent_t evFork, evJoin;
    cudaEventCreateWithFlags(&evFork, cudaEventDisableTiming);
    cudaEventCreateWithFlags(&evJoin, cudaEventDisableTiming);

    // 0) operand splits
    {
        long long n = (long long)BATCH * NSEQ * DIM;
        split_rm<<<(unsigned)((n + 255) / 256), 256>>>(x, xh, xl, 1.0f, n);
        long long nw = (long long)DIM * 3 * DIM;
        split_rm<<<(unsigned)((nw + 255) / 256), 256>>>(w_qkv, wqh, wql, S_W, nw);
        long long nw2 = (long long)DIM * DIM;
        split_rm<<<(unsigned)((nw2 + 255) / 256), 256>>>(w_out, woh, wol, S_W, nw2);
    }

    // 1) qkv projection (fp16x3, 512-thread GEMM) + scatter
    launch_h3<128, 3>(xh, xl, wqh, wql, BATCH * NSEQ, 3 * DIM, DIM, 0, 0, 1,
                      1.0f / S_W, 1.0f,
                      nullptr, 0, nullptr, nullptr, nullptr, 0,
                      nullptr, nullptr, 0, 0.f, 1, 0.125f, q, k, v);

    // 2) landmarks
    {
        long long n = (long long)BHD * NL * DH;
        landmark_mean<<<(unsigned)(n / 256), 256>>>(q, ql);
        landmark_mean<<<(unsigned)(n / 256), 256>>>(k, kl);
    }

    // ---- fork on s2: flash1 (a3v) then flash_p (exp scores of attn1),
    //      both independent of the pinv chain on the main stream ----
    cudaEventRecord(evFork, 0);
    cudaStreamWaitEvent(s2, evFork, 0);
    {
        dim3 grid(NL / 128, 4, BHD);
        flash_pv<1><<<grid, 256, sizeof(FlashSmem), s2>>>(ql, k, v, part, lpart, NL, NSEQ, NSEQ / 4);
        combine4<<<(BHD * NL * DH) / 256, 256, 0, s2>>>(part, lpart, a3vh, a3vl);
        dim3 pgrid(NSEQ / 128, 1, BHD);
        flash_p<<<pgrid, 256, sizeof(PSmem), s2>>>(q, kl, Pm, Lf);
    }
    cudaEventRecord(evJoin, s2);

    // 3) a2 = ql @ kl^T (tf32x3, fp32) + softmax (emits splits)
    {
        size_t smem = (size_t)(3 * 128 * 20 + 3 * 128 * 20) * 4;
        cudaFuncSetAttribute(gemm_tf32<128, 1>, cudaFuncAttributeMaxDynamicSharedMemorySize, (int)smem);
        dim3 grid(NL / 128, NL / 128, BHD);
        gemm_tf32<128, 1><<<grid, 256, smem>>>(ql, kl, a2, NL, NL, DH, svd, svd, sb);
    }
    softmax_rows<<<BHD * NL, 256>>>(a2, NL, a2h, a2l);

    // 4) pinv init
    scal_init<<<1, 1>>>(scal);
    {
        dim3 g(NL, BHD);
        colsum_max<<<g, 256>>>(a2, scal);
    }
    zinit<<<(unsigned)((long long)BHD * NL * NL / 256), 256>>>(a2, zAh, zAl, scal);

    // 5) Newton iterations (launch-based). 4 cheap + 1 full.
    __half *zch = zAh, *zcl = zAl, *znh = zBh, *znl = zBl;
    const float sa2 = 1.0f / (S_PINV * S_PINV);
    const int NITER = 5;
    for (int it = 0; it < NITER; it++) {
        bool cheap = (it < NITER - 1);
        #define PINV_STEP(PREC_) \
            launch_h3<128, PREC_>(a2h, a2l, zch, zcl, NL, NL, NL, sb, sb, BHD, \
                           sa2, S_PINV, nullptr, 0, nullptr, \
                           xzh, xzl, sb, T1h, T1l, sb, 7.0f, \
                           0, 0.f, nullptr, nullptr, nullptr); \
            launch_h3<128, PREC_>(xzh, xzl, T1h, T1l, NL, NL, NL, sb, sb, BHD, \
                           sa2, S_PINV, nullptr, 0, nullptr, \
                           nullptr, nullptr, 0, T2h, T2l, sb, 15.0f, \
                           0, 0.f, nullptr, nullptr, nullptr); \
            launch_h3<128, PREC_>(xzh, xzl, T2h, T2l, NL, NL, NL, sb, sb, BHD, \
                           sa2, S_PINV, nullptr, 0, nullptr, \
                           nullptr, nullptr, 0, T1h, T1l, sb, 13.0f, \
                           0, 0.f, nullptr, nullptr, nullptr); \
            launch_h3<128, PREC_>(zch, zcl, T1h, T1l, NL, NL, NL, sb, sb, BHD, \
                           0.25f * sa2, S_PINV, nullptr, 0, nullptr, \
                           znh, znl, sb, nullptr, nullptr, 0, 0.f, \
                           0, 0.f, nullptr, nullptr, nullptr);
        if (cheap) { PINV_STEP(1) } else { PINV_STEP(3) }
        #undef PINV_STEP
        __half* t;
        t = zch; zch = znh; znh = t;
        t = zcl; zcl = znl; znl = t;
    }

    // ---- join: tail needs a3v, P, L from s2 ----
    cudaStreamWaitEvent(0, evJoin, 0);

    // 7) za3v = z @ a3v (fp16x3) -> fp16 splits (same quantization the old
    //    flash2 applied when converting za3v to fp16 in smem)
    launch_h3<64, 3>(zch, zcl, a3vh, a3vl, NL, DH, NL, sb, svd, BHD,
                     sa2, 1.0f, nullptr, 0, nullptr,
                     za3vh, za3vl, svd, nullptr, nullptr, 0, 0.f,
                     0, 0.f, nullptr, nullptr, nullptr);

    // 8) oh_unnorm = P @ za3v (1-pass fp16: P and za3v-hi, matching old PV)
    launch_h3<64, 1>(Pm, Pm, za3vh, za3vh, NSEQ, DH, NL,
                     (long long)NSEQ * NL, svd, BHD,
                     1.0f, 1.0f, oh, (long long)NSEQ * DH, nullptr,
                     nullptr, nullptr, 0, nullptr, nullptr, 0, 0.f,
                     0, 0.f, nullptr, nullptr, nullptr);

    // 9) tail: oh/L + conv(v) -> x2 splits
    conv_add_norm<<<(unsigned)((long long)BATCH * NSEQ * HEADS * DH / 256), 256>>>(oh, Lf, v, res_k, x2h, x2l);

    // 10) out = x2 @ w_out + b_out (fp16x3)
    launch_h3<128, 3>(x2h, x2l, woh, wol, BATCH * NSEQ, DIM, DIM, 0, 0, 1,
                      1.0f / S_W, 1.0f,
                      out, 0, b_out, nullptr, nullptr, 0,
                      nullptr, nullptr, 0, 0.f, 0, 0.f, nullptr, nullptr, nullptr);

    cudaEventDestroy(evFork);
    cudaEventDestroy(evJoin);
    cudaStreamDestroy(s2);
}

// round 15
// speedup vs baseline: 1.0938x; 1.0207x over previous
#include <cuda_runtime.h>
#include <cuda_fp16.h>
#include <math.h>
#include <stdint.h>

// ---------------- problem constants ----------------
#define BATCH 4
#define HEADS 8
#define NSEQ  4096
#define DH    64
#define DIM   512
#define NL    256
#define LGRP  16
#define BHD   (BATCH*HEADS)
#define CONV_TAPS 33
#define CONV_PAD 16

#define S_PINV 64.0f
#define S_W    256.0f

// ---------------- scratch (fp32) ----------------
__device__ float g_q [(size_t)BHD*NSEQ*DH];
__device__ float g_k [(size_t)BHD*NSEQ*DH];
__device__ float g_v [(size_t)BHD*NSEQ*DH];
__device__ float g_ql[(size_t)BHD*NL*DH];
__device__ float g_kl[(size_t)BHD*NL*DH];
__device__ float g_a2[(size_t)BHD*NL*NL];
__device__ float g_part[(size_t)4*BHD*NL*DH];
__device__ float g_lpart[(size_t)4*BHD*NL];
__device__ float g_oh [(size_t)BHD*NSEQ*DH];
__device__ float g_Lf [(size_t)BHD*NSEQ];
__device__ float g_scal[2];

// ---------------- scratch (half splits; all row-major) ----------------
__device__ __half g_xh [(size_t)BATCH*NSEQ*DIM];
__device__ __half g_xl [(size_t)BATCH*NSEQ*DIM];
__device__ __half g_wqh[(size_t)DIM*3*DIM];
__device__ __half g_wql[(size_t)DIM*3*DIM];
__device__ __half g_woh[(size_t)DIM*DIM];
__device__ __half g_wol[(size_t)DIM*DIM];
__device__ __half g_x2h[(size_t)BATCH*NSEQ*DIM];
__device__ __half g_x2l[(size_t)BATCH*NSEQ*DIM];
__device__ __half g_a2h[(size_t)BHD*NL*NL];
__device__ __half g_a2l[(size_t)BHD*NL*NL];
__device__ __half g_zAh[(size_t)BHD*NL*NL];
__device__ __half g_zAl[(size_t)BHD*NL*NL];
__device__ __half g_zBh[(size_t)BHD*NL*NL];
__device__ __half g_zBl[(size_t)BHD*NL*NL];
__device__ __half g_xzh[(size_t)BHD*NL*NL];
__device__ __half g_xzl[(size_t)BHD*NL*NL];
__device__ __half g_T1h[(size_t)BHD*NL*NL];
__device__ __half g_T1l[(size_t)BHD*NL*NL];
__device__ __half g_T2h[(size_t)BHD*NL*NL];
__device__ __half g_T2l[(size_t)BHD*NL*NL];
__device__ __half g_a3vh[(size_t)BHD*NL*DH];
__device__ __half g_a3vl[(size_t)BHD*NL*DH];
__device__ __half g_za3vh[(size_t)BHD*NL*DH];
__device__ __half g_za3vl[(size_t)BHD*NL*DH];
__device__ __half g_P  [(size_t)BHD*NSEQ*NL];   // unnormalized exp scores

// ---------------- helpers ----------------
__device__ __forceinline__ void split_tf32(float v, uint32_t &hi, uint32_t &lo) {
    asm("cvt.rna.tf32.f32 %0, %1;" : "=r"(hi) : "f"(v));
    float r = v - __uint_as_float(hi);
    asm("cvt.rna.tf32.f32 %0, %1;" : "=r"(lo) : "f"(r));
}

__device__ __forceinline__ void split_h(float v, __half &hi, __half &lo) {
    hi = __float2half_rn(v);
    lo = __float2half_rn(v - __half2float(hi));
}

#define MMA_TF32(D, A0,A1,A2,A3, B0,B1) \
    asm volatile("mma.sync.aligned.m16n8k8.row.col.f32.tf32.tf32.f32 " \
                 "{%0,%1,%2,%3},{%4,%5,%6,%7},{%8,%9},{%0,%1,%2,%3};" \
                 : "+f"((D)[0]), "+f"((D)[1]), "+f"((D)[2]), "+f"((D)[3]) \
                 : "r"(A0), "r"(A1), "r"(A2), "r"(A3), "r"(B0), "r"(B1))

#define MMA_F16(D, a0,a1,a2,a3, b0,b1) \
    asm volatile("mma.sync.aligned.m16n8k16.row.col.f32.f16.f16.f32 " \
                 "{%0,%1,%2,%3},{%4,%5,%6,%7},{%8,%9},{%0,%1,%2,%3};" \
                 : "+f"((D)[0]), "+f"((D)[1]), "+f"((D)[2]), "+f"((D)[3]) \
                 : "r"(a0), "r"(a1), "r"(a2), "r"(a3), "r"(b0), "r"(b1))

__device__ __forceinline__ void cp16(void* smem, const void* g) {
    uint32_t sa = (uint32_t)__cvta_generic_to_shared(smem);
    asm volatile("cp.async.ca.shared.global [%0], [%1], 16;" :: "r"(sa), "l"(g));
}
#define CP_COMMIT asm volatile("cp.async.commit_group;")
#define CP_WAIT0  asm volatile("cp.async.wait_group 0;")
#define CP_WAIT1  asm volatile("cp.async.wait_group 1;")

__device__ __forceinline__ uint32_t packh2(float a, float b) {
    __half2 h = __floats2half2_rn(a, b);
    return *reinterpret_cast<uint32_t*>(&h);
}

__device__ __forceinline__ void ldsm4(uint32_t* r, const __half* p) {
    uint32_t a = (uint32_t)__cvta_generic_to_shared(p);
    asm volatile("ldmatrix.sync.aligned.m8n8.x4.shared.b16 {%0,%1,%2,%3}, [%4];"
                 : "=r"(r[0]), "=r"(r[1]), "=r"(r[2]), "=r"(r[3]) : "r"(a));
}
__device__ __forceinline__ void ldsm4t(uint32_t* r, const __half* p) {
    uint32_t a = (uint32_t)__cvta_generic_to_shared(p);
    asm volatile("ldmatrix.sync.aligned.m8n8.x4.trans.shared.b16 {%0,%1,%2,%3}, [%4];"
                 : "=r"(r[0]), "=r"(r[1]), "=r"(r[2]), "=r"(r[3]) : "r"(a));
}

// ================= fp16 batched GEMM — 512 threads, warp tile 32x32 =====
template<int BN, int PREC>
__global__ void __launch_bounds__(512, 1)
gemm_h3(const __half* __restrict__ Ahg, const __half* __restrict__ Alg,
        const __half* __restrict__ Bhg, const __half* __restrict__ Blg,
        int M, int N, int K, long long sA, long long sB,
        float scale, float outS,
        float* __restrict__ Cf, long long sC, const float* __restrict__ bias,
        __half* __restrict__ R1h, __half* __restrict__ R1l, long long sR1,
        __half* __restrict__ R2h, __half* __restrict__ R2l, long long sR2, float dv,
        int qkv, float qscale,
        float* __restrict__ qp, float* __restrict__ kp, float* __restrict__ vp)
{
    constexpr int NT  = BN / 32;
    constexpr int ALD = 40;
    constexpr int BLD = BN + 8;
    constexpr int ASZ = 128 * ALD;
    constexpr int BSZ = 32 * BLD;

    const int zb = blockIdx.z;
    const __half* Ah_g = Ahg + (long long)zb * sA;
    const __half* Al_g = Alg + (long long)zb * sA;
    const __half* Bh_g = Bhg + (long long)zb * sB;
    const __half* Bl_g = Blg + (long long)zb * sB;
    if (Cf)  Cf  += (long long)zb * sC;
    if (R1h) { R1h += (long long)zb * sR1; R1l += (long long)zb * sR1; }
    if (R2h) { R2h += (long long)zb * sR2; R2l += (long long)zb * sR2; }

    extern __shared__ __half hsm[];
    __half* Ash = hsm;
    __half* Asl = Ash + 3 * ASZ;
    __half* Bsh = (PREC == 3) ? (Asl + 3 * ASZ) : (Ash + 3 * ASZ);
    __half* Bsl = Bsh + 3 * BSZ;

    const int brow = blockIdx.y * 128;
    const int bcol = blockIdx.x * BN;

    const int tid  = threadIdx.x;
    const int warp = tid >> 5;
    const int lane = tid & 31;
    const int wm   = warp & 3;
    const int wn   = warp >> 2;
    const int grp  = lane >> 2;
    const int t4   = lane & 3;
    const int r8   = lane & 7;
    const int quad = lane >> 3;

    const int nk = K / 32;

    auto load_stage = [&](int s, int kt) {
        int k0 = kt * 32;
        {
            int row = tid >> 2, seg = (tid & 3) * 8;
            cp16(&Ash[(s * 128 + row) * ALD + seg], &Ah_g[(long long)(brow + row) * K + k0 + seg]);
            if (PREC == 3)
                cp16(&Asl[(s * 128 + row) * ALD + seg], &Al_g[(long long)(brow + row) * K + k0 + seg]);
        }
        if (tid < BN * 4) {
            int row = tid / (BN / 8), seg = (tid % (BN / 8)) * 8;
            cp16(&Bsh[(s * 32 + row) * BLD + seg], &Bh_g[(long long)(k0 + row) * N + bcol + seg]);
            if (PREC == 3)
                cp16(&Bsl[(s * 32 + row) * BLD + seg], &Bl_g[(long long)(k0 + row) * N + bcol + seg]);
        }
    };

    float acc[2][NT][4];
    #pragma unroll
    for (int i = 0; i < 2; i++)
        #pragma unroll
        for (int j = 0; j < NT; j++)
            #pragma unroll
            for (int l = 0; l < 4; l++) acc[i][j][l] = 0.f;

    load_stage(0, 0); CP_COMMIT;
    load_stage(1, 1); CP_COMMIT;

    for (int kt = 0; kt < nk; kt++) {
        CP_WAIT1;
        __syncthreads();
        int buf = kt % 3;
        if (kt + 2 < nk) load_stage((kt + 2) % 3, kt + 2);
        CP_COMMIT;

        #pragma unroll
        for (int ss = 0; ss < 2; ss++) {
            int kb = ss * 16;
            uint32_t ah[2][4], al[2][4];
            #pragma unroll
            for (int mt = 0; mt < 2; mt++) {
                int m0 = wm * 32 + mt * 16;
                int off = (buf * 128 + m0 + r8 + (quad & 1) * 8) * ALD + kb + (quad >> 1) * 8;
                ldsm4(ah[mt], Ash + off);
                if (PREC == 3) ldsm4(al[mt], Asl + off);
            }
            uint32_t bh[NT][2], bl[NT][2];
            #pragma unroll
            for (int np = 0; np < NT / 2; np++) {
                int n0 = wn * (BN / 4) + np * 16;
                int off = (buf * 32 + kb + (quad & 1) * 8 + r8) * BLD + n0 + (quad >> 1) * 8;
                uint32_t tb[4];
                ldsm4t(tb, Bsh + off);
                bh[np * 2][0] = tb[0]; bh[np * 2][1] = tb[1];
                bh[np * 2 + 1][0] = tb[2]; bh[np * 2 + 1][1] = tb[3];
                if (PREC == 3) {
                    ldsm4t(tb, Bsl + off);
                    bl[np * 2][0] = tb[0]; bl[np * 2][1] = tb[1];
                    bl[np * 2 + 1][0] = tb[2]; bl[np * 2 + 1][1] = tb[3];
                }
            }
            #pragma unroll
            for (int mt = 0; mt < 2; mt++)
                #pragma unroll
                for (int nt = 0; nt < NT; nt++) {
                    MMA_F16(acc[mt][nt], ah[mt][0], ah[mt][1], ah[mt][2], ah[mt][3], bh[nt][0], bh[nt][1]);
                    if (PREC == 3) {
                        MMA_F16(acc[mt][nt], ah[mt][0], ah[mt][1], ah[mt][2], ah[mt][3], bl[nt][0], bl[nt][1]);
                        MMA_F16(acc[mt][nt], al[mt][0], al[mt][1], al[mt][2], al[mt][3], bh[nt][0], bh[nt][1]);
                    }
                }
        }
    }

    #pragma unroll
    for (int mt = 0; mt < 2; mt++) {
        int r0 = brow + wm * 32 + mt * 16 + grp;
        #pragma unroll
        for (int nt = 0; nt < NT; nt++) {
            int c = bcol + wn * (BN / 4) + nt * 8 + t4 * 2;
            #pragma unroll
            for (int half_i = 0; half_i < 2; half_i++) {
                int r = r0 + half_i * 8;
                float v0 = acc[mt][nt][half_i * 2 + 0] * scale;
                float v1 = acc[mt][nt][half_i * 2 + 1] * scale;
                if (qkv) {
                    int bidx = r >> 12, nn = r & 4095;
                    int part = c / DIM, rem = c % DIM;
                    int hh = rem >> 6, dd = rem & 63;
                    long long dst = ((((long long)bidx * HEADS + hh) * NSEQ) + nn) * DH + dd;
                    float2 val;
                    if (part == 0) { val.x = v0 * qscale; val.y = v1 * qscale; *(float2*)&qp[dst] = val; }
                    else if (part == 1) { val.x = v0; val.y = v1; *(float2*)&kp[dst] = val; }
                    else { val.x = v0; val.y = v1; *(float2*)&vp[dst] = val; }
                } else {
                    if (Cf) {
                        float b0 = bias ? bias[c] : 0.f;
                        float b1 = bias ? bias[c + 1] : 0.f;
                        float2 val; val.x = v0 + b0; val.y = v1 + b1;
                        *(float2*)&Cf[(long long)r * N + c] = val;
                    }
                    if (R1h) {
                        __half h0, l0, h1, l1;
                        split_h(v0 * outS, h0, l0);
                        split_h(v1 * outS, h1, l1);
                        __half2 hp; hp.x = h0; hp.y = h1;
                        __half2 lp; lp.x = l0; lp.y = l1;
                        *(__half2*)&R1h[(long long)r * N + c] = hp;
                        *(__half2*)&R1l[(long long)r * N + c] = lp;
                    }
                    if (R2h) {
                        float tv0 = (((r == c) ? dv : 0.f) - v0) * outS;
                        float tv1 = (((r == c + 1) ? dv : 0.f) - v1) * outS;
                        __half h0, l0, h1, l1;
                        split_h(tv0, h0, l0);
                        split_h(tv1, h1, l1);
                        __half2 hp; hp.x = h0; hp.y = h1;
                        __half2 lp; lp.x = l0; lp.y = l1;
                        *(__half2*)&R2h[(long long)r * N + c] = hp;
                        *(__half2*)&R2l[(long long)r * N + c] = lp;
                    }
                }
            }
        }
    }
}

// ================= 3xTF32 GEMM (a2 = ql @ kl^T only) =================
template<int BN, int TB>
__global__ void __launch_bounds__(256, 1)
gemm_tf32(const float* __restrict__ Ag, const float* __restrict__ Bg,
          float* __restrict__ Cg, int M, int N, int K,
          long long sA, long long sB, long long sC)
{
    constexpr int NT   = BN / 32;
    constexpr int BSZ  = TB ? BN * 20 : 16 * (BN + 8);
    constexpr int ASZ  = 128 * 20;

    extern __shared__ char dynsm[];
    float* As = (float*)dynsm;
    float* Bs = As + 3 * ASZ;

    const float* A = Ag + (long long)blockIdx.z * sA;
    const float* B = Bg + (long long)blockIdx.z * sB;
    float*       C = Cg + (long long)blockIdx.z * sC;

    const int brow = blockIdx.y * 128;
    const int bcol = blockIdx.x * BN;

    const int tid  = threadIdx.x;
    const int warp = tid >> 5;
    const int lane = tid & 31;
    const int wm   = warp & 1;
    const int wn   = warp >> 1;
    const int grp  = lane >> 2;
    const int t4   = lane & 3;

    const int a_row0 = tid >> 2;
    const int a_k    = (tid & 3) * 4;
    const int nk = K / 16;

    auto load_stage = [&](int s, int kt) {
        int k0 = kt * 16;
        cp16(&As[s * ASZ + a_row0 * 20 + a_k],        &A[(long long)(brow + a_row0) * K + k0 + a_k]);
        cp16(&As[s * ASZ + (a_row0 + 64) * 20 + a_k], &A[(long long)(brow + a_row0 + 64) * K + k0 + a_k]);
        #pragma unroll
        for (int j = 0; j < BN / 64; j++) {
            int i = tid + 256 * j;
            int n  = i >> 2;
            int kq = (i & 3) * 4;
            cp16(&Bs[s * BSZ + n * 20 + kq], &B[(long long)(bcol + n) * K + k0 + kq]);
        }
    };

    float acc[4][NT][4];
    #pragma unroll
    for (int i = 0; i < 4; i++)
        #pragma unroll
        for (int j = 0; j < NT; j++)
            #pragma unroll
            for (int l = 0; l < 4; l++) acc[i][j][l] = 0.f;

    load_stage(0, 0); CP_COMMIT;
    load_stage(1, 1); CP_COMMIT;

    for (int kt = 0; kt < nk; kt++) {
        CP_WAIT1;
        __syncthreads();
        int buf = kt % 3;
        if (kt + 2 < nk) load_stage((kt + 2) % 3, kt + 2);
        CP_COMMIT;

        #pragma unroll
        for (int ss = 0; ss < 2; ss++) {
            int kb = ss * 8;
            uint32_t ah[4][4], al[4][4];
            #pragma unroll
            for (int mt = 0; mt < 4; mt++) {
                int m = wm * 64 + mt * 16 + grp;
                float f0 = As[buf * ASZ + m * 20 + kb + t4];
                float f1 = As[buf * ASZ + (m + 8) * 20 + kb + t4];
                float f2 = As[buf * ASZ + m * 20 + kb + t4 + 4];
                float f3 = As[buf * ASZ + (m + 8) * 20 + kb + t4 + 4];
                split_tf32(f0, ah[mt][0], al[mt][0]);
                split_tf32(f1, ah[mt][1], al[mt][1]);
                split_tf32(f2, ah[mt][2], al[mt][2]);
                split_tf32(f3, ah[mt][3], al[mt][3]);
            }
            uint32_t bh[NT][2], bl[NT][2];
            #pragma unroll
            for (int nt = 0; nt < NT; nt++) {
                int n = wn * (BN / 4) + nt * 8 + grp;
                float b0 = Bs[buf * BSZ + n * 20 + kb + t4];
                float b1 = Bs[buf * BSZ + n * 20 + kb + t4 + 4];
                split_tf32(b0, bh[nt][0], bl[nt][0]);
                split_tf32(b1, bh[nt][1], bl[nt][1]);
            }
            #pragma unroll
            for (int mt = 0; mt < 4; mt++)
                #pragma unroll
                for (int nt = 0; nt < NT; nt++) {
                    MMA_TF32(acc[mt][nt], ah[mt][0], ah[mt][1], ah[mt][2], ah[mt][3], bh[nt][0], bh[nt][1]);
                    MMA_TF32(acc[mt][nt], ah[mt][0], ah[mt][1], ah[mt][2], ah[mt][3], bl[nt][0], bl[nt][1]);
                    MMA_TF32(acc[mt][nt], al[mt][0], al[mt][1], al[mt][2], al[mt][3], bh[nt][0], bh[nt][1]);
                }
        }
    }

    #pragma unroll
    for (int mt = 0; mt < 4; mt++) {
        int r0 = brow + wm * 64 + mt * 16 + grp;
        #pragma unroll
        for (int nt = 0; nt < NT; nt++) {
            int c = bcol + wn * (BN / 4) + nt * 8 + t4 * 2;
            #pragma unroll
            for (int half_i = 0; half_i < 2; half_i++) {
                int r = r0 + half_i * 8;
                float2 val;
                val.x = acc[mt][nt][half_i * 2 + 0];
                val.y = acc[mt][nt][half_i * 2 + 1];
                *(float2*)&C[(long long)r * N + c] = val;
            }
        }
    }
}

// ---------------- fused flash kernel (flash1 / a3v only) ----------------
struct FlashSmem {
    float  qhi[128][68];
    float  qlo[128][68];
    float  raw[2][2][64][64];
    float  khi[64][68];
    float  klo[64][68];
    __half vh[64][72];
};

template<int PARTIAL>
__global__ void __launch_bounds__(256, 1)
flash_pv(const float* __restrict__ Qg, const float* __restrict__ Kg,
         const float* __restrict__ Vg, float* __restrict__ Og,
         float* __restrict__ Lg, int rows, int keys, int kvchunk)
{
    extern __shared__ char dynsm[];
    FlashSmem& sm = *reinterpret_cast<FlashSmem*>(dynsm);

    const int tid  = threadIdx.x;
    const int warp = tid >> 5;
    const int lane = tid & 31;
    const int grp  = lane >> 2;
    const int t4   = lane & 3;
    const int bh   = blockIdx.z;

    const long long qbase = ((long long)bh * rows + blockIdx.x * 128) * 64;
    const long long kbase = ((long long)bh * keys + (long long)blockIdx.y * kvchunk) * 64;

    #pragma unroll
    for (int j = 0; j < 8; j++) {
        int e = tid + 256 * j;
        int r = e >> 4, c4 = (e & 15) * 4;
        float4 qv = *(const float4*)&Qg[qbase + (long long)r * 64 + c4];
        uint32_t hi, lo;
        split_tf32(qv.x, hi, lo); sm.qhi[r][c4+0] = __uint_as_float(hi); sm.qlo[r][c4+0] = __uint_as_float(lo);
        split_tf32(qv.y, hi, lo); sm.qhi[r][c4+1] = __uint_as_float(hi); sm.qlo[r][c4+1] = __uint_as_float(lo);
        split_tf32(qv.z, hi, lo); sm.qhi[r][c4+2] = __uint_as_float(hi); sm.qlo[r][c4+2] = __uint_as_float(lo);
        split_tf32(qv.w, hi, lo); sm.qhi[r][c4+3] = __uint_as_float(hi); sm.qlo[r][c4+3] = __uint_as_float(lo);
    }

    auto stage = [&](int slot, int sub) {
        long long base = kbase + (long long)sub * 64 * 64;
        #pragma unroll
        for (int j = 0; j < 4; j++) {
            int e = tid + 256 * j;
            int r = e >> 4, c4 = (e & 15) * 4;
            cp16(&sm.raw[slot][0][r][c4], &Kg[base + (long long)r * 64 + c4]);
        }
        #pragma unroll
        for (int j = 0; j < 4; j++) {
            int e = tid + 256 * j;
            int r = e >> 4, c4 = (e & 15) * 4;
            cp16(&sm.raw[slot][1][r][c4], &Vg[base + (long long)r * 64 + c4]);
        }
    };

    const int nsub = kvchunk / 64;
    stage(0, 0); CP_COMMIT;

    float o[8][4];
    #pragma unroll
    for (int i = 0; i < 8; i++)
        #pragma unroll
        for (int j = 0; j < 4; j++) o[i][j] = 0.f;
    float l0 = 0.f, l1 = 0.f;
    const int r0s = warp * 16 + grp;

    for (int sub = 0; sub < nsub; sub++) {
        CP_WAIT0;
        __syncthreads();
        int slot = sub & 1;
        if (sub + 1 < nsub) stage(slot ^ 1, sub + 1);
        CP_COMMIT;

        #pragma unroll
        for (int j = 0; j < 4; j++) {
            int e = tid + 256 * j;
            int r = e >> 4, c4 = (e & 15) * 4;
            float4 kv = *(const float4*)&sm.raw[slot][0][r][c4];
            uint32_t hi, lo;
            split_tf32(kv.x, hi, lo); sm.khi[r][c4+0] = __uint_as_float(hi); sm.klo[r][c4+0] = __uint_as_float(lo);
            split_tf32(kv.y, hi, lo); sm.khi[r][c4+1] = __uint_as_float(hi); sm.klo[r][c4+1] = __uint_as_float(lo);
            split_tf32(kv.z, hi, lo); sm.khi[r][c4+2] = __uint_as_float(hi); sm.klo[r][c4+2] = __uint_as_float(lo);
            split_tf32(kv.w, hi, lo); sm.khi[r][c4+3] = __uint_as_float(hi); sm.klo[r][c4+3] = __uint_as_float(lo);
            float4 vv = *(const float4*)&sm.raw[slot][1][r][c4];
            sm.vh[c4+0][r] = __float2half(vv.x);
            sm.vh[c4+1][r] = __float2half(vv.y);
            sm.vh[c4+2][r] = __float2half(vv.z);
            sm.vh[c4+3][r] = __float2half(vv.w);
        }
        __syncthreads();

        float s[8][4];
        #pragma unroll
        for (int i = 0; i < 8; i++)
            #pragma unroll
            for (int j = 0; j < 4; j++) s[i][j] = 0.f;

        #pragma unroll
        for (int ks = 0; ks < 8; ks++) {
            int kk = ks * 8;
            uint32_t a0h = __float_as_uint(sm.qhi[r0s][kk + t4]);
            uint32_t a1h = __float_as_uint(sm.qhi[r0s + 8][kk + t4]);
            uint32_t a2h = __float_as_uint(sm.qhi[r0s][kk + t4 + 4]);
            uint32_t a3h = __float_as_uint(sm.qhi[r0s + 8][kk + t4 + 4]);
            uint32_t a0l = __float_as_uint(sm.qlo[r0s][kk + t4]);
            uint32_t a1l = __float_as_uint(sm.qlo[r0s + 8][kk + t4]);
            uint32_t a2l = __float_as_uint(sm.qlo[r0s][kk + t4 + 4]);
            uint32_t a3l = __float_as_uint(sm.qlo[r0s + 8][kk + t4 + 4]);
            #pragma unroll
            for (int nt = 0; nt < 8; nt++) {
                int n = nt * 8 + grp;
                uint32_t b0h = __float_as_uint(sm.khi[n][kk + t4]);
                uint32_t b1h = __float_as_uint(sm.khi[n][kk + t4 + 4]);
                uint32_t b0l = __float_as_uint(sm.klo[n][kk + t4]);
                uint32_t b1l = __float_as_uint(sm.klo[n][kk + t4 + 4]);
                MMA_TF32(s[nt], a0h, a1h, a2h, a3h, b0h, b1h);
                MMA_TF32(s[nt], a0h, a1h, a2h, a3h, b0l, b1l);
                MMA_TF32(s[nt], a0l, a1l, a2l, a3l, b0h, b1h);
            }
        }

        #pragma unroll
        for (int nt = 0; nt < 8; nt++) {
            s[nt][0] = __expf(s[nt][0]);
            s[nt][1] = __expf(s[nt][1]);
            s[nt][2] = __expf(s[nt][2]);
            s[nt][3] = __expf(s[nt][3]);
            l0 += s[nt][0] + s[nt][1];
            l1 += s[nt][2] + s[nt][3];
        }

        #pragma unroll
        for (int kg = 0; kg < 4; kg++) {
            uint32_t a0 = packh2(s[2*kg][0],   s[2*kg][1]);
            uint32_t a1 = packh2(s[2*kg][2],   s[2*kg][3]);
            uint32_t a2 = packh2(s[2*kg+1][0], s[2*kg+1][1]);
            uint32_t a3 = packh2(s[2*kg+1][2], s[2*kg+1][3]);
            #pragma unroll
            for (int dt = 0; dt < 8; dt++) {
                uint32_t b0 = *(const uint32_t*)&sm.vh[dt * 8 + grp][kg * 16 + 2 * t4];
                uint32_t b1 = *(const uint32_t*)&sm.vh[dt * 8 + grp][kg * 16 + 2 * t4 + 8];
                MMA_F16(o[dt], a0, a1, a2, a3, b0, b1);
            }
        }
    }

    l0 += __shfl_xor_sync(0xffffffffu, l0, 1);
    l0 += __shfl_xor_sync(0xffffffffu, l0, 2);
    l1 += __shfl_xor_sync(0xffffffffu, l1, 1);
    l1 += __shfl_xor_sync(0xffffffffu, l1, 2);

    const int rg0 = blockIdx.x * 128 + warp * 16 + grp;
    if (PARTIAL) {
        long long ob = (long long)(blockIdx.y * BHD + bh) * rows * 64;
        #pragma unroll
        for (int dt = 0; dt < 8; dt++) {
            int d = dt * 8 + 2 * t4;
            float2 w0; w0.x = o[dt][0]; w0.y = o[dt][1];
            float2 w1; w1.x = o[dt][2]; w1.y = o[dt][3];
            *(float2*)&Og[ob + (long long)rg0 * 64 + d] = w0;
            *(float2*)&Og[ob + (long long)(rg0 + 8) * 64 + d] = w1;
        }
        if (t4 == 0) {
            Lg[(long long)(blockIdx.y * BHD + bh) * rows + rg0]     = l0;
            Lg[(long long)(blockIdx.y * BHD + bh) * rows + rg0 + 8] = l1;
        }
    } else {
        float i0 = 1.f / l0, i1 = 1.f / l1;
        long long ob = (long long)bh * rows * 64;
        #pragma unroll
        for (int dt = 0; dt < 8; dt++) {
            int d = dt * 8 + 2 * t4;
            float2 w0; w0.x = o[dt][0] * i0; w0.y = o[dt][1] * i0;
            float2 w1; w1.x = o[dt][2] * i1; w1.y = o[dt][3] * i1;
            *(float2*)&Og[ob + (long long)rg0 * 64 + d] = w0;
            *(float2*)&Og[ob + (long long)(rg0 + 8) * 64 + d] = w1;
        }
    }
}

// ---------------- flash_p: P = exp(q @ kl^T) (unnormalized) + row sums ----
struct PSmem {
    float qhi[128][68];
    float qlo[128][68];
    float khi[64][68];
    float klo[64][68];
};

__global__ void __launch_bounds__(256, 1)
flash_p(const float* __restrict__ Qg, const float* __restrict__ Kg,
        __half* __restrict__ P, float* __restrict__ Lg)
{
    extern __shared__ char dynsm[];
    PSmem& sm = *reinterpret_cast<PSmem*>(dynsm);

    const int tid  = threadIdx.x;
    const int warp = tid >> 5;
    const int lane = tid & 31;
    const int grp  = lane >> 2;
    const int t4   = lane & 3;
    const int bh   = blockIdx.z;

    const long long qbase = ((long long)bh * NSEQ + blockIdx.x * 128) * 64;
    const long long kbase = (long long)bh * NL * 64;

    #pragma unroll
    for (int j = 0; j < 8; j++) {
        int e = tid + 256 * j;
        int r = e >> 4, c4 = (e & 15) * 4;
        float4 qv = *(const float4*)&Qg[qbase + (long long)r * 64 + c4];
        uint32_t hi, lo;
        split_tf32(qv.x, hi, lo); sm.qhi[r][c4+0] = __uint_as_float(hi); sm.qlo[r][c4+0] = __uint_as_float(lo);
        split_tf32(qv.y, hi, lo); sm.qhi[r][c4+1] = __uint_as_float(hi); sm.qlo[r][c4+1] = __uint_as_float(lo);
        split_tf32(qv.z, hi, lo); sm.qhi[r][c4+2] = __uint_as_float(hi); sm.qlo[r][c4+2] = __uint_as_float(lo);
        split_tf32(qv.w, hi, lo); sm.qhi[r][c4+3] = __uint_as_float(hi); sm.qlo[r][c4+3] = __uint_as_float(lo);
    }

    float l0 = 0.f, l1 = 0.f;
    const int r0s = warp * 16 + grp;
    const int rg0 = blockIdx.x * 128 + warp * 16 + grp;

    for (int sub = 0; sub < 4; sub++) {
        __syncthreads();
        #pragma unroll
        for (int j = 0; j < 4; j++) {
            int e = tid + 256 * j;
            int r = e >> 4, c4 = (e & 15) * 4;
            float4 kv = *(const float4*)&Kg[kbase + (long long)(sub * 64 + r) * 64 + c4];
            uint32_t hi, lo;
            split_tf32(kv.x, hi, lo); sm.khi[r][c4+0] = __uint_as_float(hi); sm.klo[r][c4+0] = __uint_as_float(lo);
            split_tf32(kv.y, hi, lo); sm.khi[r][c4+1] = __uint_as_float(hi); sm.klo[r][c4+1] = __uint_as_float(lo);
            split_tf32(kv.z, hi, lo); sm.khi[r][c4+2] = __uint_as_float(hi); sm.klo[r][c4+2] = __uint_as_float(lo);
            split_tf32(kv.w, hi, lo); sm.khi[r][c4+3] = __uint_as_float(hi); sm.klo[r][c4+3] = __uint_as_float(lo);
        }
        __syncthreads();

        float s[8][4];
        #pragma unroll
        for (int i = 0; i < 8; i++)
            #pragma unroll
            for (int j = 0; j < 4; j++) s[i][j] = 0.f;

        #pragma unroll
        for (int ks = 0; ks < 8; ks++) {
            int kk = ks * 8;
            uint32_t a0h = __float_as_uint(sm.qhi[r0s][kk + t4]);
            uint32_t a1h = __float_as_uint(sm.qhi[r0s + 8][kk + t4]);
            uint32_t a2h = __float_as_uint(sm.qhi[r0s][kk + t4 + 4]);
            uint32_t a3h = __float_as_uint(sm.qhi[r0s + 8][kk + t4 + 4]);
            uint32_t a0l = __float_as_uint(sm.qlo[r0s][kk + t4]);
            uint32_t a1l = __float_as_uint(sm.qlo[r0s + 8][kk + t4]);
            uint32_t a2l = __float_as_uint(sm.qlo[r0s][kk + t4 + 4]);
            uint32_t a3l = __float_as_uint(sm.qlo[r0s + 8][kk + t4 + 4]);
            #pragma unroll
            for (int nt = 0; nt < 8; nt++) {
                int n = nt * 8 + grp;
                uint32_t b0h = __float_as_uint(sm.khi[n][kk + t4]);
                uint32_t b1h = __float_as_uint(sm.khi[n][kk + t4 + 4]);
                uint32_t b0l = __float_as_uint(sm.klo[n][kk + t4]);
                uint32_t b1l = __float_as_uint(sm.klo[n][kk + t4 + 4]);
                MMA_TF32(s[nt], a0h, a1h, a2h, a3h, b0h, b1h);
                MMA_TF32(s[nt], a0h, a1h, a2h, a3h, b0l, b1l);
                MMA_TF32(s[nt], a0l, a1l, a2l, a3l, b0h, b1h);
            }
        }

        long long pbase = ((long long)bh * NSEQ) * NL;
        #pragma unroll
        for (int nt = 0; nt < 8; nt++) {
            s[nt][0] = __expf(s[nt][0]);
            s[nt][1] = __expf(s[nt][1]);
            s[nt][2] = __expf(s[nt][2]);
            s[nt][3] = __expf(s[nt][3]);
            l0 += s[nt][0] + s[nt][1];
            l1 += s[nt][2] + s[nt][3];
            int c = sub * 64 + nt * 8 + t4 * 2;
            __half2 p0 = __floats2half2_rn(s[nt][0], s[nt][1]);
            __half2 p1 = __floats2half2_rn(s[nt][2], s[nt][3]);
            *(__half2*)&P[pbase + (long long)rg0 * NL + c] = p0;
            *(__half2*)&P[pbase + (long long)(rg0 + 8) * NL + c] = p1;
        }
    }

    l0 += __shfl_xor_sync(0xffffffffu, l0, 1);
    l0 += __shfl_xor_sync(0xffffffffu, l0, 2);
    l1 += __shfl_xor_sync(0xffffffffu, l1, 1);
    l1 += __shfl_xor_sync(0xffffffffu, l1, 2);
    if (t4 == 0) {
        Lg[(long long)bh * NSEQ + rg0]     = l0;
        Lg[(long long)bh * NSEQ + rg0 + 8] = l1;
    }
}

// combine 4 split-KV partials -> a3v row-major splits, scaled S_PINV
__global__ void combine4(const float* __restrict__ P, const float* __restrict__ L,
                         __half* __restrict__ Rh, __half* __restrict__ Rl)
{
    int idx = blockIdx.x * 256 + threadIdx.x;
    int bhr = idx >> 6;
    const int SL = BHD * NL;
    const int SD = BHD * NL * DH;
    float l = L[bhr] + L[SL + bhr] + L[2 * SL + bhr] + L[3 * SL + bhr];
    float val = (P[idx] + P[SD + idx] + P[2 * SD + idx] + P[3 * SD + idx]) / l;
    __half h, lo2;
    split_h(val * S_PINV, h, lo2);
    Rh[idx] = h; Rl[idx] = lo2;
}

// ---------------- split kernel ----------------
__global__ void split_rm(const float* __restrict__ src, __half* __restrict__ hi,
                         __half* __restrict__ lo, float S, long long n)
{
    long long idx = (long long)blockIdx.x * 256 + threadIdx.x;
    if (idx >= n) return;
    __half h, l;
    split_h(src[idx] * S, h, l);
    hi[idx] = h; lo[idx] = l;
}

// ---------------- landmark means ----------------
__global__ void landmark_mean(const float* __restrict__ src, float* __restrict__ dst)
{
    long long idx = (long long)blockIdx.x * 256 + threadIdx.x;
    int d  = idx & 63;
    int mm = (int)((idx >> 6) & 255);
    long long bh = idx >> 14;
    const float* base = src + ((bh * NSEQ) + (long long)mm * LGRP) * DH + d;
    float s = 0.f;
    #pragma unroll
    for (int t = 0; t < LGRP; t++) s += base[(long long)t * DH];
    dst[idx] = s * (1.0f / LGRP);
}

// ---------------- row softmax (a2), emits scaled splits ----------------
__global__ void softmax_rows(float* __restrict__ data, int L,
                             __half* __restrict__ sh, __half* __restrict__ sl)
{
    long long row = blockIdx.x;
    float* p = data + row * (long long)L;
    __shared__ float red[256];
    int t = threadIdx.x;

    float mx = -INFINITY;
    for (int i = t; i < L; i += 256) mx = fmaxf(mx, p[i]);
    red[t] = mx; __syncthreads();
    for (int s = 128; s > 0; s >>= 1) { if (t < s) red[t] = fmaxf(red[t], red[t + s]); __syncthreads(); }
    mx = red[0]; __syncthreads();

    float sm = 0.f;
    for (int i = t; i < L; i += 256) { float e = expf(p[i] - mx); p[i] = e; sm += e; }
    red[t] = sm; __syncthreads();
    for (int s = 128; s > 0; s >>= 1) { if (t < s) red[t] += red[t + s]; __syncthreads(); }
    float inv = 1.f / red[0];
    for (int i = t; i < L; i += 256) {
        float val = p[i] * inv;
        p[i] = val;
        __half h, l;
        split_h(val * S_PINV, h, l);
        sh[row * L + i] = h;
        sl[row * L + i] = l;
    }
}

// ---------------- pinv init scalars ----------------
__global__ void scal_init(float* scal) { scal[0] = 1.0f; scal[1] = 0.f; }

__global__ void colsum_max(const float* __restrict__ a, float* scal)
{
    int j = blockIdx.x, bh = blockIdx.y, t = threadIdx.x;
    __shared__ float red[256];
    red[t] = a[(((long long)bh * NL) + t) * NL + j];
    __syncthreads();
    for (int s = 128; s > 0; s >>= 1) { if (t < s) red[t] += red[t + s]; __syncthreads(); }
    if (t == 0) atomicMax((int*)(scal + 1), __float_as_int(red[0]));
}

// z0 = a2^T / (col*row): row-major splits, scaled
__global__ void zinit(const float* __restrict__ a,
                      __half* __restrict__ zh, __half* __restrict__ zl,
                      const float* __restrict__ scal)
{
    long long idx = (long long)blockIdx.x * 256 + threadIdx.x;
    float inv = S_PINV / (scal[0] * scal[1]);
    int j = (int)(idx & 255);
    int i = (int)((idx >> 8) & 255);
    long long bh = idx >> 16;
    float val = a[(bh << 16) + ((long long)j << 8) + i] * inv;
    __half h, l;
    split_h(val, h, l);
    zh[idx] = h; zl[idx] = l;
}

// ---------------- tail: oh/L + conv(v) -> x2 splits ----------------
__global__ void conv_add_norm(const float* __restrict__ oh, const float* __restrict__ Lr,
                              const float* __restrict__ v, const float* __restrict__ ker,
                              __half* __restrict__ x2h, __half* __restrict__ x2l)
{
    long long idx = (long long)blockIdx.x * 256 + threadIdx.x;
    int d  = (int)(idx & 63);
    int h  = (int)((idx >> 6) & 7);
    int nn = (int)((idx >> 9) & 4095);
    int b  = (int)(idx >> 21);
    long long bh = (long long)b * HEADS + h;
    const float* vb = v + (bh * NSEQ) * DH + d;
    float s = 0.f;
    #pragma unroll
    for (int t = 0; t < CONV_TAPS; t++) {
        int pos = nn + t - CONV_PAD;
        if (pos >= 0 && pos < NSEQ) s += vb[(long long)pos * DH] * ker[h * CONV_TAPS + t];
    }
    float val = oh[(bh * NSEQ + nn) * DH + d] / Lr[bh * NSEQ + nn] + s;
    __half hh, ll;
    split_h(val, hh, ll);
    x2h[idx] = hh; x2l[idx] = ll;
}

// ---------------- host ----------------
template<int BN, int PREC>
static void launch_h3(const __half* Ah, const __half* Al, const __half* Bh, const __half* Bl,
                      int M, int N, int K, long long sA, long long sB, int batch,
                      float scale, float outS,
                      float* Cf, long long sC, const float* bias,
                      __half* R1h, __half* R1l, long long sR1,
                      __half* R2h, __half* R2l, long long sR2, float dv,
                      int qkv, float qscale, float* qp, float* kp, float* vp,
                      cudaStream_t st = 0, int gridN = -1)
{
    size_t smem = (size_t)((PREC == 3 ? 2 : 1) * 3 * (128 * 40 + 32 * (BN + 8))) * 2;
    cudaFuncSetAttribute(gemm_h3<BN, PREC>, cudaFuncAttributeMaxDynamicSharedMemorySize, (int)smem);
    if (gridN < 0) gridN = N;
    dim3 grid(gridN / BN, M / 128, batch);
    gemm_h3<BN, PREC><<<grid, 512, smem, st>>>(Ah, Al, Bh, Bl, M, N, K, sA, sB,
                                               scale, outS, Cf, sC, bias,
                                               R1h, R1l, sR1, R2h, R2l, sR2, dv,
                                               qkv, qscale, qp, kp, vp);
}

extern "C" void kernel_launch(void* const* d_in, const int* in_sizes, int n_in,
                              void* d_out, int out_size)
{
    const float* x      = (const float*)d_in[0];
    const float* w_qkv  = (const float*)d_in[1];
    const float* w_out  = (const float*)d_in[2];
    const float* b_out  = (const float*)d_in[3];
    const float* res_k  = (const float*)d_in[4];
    float* out = (float*)d_out;

    float *q, *k, *v, *ql, *kl, *a2, *part, *lpart, *oh, *Lf, *scal;
    cudaGetSymbolAddress((void**)&q,     g_q);
    cudaGetSymbolAddress((void**)&k,     g_k);
    cudaGetSymbolAddress((void**)&v,     g_v);
    cudaGetSymbolAddress((void**)&ql,    g_ql);
    cudaGetSymbolAddress((void**)&kl,    g_kl);
    cudaGetSymbolAddress((void**)&a2,    g_a2);
    cudaGetSymbolAddress((void**)&part,  g_part);
    cudaGetSymbolAddress((void**)&lpart, g_lpart);
    cudaGetSymbolAddress((void**)&oh,    g_oh);
    cudaGetSymbolAddress((void**)&Lf,    g_Lf);
    cudaGetSymbolAddress((void**)&scal,  g_scal);

    __half *xh, *xl, *wqh, *wql, *woh, *wol, *x2h, *x2l, *a2h, *a2l;
    __half *zAh, *zAl, *zBh, *zBl, *xzh, *xzl, *T1h, *T1l, *T2h, *T2l;
    __half *a3vh, *a3vl, *za3vh, *za3vl, *Pm;
    cudaGetSymbolAddress((void**)&xh,    g_xh);
    cudaGetSymbolAddress((void**)&xl,    g_xl);
    cudaGetSymbolAddress((void**)&wqh,   g_wqh);
    cudaGetSymbolAddress((void**)&wql,   g_wql);
    cudaGetSymbolAddress((void**)&woh,   g_woh);
    cudaGetSymbolAddress((void**)&wol,   g_wol);
    cudaGetSymbolAddress((void**)&x2h,   g_x2h);
    cudaGetSymbolAddress((void**)&x2l,   g_x2l);
    cudaGetSymbolAddress((void**)&a2h,   g_a2h);
    cudaGetSymbolAddress((void**)&a2l,   g_a2l);
    cudaGetSymbolAddress((void**)&zAh,   g_zAh);
    cudaGetSymbolAddress((void**)&zAl,   g_zAl);
    cudaGetSymbolAddress((void**)&zBh,   g_zBh);
    cudaGetSymbolAddress((void**)&zBl,   g_zBl);
    cudaGetSymbolAddress((void**)&xzh,   g_xzh);
    cudaGetSymbolAddress((void**)&xzl,   g_xzl);
    cudaGetSymbolAddress((void**)&T1h,   g_T1h);
    cudaGetSymbolAddress((void**)&T1l,   g_T1l);
    cudaGetSymbolAddress((void**)&T2h,   g_T2h);
    cudaGetSymbolAddress((void**)&T2l,   g_T2l);
    cudaGetSymbolAddress((void**)&a3vh,  g_a3vh);
    cudaGetSymbolAddress((void**)&a3vl,  g_a3vl);
    cudaGetSymbolAddress((void**)&za3vh, g_za3vh);
    cudaGetSymbolAddress((void**)&za3vl, g_za3vl);
    cudaGetSymbolAddress((void**)&Pm,    g_P);

    cudaFuncSetAttribute(flash_pv<1>, cudaFuncAttributeMaxDynamicSharedMemorySize, (int)sizeof(FlashSmem));
    cudaFuncSetAttribute(flash_p, cudaFuncAttributeMaxDynamicSharedMemorySize, (int)sizeof(PSmem));

    const long long sb = (long long)NL * NL;
    const long long svd = (long long)NL * DH;

    cudaStream_t s2;
    cudaStreamCreateWithFlags(&s2, cudaStreamNonBlocking);
    cudaEvent_t evQK, evLand, evJoin;
    cudaEventCreateWithFlags(&evQK,   cudaEventDisableTiming);
    cudaEventCreateWithFlags(&evLand, cudaEventDisableTiming);
    cudaEventCreateWithFlags(&evJoin, cudaEventDisableTiming);

    // 0) operand splits
    {
        long long n = (long long)BATCH * NSEQ * DIM;
        split_rm<<<(unsigned)((n + 255) / 256), 256>>>(x, xh, xl, 1.0f, n);
        long long nw = (long long)DIM * 3 * DIM;
        split_rm<<<(unsigned)((nw + 255) / 256), 256>>>(w_qkv, wqh, wql, S_W, nw);
        long long nw2 = (long long)DIM * DIM;
        split_rm<<<(unsigned)((nw2 + 255) / 256), 256>>>(w_out, woh, wol, S_W, nw2);
    }

    // 1a) q,k projection ONLY (columns 0..1023) — shortens the serial segment
    launch_h3<128, 3>(xh, xl, wqh, wql, BATCH * NSEQ, 3 * DIM, DIM, 0, 0, 1,
                      1.0f / S_W, 1.0f,
                      nullptr, 0, nullptr, nullptr, nullptr, 0,
                      nullptr, nullptr, 0, 0.f, 1, 0.125f, q, k, v,
                      0, /*gridN=*/2 * DIM);
    cudaEventRecord(evQK, 0);

    // 2) landmarks (need q,k only)
    {
        long long n = (long long)BHD * NL * DH;
        landmark_mean<<<(unsigned)(n / 256), 256>>>(q, ql);
        landmark_mean<<<(unsigned)(n / 256), 256>>>(k, kl);
    }
    cudaEventRecord(evLand, 0);

    // ---- s2: v projection (cols 1024..1535 via offset B pointer; all output
    //      columns land in part 0 => target pointer = v, qscale = 1),
    //      then flash1 (a3v) and flash_p — all off the critical path ----
    cudaStreamWaitEvent(s2, evQK, 0);
    launch_h3<128, 3>(xh, xl, wqh + 2 * DIM, wql + 2 * DIM, BATCH * NSEQ, 3 * DIM, DIM,
                      0, 0, 1, 1.0f / S_W, 1.0f,
                      nullptr, 0, nullptr, nullptr, nullptr, 0,
                      nullptr, nullptr, 0, 0.f, 1, 1.0f, v, v, v,
                      s2, /*gridN=*/DIM);
    cudaStreamWaitEvent(s2, evLand, 0);
    {
        dim3 grid(NL / 128, 4, BHD);
        flash_pv<1><<<grid, 256, sizeof(FlashSmem), s2>>>(ql, k, v, part, lpart, NL, NSEQ, NSEQ / 4);
        combine4<<<(BHD * NL * DH) / 256, 256, 0, s2>>>(part, lpart, a3vh, a3vl);
        dim3 pgrid(NSEQ / 128, 1, BHD);
        flash_p<<<pgrid, 256, sizeof(PSmem), s2>>>(q, kl, Pm, Lf);
    }
    cudaEventRecord(evJoin, s2);

    // 3) a2 = ql @ kl^T (tf32x3, fp32) + softmax (emits splits)
    {
        size_t smem = (size_t)(3 * 128 * 20 + 3 * 128 * 20) * 4;
        cudaFuncSetAttribute(gemm_tf32<128, 1>, cudaFuncAttributeMaxDynamicSharedMemorySize, (int)smem);
        dim3 grid(NL / 128, NL / 128, BHD);
        gemm_tf32<128, 1><<<grid, 256, smem>>>(ql, kl, a2, NL, NL, DH, svd, svd, sb);
    }
    softmax_rows<<<BHD * NL, 256>>>(a2, NL, a2h, a2l);

    // 4) pinv init (row-sum max of a softmax output = 1 exactly)
    scal_init<<<1, 1>>>(scal);
    {
        dim3 g(NL, BHD);
        colsum_max<<<g, 256>>>(a2, scal);
    }
    zinit<<<(unsigned)((long long)BHD * NL * NL / 256), 256>>>(a2, zAh, zAl, scal);

    // 5) Newton iterations (launch-based). 4 cheap + 1 full.
    __half *zch = zAh, *zcl = zAl, *znh = zBh, *znl = zBl;
    const float sa2 = 1.0f / (S_PINV * S_PINV);
    const int NITER = 5;
    for (int it = 0; it < NITER; it++) {
        bool cheap = (it < NITER - 1);
        #define PINV_STEP(PREC_) \
            launch_h3<128, PREC_>(a2h, a2l, zch, zcl, NL, NL, NL, sb, sb, BHD, \
                           sa2, S_PINV, nullptr, 0, nullptr, \
                           xzh, xzl, sb, T1h, T1l, sb, 7.0f, \
                           0, 0.f, nullptr, nullptr, nullptr); \
            launch_h3<128, PREC_>(xzh, xzl, T1h, T1l, NL, NL, NL, sb, sb, BHD, \
                           sa2, S_PINV, nullptr, 0, nullptr, \
                           nullptr, nullptr, 0, T2h, T2l, sb, 15.0f, \
                           0, 0.f, nullptr, nullptr, nullptr); \
            launch_h3<128, PREC_>(xzh, xzl, T2h, T2l, NL, NL, NL, sb, sb, BHD, \
                           sa2, S_PINV, nullptr, 0, nullptr, \
                           nullptr, nullptr, 0, T1h, T1l, sb, 13.0f, \
                           0, 0.f, nullptr, nullptr, nullptr); \
            launch_h3<128, PREC_>(zch, zcl, T1h, T1l, NL, NL, NL, sb, sb, BHD, \
                           0.25f * sa2, S_PINV, nullptr, 0, nullptr, \
                           znh, znl, sb, nullptr, nullptr, 0, 0.f, \
                           0, 0.f, nullptr, nullptr, nullptr);
        if (cheap) { PINV_STEP(1) } else { PINV_STEP(3) }
        #undef PINV_STEP
        __half* t;
        t = zch; zch = znh; znh = t;
        t = zcl; zcl = znl; znl = t;
    }

    // ---- join: tail needs a3v, P, L, v from s2 ----
    cudaStreamWaitEvent(0, evJoin, 0);

    // 7) za3v = z @ a3v (fp16x3) -> fp16 splits
    launch_h3<64, 3>(zch, zcl, a3vh, a3vl, NL, DH, NL, sb, svd, BHD,
                     sa2, 1.0f, nullptr, 0, nullptr,
                     za3vh, za3vl, svd, nullptr, nullptr, 0, 0.f,
                     0, 0.f, nullptr, nullptr, nullptr);

    // 8) oh_unnorm = P @ za3v (1-pass fp16)
    launch_h3<64, 1>(Pm, Pm, za3vh, za3vh, NSEQ, DH, NL,
                     (long long)NSEQ * NL, svd, BHD,
                     1.0f, 1.0f, oh, (long long)NSEQ * DH, nullptr,
                     nullptr, nullptr, 0, nullptr, nullptr, 0, 0.f,
                     0, 0.f, nullptr, nullptr, nullptr);

    // 9) tail: oh/L + conv(v) -> x2 splits
    conv_add_norm<<<(unsigned)((long long)BATCH * NSEQ * HEADS * DH / 256), 256>>>(oh, Lf, v, res_k, x2h, x2l);

    // 10) out = x2 @ w_out + b_out (fp16x3)
    launch_h3<128, 3>(x2h, x2l, woh, wol, BATCH * NSEQ, DIM, DIM, 0, 0, 1,
                      1.0f / S_W, 1.0f,
                      out, 0, b_out, nullptr, nullptr, 0,
                      nullptr, nullptr, 0, 0.f, 0, 0.f, nullptr, nullptr, nullptr);

    cudaEventDestroy(evQK);
    cudaEventDestroy(evLand);
    cudaEventDestroy(evJoin);
    cudaStreamDestroy(s2);
}